// round 1
// baseline (speedup 1.0000x reference)
#include <cuda_runtime.h>
#include <math_constants.h>

// Problem constants
#define H_DIM 180
#define W_DIM 360
#define C_DIM 512
#define P_TOT (H_DIM * W_DIM)          // 64800 spatial positions
#define NELEM (P_TOT * C_DIM)          // 33,177,600
#define NB 8
#define BS 64
#define SPARSITY 0.01f

// ---------------------------------------------------------------------------
// Scratch (no allocations allowed -> __device__ globals)
// ---------------------------------------------------------------------------
__device__ float g_bufA[NELEM];
__device__ float g_bufB[NELEM];
__device__ float g_casC[C_DIM * C_DIM];
__device__ float g_casW[W_DIM * W_DIM];
__device__ float g_w1a[NB * BS * BS];
__device__ float g_w1b[NB * BS * BS];
__device__ float g_w2a[NB * BS * BS];
__device__ float g_w2b[NB * BS * BS];

// ---------------------------------------------------------------------------
// cas(n)[t][d] = cos(2*pi*t*d/n) + sin(2*pi*t*d/n)
// Exact integer angle reduction: angle = pi * ((2*t*d) mod 2n) / n
// ---------------------------------------------------------------------------
__global__ void init_cas_kernel(float* __restrict__ out, int n) {
    int i = blockIdx.x * blockDim.x + threadIdx.x;
    if (i >= n * n) return;
    int t = i / n, d = i % n;
    long long m = (2LL * t * d) % (2LL * n);
    float a = (float)m / (float)n;        // in [0, 2)
    float s, c;
    sincospif(a, &s, &c);
    out[i] = c + s;
}

// w1a = w1[0]+w1[1], w1b = w1[0]-w1[1]; same for w2
__global__ void combine_weights_kernel(const float* __restrict__ w1,
                                       const float* __restrict__ w2) {
    int i = blockIdx.x * blockDim.x + threadIdx.x;
    if (i >= NB * BS * BS) return;
    float a0 = w1[i], a1 = w1[NB * BS * BS + i];
    g_w1a[i] = a0 + a1;
    g_w1b[i] = a0 - a1;
    float c0 = w2[i], c1 = w2[NB * BS * BS + i];
    g_w2a[i] = c0 + c1;
    g_w2b[i] = c0 - c1;
}

// ---------------------------------------------------------------------------
// Register-blocked SGEMM: C[M,N] = alpha * A[M,K] @ B[K,N] (+ Add)
// BM=BN=128, BK=8, 256 threads, 8x8 micro-tile.
// Assumes N % 128 == 0, K % 8 == 0 (true for all call sites). M guarded.
// Batched via blockIdx.z with element strides sA/sB/sC/sAdd.
// ---------------------------------------------------------------------------
__global__ void __launch_bounds__(256) sgemm_kernel(
    int M, int N, int K,
    const float* __restrict__ A, int lda, long long sA,
    const float* __restrict__ B, int ldb, long long sB,
    float* __restrict__ C, int ldc, long long sC,
    float alpha, const float* __restrict__ Add, long long sAdd)
{
    const int bz = blockIdx.z;
    A += (size_t)bz * sA;
    B += (size_t)bz * sB;
    C += (size_t)bz * sC;
    const float* addp = Add ? (Add + (size_t)bz * sAdd) : nullptr;

    __shared__ float As[8][128];
    __shared__ float Bs[8][128];

    const int tid = threadIdx.x;
    const int bm = blockIdx.y * 128;
    const int bn = blockIdx.x * 128;

    const int a_m = tid >> 1;            // 0..127
    const int a_k = (tid & 1) << 2;      // 0 or 4
    const int b_k = tid >> 5;            // 0..7
    const int b_n = (tid & 31) << 2;     // 0..124

    const int tx = tid & 15;
    const int ty = tid >> 4;

    float acc[8][8];
#pragma unroll
    for (int i = 0; i < 8; i++)
#pragma unroll
        for (int j = 0; j < 8; j++) acc[i][j] = 0.f;

    const int row_a = bm + a_m;
    const bool a_ok = row_a < M;
    const float4 zero4 = make_float4(0.f, 0.f, 0.f, 0.f);

    for (int k0 = 0; k0 < K; k0 += 8) {
        float4 av = a_ok ? *(const float4*)(A + (size_t)row_a * lda + (k0 + a_k)) : zero4;
        float4 bv = *(const float4*)(B + (size_t)(k0 + b_k) * ldb + (bn + b_n));

        As[a_k + 0][a_m] = av.x;
        As[a_k + 1][a_m] = av.y;
        As[a_k + 2][a_m] = av.z;
        As[a_k + 3][a_m] = av.w;
        *(float4*)&Bs[b_k][b_n] = bv;
        __syncthreads();

#pragma unroll
        for (int kk = 0; kk < 8; kk++) {
            float4 a0 = *(const float4*)&As[kk][ty * 8];
            float4 a1 = *(const float4*)&As[kk][ty * 8 + 4];
            float4 b0 = *(const float4*)&Bs[kk][tx * 8];
            float4 b1 = *(const float4*)&Bs[kk][tx * 8 + 4];
            float ar[8] = {a0.x, a0.y, a0.z, a0.w, a1.x, a1.y, a1.z, a1.w};
            float br[8] = {b0.x, b0.y, b0.z, b0.w, b1.x, b1.y, b1.z, b1.w};
#pragma unroll
            for (int i = 0; i < 8; i++)
#pragma unroll
                for (int j = 0; j < 8; j++)
                    acc[i][j] += ar[i] * br[j];
        }
        __syncthreads();
    }

#pragma unroll
    for (int i = 0; i < 8; i++) {
        int row = bm + ty * 8 + i;
        if (row < M) {
            float* crow = C + (size_t)row * ldc + bn + tx * 8;
#pragma unroll
            for (int j = 0; j < 8; j += 4) {
                float4 v;
                v.x = acc[i][j + 0] * alpha;
                v.y = acc[i][j + 1] * alpha;
                v.z = acc[i][j + 2] * alpha;
                v.w = acc[i][j + 3] * alpha;
                if (addp) {
                    float4 ad = *(const float4*)(addp + (size_t)row * ldc + bn + tx * 8 + j);
                    v.x += ad.x; v.y += ad.y; v.z += ad.z; v.w += ad.w;
                }
                *(float4*)(crow + j) = v;
            }
        }
    }
}

// ---------------------------------------------------------------------------
// Fused block-MLP + softshrink.
// Per (position tile of 32, block k): loads w1a/w1b/w2a/w2b (64KB) + xh/xn
// tiles into smem, computes o1k/o1n (ReLU), o2k, o2n (consuming o2k — the
// reference's faithful bug), writes softshrink(o2k+o2n).
// xn gather: xn[h,w] = xh[(H-h)%H, (W-w)%W].
// Thread mapping: 256 threads = 32 o-pairs x 8 m-groups; each thread does
// 2 outputs x 4 positions.
// ---------------------------------------------------------------------------
#define TP 32
#define MLP_SMEM ((4 * BS * BS + 5 * TP * BS) * 4)   // 106,496 bytes

__global__ void __launch_bounds__(256) mlp_kernel(
    const float* __restrict__ xh,
    const float* __restrict__ b1,
    const float* __restrict__ b2,
    float* __restrict__ y)
{
    extern __shared__ float sm[];
    float* w1a_s = sm;                    // 4096
    float* w1b_s = w1a_s + BS * BS;
    float* w2a_s = w1b_s + BS * BS;
    float* w2b_s = w2a_s + BS * BS;
    float* xh_s  = w2b_s + BS * BS;       // TP*64
    float* xn_s  = xh_s + TP * BS;
    float* o1k_s = xn_s + TP * BS;
    float* o1n_s = o1k_s + TP * BS;
    float* o2k_s = o1n_s + TP * BS;

    const int k   = blockIdx.y;
    const int tid = threadIdx.x;
    const int p0  = blockIdx.x * TP;

    // weights -> smem (contiguous copy)
    {
        const float4* w1a_g = (const float4*)(g_w1a + k * BS * BS);
        const float4* w1b_g = (const float4*)(g_w1b + k * BS * BS);
        const float4* w2a_g = (const float4*)(g_w2a + k * BS * BS);
        const float4* w2b_g = (const float4*)(g_w2b + k * BS * BS);
#pragma unroll
        for (int it = tid; it < BS * BS / 4; it += 256) {
            ((float4*)w1a_s)[it] = w1a_g[it];
            ((float4*)w1b_s)[it] = w1b_g[it];
            ((float4*)w2a_s)[it] = w2a_g[it];
            ((float4*)w2b_s)[it] = w2b_g[it];
        }
    }

    // xh / xn tiles -> smem
    {
#pragma unroll
        for (int it = tid; it < TP * BS / 4; it += 256) {
            int m  = it >> 4;
            int i4 = (it & 15) << 2;
            int p  = p0 + m;
            int h  = p / W_DIM;
            int w  = p - h * W_DIM;
            int pn = ((H_DIM - h) % H_DIM) * W_DIM + ((W_DIM - w) % W_DIM);
            *(float4*)&xh_s[m * BS + i4] =
                *(const float4*)(xh + (size_t)p * C_DIM + k * BS + i4);
            *(float4*)&xn_s[m * BS + i4] =
                *(const float4*)(xh + (size_t)pn * C_DIM + k * BS + i4);
        }
    }

    const int o0 = (tid & 31) * 2;   // output pair
    const int g  = tid >> 5;         // position group 0..7

    float2 b1k = *(const float2*)(b1 + k * BS + o0);
    float2 b1n = *(const float2*)(b1 + NB * BS + k * BS + o0);
    float2 b2k = *(const float2*)(b2 + k * BS + o0);
    float2 b2n = *(const float2*)(b2 + NB * BS + k * BS + o0);

    __syncthreads();

    // ---- layer 1 ----
    float a1kx[4] = {0, 0, 0, 0}, a1ky[4] = {0, 0, 0, 0};
    float a1nx[4] = {0, 0, 0, 0}, a1ny[4] = {0, 0, 0, 0};
#pragma unroll 4
    for (int i = 0; i < BS; i++) {
        float2 wa = *(const float2*)&w1a_s[i * BS + o0];
        float2 wb = *(const float2*)&w1b_s[i * BS + o0];
#pragma unroll
        for (int mm = 0; mm < 4; mm++) {
            int m = mm * 8 + g;
            float xv = xh_s[m * BS + i];
            float nv = xn_s[m * BS + i];
            a1kx[mm] += xv * wa.x + nv * wb.x;
            a1ky[mm] += xv * wa.y + nv * wb.y;
            a1nx[mm] += nv * wa.x + xv * wb.x;
            a1ny[mm] += nv * wa.y + xv * wb.y;
        }
    }
#pragma unroll
    for (int mm = 0; mm < 4; mm++) {
        int m = mm * 8 + g;
        float2 vk, vn;
        vk.x = fmaxf(0.5f * a1kx[mm] + b1k.x, 0.f);
        vk.y = fmaxf(0.5f * a1ky[mm] + b1k.y, 0.f);
        vn.x = fmaxf(0.5f * a1nx[mm] + b1n.x, 0.f);
        vn.y = fmaxf(0.5f * a1ny[mm] + b1n.y, 0.f);
        *(float2*)&o1k_s[m * BS + o0] = vk;
        *(float2*)&o1n_s[m * BS + o0] = vn;
    }
    __syncthreads();

    // ---- layer 2: o2k ----
    float a2kx[4] = {0, 0, 0, 0}, a2ky[4] = {0, 0, 0, 0};
#pragma unroll 4
    for (int i = 0; i < BS; i++) {
        float2 wa = *(const float2*)&w2a_s[i * BS + o0];
        float2 wb = *(const float2*)&w2b_s[i * BS + o0];
#pragma unroll
        for (int mm = 0; mm < 4; mm++) {
            int m = mm * 8 + g;
            float pk = o1k_s[m * BS + i];
            float pn = o1n_s[m * BS + i];
            a2kx[mm] += pk * wa.x + pn * wb.x;
            a2ky[mm] += pk * wa.y + pn * wb.y;
        }
    }
    float v2kx[4], v2ky[4];
#pragma unroll
    for (int mm = 0; mm < 4; mm++) {
        int m = mm * 8 + g;
        v2kx[mm] = 0.5f * a2kx[mm] + b2k.x;
        v2ky[mm] = 0.5f * a2ky[mm] + b2k.y;
        float2 v = {v2kx[mm], v2ky[mm]};
        *(float2*)&o2k_s[m * BS + o0] = v;
    }
    __syncthreads();

    // ---- layer 2: o2n (consumes o2k per reference bug) ----
    float a2nx[4] = {0, 0, 0, 0}, a2ny[4] = {0, 0, 0, 0};
#pragma unroll 4
    for (int i = 0; i < BS; i++) {
        float2 wa = *(const float2*)&w2a_s[i * BS + o0];
        float2 wb = *(const float2*)&w2b_s[i * BS + o0];
#pragma unroll
        for (int mm = 0; mm < 4; mm++) {
            int m = mm * 8 + g;
            float pn = o1n_s[m * BS + i];
            float qk = o2k_s[m * BS + i];
            a2nx[mm] += pn * wa.x + qk * wb.x;
            a2ny[mm] += pn * wa.y + qk * wb.y;
        }
    }
#pragma unroll
    for (int mm = 0; mm < 4; mm++) {
        int m = mm * 8 + g;
        int p = p0 + m;
        float vx = v2kx[mm] + 0.5f * a2nx[mm] + b2n.x;
        float vy = v2ky[mm] + 0.5f * a2ny[mm] + b2n.y;
        // softshrink
        float ax = fabsf(vx) - SPARSITY;
        float ay = fabsf(vy) - SPARSITY;
        float2 r;
        r.x = ax > 0.f ? copysignf(ax, vx) : 0.f;
        r.y = ay > 0.f ? copysignf(ay, vy) : 0.f;
        *(float2*)(y + (size_t)p * C_DIM + k * BS + o0) = r;
    }
}

// ---------------------------------------------------------------------------
// kernel_launch: full pipeline, graph-capturable, no allocations.
// ---------------------------------------------------------------------------
extern "C" void kernel_launch(void* const* d_in, const int* in_sizes, int n_in,
                              void* d_out, int out_size) {
    const float* x  = (const float*)d_in[0];
    const float* w1 = (const float*)d_in[1];
    const float* b1 = (const float*)d_in[2];
    const float* w2 = (const float*)d_in[3];
    const float* b2 = (const float*)d_in[4];
    float* out = (float*)d_out;

    float *bufA, *bufB, *casC, *casW;
    cudaGetSymbolAddress((void**)&bufA, g_bufA);
    cudaGetSymbolAddress((void**)&bufB, g_bufB);
    cudaGetSymbolAddress((void**)&casC, g_casC);
    cudaGetSymbolAddress((void**)&casW, g_casW);

    cudaFuncSetAttribute(mlp_kernel, cudaFuncAttributeMaxDynamicSharedMemorySize,
                         MLP_SMEM);

    // cas matrices + combined weights (cheap, deterministic per replay)
    init_cas_kernel<<<(C_DIM * C_DIM + 255) / 256, 256>>>(casC, C_DIM);
    init_cas_kernel<<<(W_DIM * W_DIM + 255) / 256, 256>>>(casW, W_DIM);
    combine_weights_kernel<<<(NB * BS * BS + 255) / 256, 256>>>(w1, w2);

    const long long sHW = (long long)W_DIM * C_DIM;   // per-h stride

    // Forward DHT: T1 = X @ casC   (64800x512 @ 512x512)
    sgemm_kernel<<<dim3(C_DIM / 128, (P_TOT + 127) / 128, 1), 256>>>(
        P_TOT, C_DIM, C_DIM,
        x, C_DIM, 0,
        casC, C_DIM, 0,
        bufA, C_DIM, 0,
        1.0f, nullptr, 0);

    // XH_h = casW @ T1_h   (180 batches of 360x360 @ 360x512)
    sgemm_kernel<<<dim3(C_DIM / 128, (W_DIM + 127) / 128, H_DIM), 256>>>(
        W_DIM, C_DIM, W_DIM,
        casW, W_DIM, 0,
        bufA, C_DIM, sHW,
        bufB, C_DIM, sHW,
        1.0f, nullptr, 0);

    // Block MLP + softshrink: bufB (xh, gathers xn) -> bufA (y)
    mlp_kernel<<<dim3(P_TOT / TP, NB), 256, MLP_SMEM>>>(bufB, b1, b2, bufA);

    // Inverse DHT stage 1: T2 = Y @ casC
    sgemm_kernel<<<dim3(C_DIM / 128, (P_TOT + 127) / 128, 1), 256>>>(
        P_TOT, C_DIM, C_DIM,
        bufA, C_DIM, 0,
        casC, C_DIM, 0,
        bufB, C_DIM, 0,
        1.0f, nullptr, 0);

    // Inverse DHT stage 2 + scale + bias: out_h = casW @ T2_h / (W*C) + x_h
    sgemm_kernel<<<dim3(C_DIM / 128, (W_DIM + 127) / 128, H_DIM), 256>>>(
        W_DIM, C_DIM, W_DIM,
        casW, W_DIM, 0,
        bufB, C_DIM, sHW,
        out, C_DIM, sHW,
        1.0f / (float)(W_DIM * C_DIM), x, sHW);
}

// round 6
// speedup vs baseline: 1.8378x; 1.8378x over previous
#include <cuda_runtime.h>
#include <cstdint>

// Problem constants
#define H_DIM 180
#define W_DIM 360
#define WPAD  384                       // W padded to mult of 32 for K-tiling
#define C_DIM 512
#define P_TOT (H_DIM * W_DIM)           // 64800
#define PADELEM (H_DIM * C_DIM * WPAD)  // 35,389,440
#define NB 8
#define BS 64
#define SPARSITY 0.01f

// ---------------------------------------------------------------------------
// Scratch (no allocations allowed -> __device__ globals)
// ---------------------------------------------------------------------------
__device__ float g_bufA[PADELEM];
__device__ float g_bufB[PADELEM];
__device__ float g_casC[C_DIM * C_DIM];
__device__ float g_casW[WPAD * WPAD];   // zero-padded 384x384
__device__ float g_w1a[NB * BS * BS];
__device__ float g_w1b[NB * BS * BS];
__device__ float g_w2a[NB * BS * BS];
__device__ float g_w2b[NB * BS * BS];

// ---------------------------------------------------------------------------
// tf32 helpers (plain mma.sync — compiles for base sm_103, no 'a' features)
// ---------------------------------------------------------------------------
__device__ __forceinline__ uint32_t f2tf(float f) {
    uint32_t r;
    asm("cvt.rna.tf32.f32 %0, %1;" : "=r"(r) : "f"(f));
    return r;
}

__device__ __forceinline__ void mma_tf32(float* d, const uint32_t* a, const uint32_t* b) {
    asm volatile(
        "mma.sync.aligned.m16n8k8.row.col.f32.tf32.tf32.f32 "
        "{%0,%1,%2,%3}, {%4,%5,%6,%7}, {%8,%9}, {%0,%1,%2,%3};"
        : "+f"(d[0]), "+f"(d[1]), "+f"(d[2]), "+f"(d[3])
        : "r"(a[0]), "r"(a[1]), "r"(a[2]), "r"(a[3]), "r"(b[0]), "r"(b[1]));
}

// ---------------------------------------------------------------------------
// Init kernels
// ---------------------------------------------------------------------------
__global__ void init_cas_kernel(float* __restrict__ out, int n) {
    int i = blockIdx.x * blockDim.x + threadIdx.x;
    if (i >= n * n) return;
    int t = i / n, d = i % n;
    long long m = (2LL * t * d) % (2LL * n);
    float a = (float)m / (float)n;
    float s, c;
    sincospif(a, &s, &c);
    out[i] = c + s;
}

__global__ void init_casw_pad_kernel() {
    int i = blockIdx.x * blockDim.x + threadIdx.x;
    if (i >= WPAD * WPAD) return;
    int t = i / WPAD, d = i % WPAD;
    float v = 0.f;
    if (t < W_DIM && d < W_DIM) {
        long long m = (2LL * t * d) % (2LL * W_DIM);
        float a = (float)m / (float)W_DIM;
        float s, c;
        sincospif(a, &s, &c);
        v = c + s;
    }
    g_casW[i] = v;
}

__global__ void combine_weights_kernel(const float* __restrict__ w1,
                                       const float* __restrict__ w2) {
    int i = blockIdx.x * blockDim.x + threadIdx.x;
    if (i >= NB * BS * BS) return;
    float a0 = w1[i], a1 = w1[NB * BS * BS + i];
    g_w1a[i] = a0 + a1;
    g_w1b[i] = a0 - a1;
    float c0 = w2[i], c1 = w2[NB * BS * BS + i];
    g_w2a[i] = c0 + c1;
    g_w2b[i] = c0 - c1;
}

// zero w in [360,384) for all (h, c) in a [h][c][wpad] buffer
__global__ void zeropad_kernel(float* __restrict__ buf) {
    int i = blockIdx.x * blockDim.x + threadIdx.x;
    if (i >= H_DIM * C_DIM * (WPAD - W_DIM)) return;
    int hc = i / (WPAD - W_DIM);
    int r = i - hc * (WPAD - W_DIM);
    buf[(size_t)hc * WPAD + W_DIM + r] = 0.f;
}

// ---------------------------------------------------------------------------
// tf32 warp-MMA GEMM: D[128x128 tile] = A @ B.
//   A: row-major [aM x lda] (rows clamped to aM-1 for OOB tiles)
//   B: "B^T layout" [n][k] k-fast: Btile[n][k] = Bt[(bn+n)*ldb + k]
//   epi_mode 0: C[row][col] row-major store (*alpha, +Add), guard row<M
//   epi_mode 1: transposed-padded store: p=(bm+r) -> C[h*512*384 + n*384 + w]
// BM=BN=128, BK=32, 8 warps (2x4), warp tile 64x32, m16n8k8 tf32.
// K multiple of 32. Batched via blockIdx.z with strides sA/sB/sC/sAdd.
// ---------------------------------------------------------------------------
#define SMSTR 36   // smem row stride (floats): 4m+k bank pattern, conflict-free

__global__ void __launch_bounds__(256) tf32gemm_kernel(
    int M, int K, int aM,
    const float* __restrict__ A, int lda, long long sA,
    const float* __restrict__ Bt, int ldb, long long sB,
    float* __restrict__ C, int ldc, long long sC,
    float alpha, const float* __restrict__ Add, long long sAdd,
    int epi_mode)
{
    __shared__ uint32_t As[128 * SMSTR];
    __shared__ uint32_t Bs[128 * SMSTR];

    const int tid  = threadIdx.x;
    const int lane = tid & 31;
    const int wid  = tid >> 5;
    const int wm   = wid & 1;       // warp row (2)
    const int wn   = wid >> 1;      // warp col (4)
    const int bm   = blockIdx.y * 128;
    const int bn   = blockIdx.x * 128;
    const int bz   = blockIdx.z;

    A  += (size_t)bz * sA;
    Bt += (size_t)bz * sB;
    C  += (size_t)bz * sC;

    float acc[4][4][4];
#pragma unroll
    for (int mi = 0; mi < 4; mi++)
#pragma unroll
        for (int ni = 0; ni < 4; ni++)
#pragma unroll
            for (int q = 0; q < 4; q++) acc[mi][ni][q] = 0.f;

    float4 pa[4], pb[4];

    // prefetch k-tile k0 into registers (A rows clamped)
#define PREFETCH(k0)                                                         \
    do {                                                                     \
        _Pragma("unroll")                                                    \
        for (int c = 0; c < 4; c++) {                                        \
            int id = tid + c * 256;                                          \
            int r = id >> 3, k4 = (id & 7) << 2;                             \
            int ra = bm + r;                                                 \
            if (ra >= aM) ra = aM - 1;                                       \
            pa[c] = *(const float4*)(A + (size_t)ra * lda + (k0) + k4);      \
            pb[c] = *(const float4*)(Bt + (size_t)(bn + r) * ldb + (k0) + k4); \
        }                                                                    \
    } while (0)

    PREFETCH(0);
    const int nT = K >> 5;

    for (int t = 0; t < nT; t++) {
        // convert + store to smem
#pragma unroll
        for (int c = 0; c < 4; c++) {
            int id = tid + c * 256;
            int r = id >> 3, k4 = (id & 7) << 2;
            uint32_t* a4 = &As[r * SMSTR + k4];
            a4[0] = f2tf(pa[c].x); a4[1] = f2tf(pa[c].y);
            a4[2] = f2tf(pa[c].z); a4[3] = f2tf(pa[c].w);
            uint32_t* b4 = &Bs[r * SMSTR + k4];
            b4[0] = f2tf(pb[c].x); b4[1] = f2tf(pb[c].y);
            b4[2] = f2tf(pb[c].z); b4[3] = f2tf(pb[c].w);
        }
        __syncthreads();

        if (t + 1 < nT) PREFETCH((t + 1) << 5);

        // compute: 4 k8 steps
#pragma unroll
        for (int kk = 0; kk < 4; kk++) {
            uint32_t af[4][4], bf[4][2];
            const int kc = kk * 8 + (lane & 3);
#pragma unroll
            for (int mi = 0; mi < 4; mi++) {
                int r0 = wm * 64 + mi * 16 + (lane >> 2);
                af[mi][0] = As[r0 * SMSTR + kc];
                af[mi][1] = As[(r0 + 8) * SMSTR + kc];
                af[mi][2] = As[r0 * SMSTR + kc + 4];
                af[mi][3] = As[(r0 + 8) * SMSTR + kc + 4];
            }
#pragma unroll
            for (int ni = 0; ni < 4; ni++) {
                int n0 = wn * 32 + ni * 8 + (lane >> 2);
                bf[ni][0] = Bs[n0 * SMSTR + kc];
                bf[ni][1] = Bs[n0 * SMSTR + kc + 4];
            }
#pragma unroll
            for (int mi = 0; mi < 4; mi++)
#pragma unroll
                for (int ni = 0; ni < 4; ni++)
                    mma_tf32(acc[mi][ni], af[mi], bf[ni]);
        }
        __syncthreads();
    }
#undef PREFETCH

    // epilogue
    const float* addb = Add ? (Add + (size_t)bz * sAdd) : (const float*)0;
#pragma unroll
    for (int mi = 0; mi < 4; mi++) {
#pragma unroll
        for (int half = 0; half < 2; half++) {
            int r = wm * 64 + mi * 16 + (lane >> 2) + half * 8;
            int p = bm + r;
            if (p < M) {
                if (epi_mode == 0) {
                    float* cp = C + (size_t)p * ldc + bn;
                    const float* ap = addb ? (addb + (size_t)p * ldc + bn) : (const float*)0;
#pragma unroll
                    for (int ni = 0; ni < 4; ni++) {
                        int c0 = wn * 32 + ni * 8 + (lane & 3) * 2;
                        float2 v;
                        v.x = acc[mi][ni][half * 2 + 0] * alpha;
                        v.y = acc[mi][ni][half * 2 + 1] * alpha;
                        if (ap) {
                            float2 a2 = *(const float2*)(ap + c0);
                            v.x += a2.x; v.y += a2.y;
                        }
                        *(float2*)(cp + c0) = v;
                    }
                } else {
                    int h = p / W_DIM, w = p - h * W_DIM;
                    float* cp = C + (size_t)h * (C_DIM * WPAD) + w;
#pragma unroll
                    for (int ni = 0; ni < 4; ni++) {
                        int c0 = bn + wn * 32 + ni * 8 + (lane & 3) * 2;
                        cp[(size_t)c0 * WPAD]       = acc[mi][ni][half * 2 + 0];
                        cp[(size_t)(c0 + 1) * WPAD] = acc[mi][ni][half * 2 + 1];
                    }
                }
            }
        }
    }
}

// ---------------------------------------------------------------------------
// Fused block-MLP + softshrink (SIMT fp32, proven in R1).
// ---------------------------------------------------------------------------
#define TP 32
#define MLP_SMEM ((4 * BS * BS + 5 * TP * BS) * 4)

__global__ void __launch_bounds__(256) mlp_kernel(
    const float* __restrict__ xh,
    const float* __restrict__ b1,
    const float* __restrict__ b2,
    float* __restrict__ y)
{
    extern __shared__ float smf[];
    float* w1a_s = smf;
    float* w1b_s = w1a_s + BS * BS;
    float* w2a_s = w1b_s + BS * BS;
    float* w2b_s = w2a_s + BS * BS;
    float* xh_s  = w2b_s + BS * BS;
    float* xn_s  = xh_s + TP * BS;
    float* o1k_s = xn_s + TP * BS;
    float* o1n_s = o1k_s + TP * BS;
    float* o2k_s = o1n_s + TP * BS;

    const int k   = blockIdx.y;
    const int tid = threadIdx.x;
    const int p0  = blockIdx.x * TP;

    {
        const float4* w1a_g = (const float4*)(g_w1a + k * BS * BS);
        const float4* w1b_g = (const float4*)(g_w1b + k * BS * BS);
        const float4* w2a_g = (const float4*)(g_w2a + k * BS * BS);
        const float4* w2b_g = (const float4*)(g_w2b + k * BS * BS);
#pragma unroll
        for (int it = tid; it < BS * BS / 4; it += 256) {
            ((float4*)w1a_s)[it] = w1a_g[it];
            ((float4*)w1b_s)[it] = w1b_g[it];
            ((float4*)w2a_s)[it] = w2a_g[it];
            ((float4*)w2b_s)[it] = w2b_g[it];
        }
    }
    {
#pragma unroll
        for (int it = tid; it < TP * BS / 4; it += 256) {
            int m  = it >> 4;
            int i4 = (it & 15) << 2;
            int p  = p0 + m;
            int h  = p / W_DIM;
            int w  = p - h * W_DIM;
            int pn = ((H_DIM - h) % H_DIM) * W_DIM + ((W_DIM - w) % W_DIM);
            *(float4*)&xh_s[m * BS + i4] =
                *(const float4*)(xh + (size_t)p * C_DIM + k * BS + i4);
            *(float4*)&xn_s[m * BS + i4] =
                *(const float4*)(xh + (size_t)pn * C_DIM + k * BS + i4);
        }
    }

    const int o0 = (tid & 31) * 2;
    const int g  = tid >> 5;

    float2 b1k = *(const float2*)(b1 + k * BS + o0);
    float2 b1n = *(const float2*)(b1 + NB * BS + k * BS + o0);
    float2 b2k = *(const float2*)(b2 + k * BS + o0);
    float2 b2n = *(const float2*)(b2 + NB * BS + k * BS + o0);

    __syncthreads();

    float a1kx[4] = {0, 0, 0, 0}, a1ky[4] = {0, 0, 0, 0};
    float a1nx[4] = {0, 0, 0, 0}, a1ny[4] = {0, 0, 0, 0};
#pragma unroll 4
    for (int i = 0; i < BS; i++) {
        float2 wa = *(const float2*)&w1a_s[i * BS + o0];
        float2 wb = *(const float2*)&w1b_s[i * BS + o0];
#pragma unroll
        for (int mm = 0; mm < 4; mm++) {
            int m = mm * 8 + g;
            float xv = xh_s[m * BS + i];
            float nv = xn_s[m * BS + i];
            a1kx[mm] += xv * wa.x + nv * wb.x;
            a1ky[mm] += xv * wa.y + nv * wb.y;
            a1nx[mm] += nv * wa.x + xv * wb.x;
            a1ny[mm] += nv * wa.y + xv * wb.y;
        }
    }
#pragma unroll
    for (int mm = 0; mm < 4; mm++) {
        int m = mm * 8 + g;
        float2 vk, vn;
        vk.x = fmaxf(0.5f * a1kx[mm] + b1k.x, 0.f);
        vk.y = fmaxf(0.5f * a1ky[mm] + b1k.y, 0.f);
        vn.x = fmaxf(0.5f * a1nx[mm] + b1n.x, 0.f);
        vn.y = fmaxf(0.5f * a1ny[mm] + b1n.y, 0.f);
        *(float2*)&o1k_s[m * BS + o0] = vk;
        *(float2*)&o1n_s[m * BS + o0] = vn;
    }
    __syncthreads();

    float a2kx[4] = {0, 0, 0, 0}, a2ky[4] = {0, 0, 0, 0};
#pragma unroll 4
    for (int i = 0; i < BS; i++) {
        float2 wa = *(const float2*)&w2a_s[i * BS + o0];
        float2 wb = *(const float2*)&w2b_s[i * BS + o0];
#pragma unroll
        for (int mm = 0; mm < 4; mm++) {
            int m = mm * 8 + g;
            float pk = o1k_s[m * BS + i];
            float pn = o1n_s[m * BS + i];
            a2kx[mm] += pk * wa.x + pn * wb.x;
            a2ky[mm] += pk * wa.y + pn * wb.y;
        }
    }
    float v2kx[4], v2ky[4];
#pragma unroll
    for (int mm = 0; mm < 4; mm++) {
        int m = mm * 8 + g;
        v2kx[mm] = 0.5f * a2kx[mm] + b2k.x;
        v2ky[mm] = 0.5f * a2ky[mm] + b2k.y;
        float2 v = {v2kx[mm], v2ky[mm]};
        *(float2*)&o2k_s[m * BS + o0] = v;
    }
    __syncthreads();

    float a2nx[4] = {0, 0, 0, 0}, a2ny[4] = {0, 0, 0, 0};
#pragma unroll 4
    for (int i = 0; i < BS; i++) {
        float2 wa = *(const float2*)&w2a_s[i * BS + o0];
        float2 wb = *(const float2*)&w2b_s[i * BS + o0];
#pragma unroll
        for (int mm = 0; mm < 4; mm++) {
            int m = mm * 8 + g;
            float pn = o1n_s[m * BS + i];
            float qk = o2k_s[m * BS + i];
            a2nx[mm] += pn * wa.x + qk * wb.x;
            a2ny[mm] += pn * wa.y + qk * wb.y;
        }
    }
#pragma unroll
    for (int mm = 0; mm < 4; mm++) {
        int m = mm * 8 + g;
        int p = p0 + m;
        float vx = v2kx[mm] + 0.5f * a2nx[mm] + b2n.x;
        float vy = v2ky[mm] + 0.5f * a2ny[mm] + b2n.y;
        float ax = fabsf(vx) - SPARSITY;
        float ay = fabsf(vy) - SPARSITY;
        float2 r;
        r.x = ax > 0.f ? copysignf(ax, vx) : 0.f;
        r.y = ay > 0.f ? copysignf(ay, vy) : 0.f;
        *(float2*)(y + (size_t)p * C_DIM + k * BS + o0) = r;
    }
}

// ---------------------------------------------------------------------------
// kernel_launch: full pipeline, graph-capturable, no allocations.
// ---------------------------------------------------------------------------
extern "C" void kernel_launch(void* const* d_in, const int* in_sizes, int n_in,
                              void* d_out, int out_size) {
    const float* x  = (const float*)d_in[0];
    const float* w1 = (const float*)d_in[1];
    const float* b1 = (const float*)d_in[2];
    const float* w2 = (const float*)d_in[3];
    const float* b2 = (const float*)d_in[4];
    float* out = (float*)d_out;

    float *bufA, *bufB, *casC, *casW;
    cudaGetSymbolAddress((void**)&bufA, g_bufA);
    cudaGetSymbolAddress((void**)&bufB, g_bufB);
    cudaGetSymbolAddress((void**)&casC, g_casC);
    cudaGetSymbolAddress((void**)&casW, g_casW);

    cudaFuncSetAttribute(mlp_kernel, cudaFuncAttributeMaxDynamicSharedMemorySize,
                         MLP_SMEM);

    init_cas_kernel<<<(C_DIM * C_DIM + 255) / 256, 256>>>(casC, C_DIM);
    init_casw_pad_kernel<<<(WPAD * WPAD + 255) / 256, 256>>>();
    combine_weights_kernel<<<(NB * BS * BS + 255) / 256, 256>>>(w1, w2);

    const long long sPadH = (long long)C_DIM * WPAD;   // per-h stride, padded layout
    const long long sCmpH = (long long)W_DIM * C_DIM;  // per-h stride, compact layout
    const int nPad = H_DIM * C_DIM * (WPAD - W_DIM);

    // zero pad columns of bufA (T1t target)
    zeropad_kernel<<<(nPad + 255) / 256, 256>>>(bufA);

    // GEMM1: T1t = (X @ casC) stored transposed-padded [h][c][wpad] into bufA
    tf32gemm_kernel<<<dim3(C_DIM / 128, (P_TOT + 127) / 128, 1), 256>>>(
        P_TOT, C_DIM, P_TOT,
        x, C_DIM, 0,
        casC, C_DIM, 0,
        bufA, 0, 0,
        1.0f, nullptr, 0, /*epi*/1);

    // GEMM2: XH[h] = casW @ T1[h] -> compact [p][c] into bufB
    tf32gemm_kernel<<<dim3(C_DIM / 128, 3, H_DIM), 256>>>(
        W_DIM, WPAD, WPAD,
        casW, WPAD, 0,
        bufA, WPAD, sPadH,
        bufB, C_DIM, sCmpH,
        1.0f, nullptr, 0, /*epi*/0);

    // Block MLP + softshrink: bufB (xh) -> bufA (y, compact)
    mlp_kernel<<<dim3(P_TOT / TP, NB), 256, MLP_SMEM>>>(bufB, b1, b2, bufA);

    // zero pad columns of bufB (T2t target)
    zeropad_kernel<<<(nPad + 255) / 256, 256>>>(bufB);

    // GEMM3: T2t = (Y @ casC) transposed-padded into bufB
    tf32gemm_kernel<<<dim3(C_DIM / 128, (P_TOT + 127) / 128, 1), 256>>>(
        P_TOT, C_DIM, P_TOT,
        bufA, C_DIM, 0,
        casC, C_DIM, 0,
        bufB, 0, 0,
        1.0f, nullptr, 0, /*epi*/1);

    // GEMM4: out[h] = casW @ T2[h] / (W*C) + x[h]  (compact)
    tf32gemm_kernel<<<dim3(C_DIM / 128, 3, H_DIM), 256>>>(
        W_DIM, WPAD, WPAD,
        casW, WPAD, 0,
        bufB, WPAD, sPadH,
        out, C_DIM, sCmpH,
        1.0f / (float)(W_DIM * C_DIM), x, sCmpH, /*epi*/0);
}

// round 7
// speedup vs baseline: 2.6368x; 1.4348x over previous
#include <cuda_runtime.h>
#include <cstdint>

// Problem constants
#define H_DIM 180
#define W_DIM 360
#define WPAD  384
#define C_DIM 512
#define P_TOT (H_DIM * W_DIM)           // 64800
#define PADELEM (H_DIM * C_DIM * WPAD)
#define NB 8
#define BS 64
#define SPARSITY 0.01f

// ---------------------------------------------------------------------------
// Scratch
// ---------------------------------------------------------------------------
__device__ float g_bufA[PADELEM];
__device__ float g_bufB[PADELEM];
__device__ float g_casC[C_DIM * C_DIM];
__device__ float g_casW[WPAD * WPAD];
__device__ uint32_t g_w1cat[NB * 128 * 128];  // [blk][o][i] tf32, W1cat transposed
__device__ uint32_t g_w2cat[NB * 64 * 128];   // [blk][o][i] tf32, W2cat transposed

// ---------------------------------------------------------------------------
// tf32 helpers (plain mma.sync — compiles for base sm_103)
// ---------------------------------------------------------------------------
__device__ __forceinline__ uint32_t f2tf(float f) {
    uint32_t r;
    asm("cvt.rna.tf32.f32 %0, %1;" : "=r"(r) : "f"(f));
    return r;
}

__device__ __forceinline__ void mma_tf32(float* d, const uint32_t* a, const uint32_t* b) {
    asm volatile(
        "mma.sync.aligned.m16n8k8.row.col.f32.tf32.tf32.f32 "
        "{%0,%1,%2,%3}, {%4,%5,%6,%7}, {%8,%9}, {%0,%1,%2,%3};"
        : "+f"(d[0]), "+f"(d[1]), "+f"(d[2]), "+f"(d[3])
        : "r"(a[0]), "r"(a[1]), "r"(a[2]), "r"(a[3]), "r"(b[0]), "r"(b[1]));
}

// ---------------------------------------------------------------------------
// Init kernels
// ---------------------------------------------------------------------------
__global__ void init_cas_kernel(float* __restrict__ out, int n) {
    int i = blockIdx.x * blockDim.x + threadIdx.x;
    if (i >= n * n) return;
    int t = i / n, d = i % n;
    long long m = (2LL * t * d) % (2LL * n);
    float a = (float)m / (float)n;
    float s, c;
    sincospif(a, &s, &c);
    out[i] = c + s;
}

__global__ void init_casw_pad_kernel() {
    int i = blockIdx.x * blockDim.x + threadIdx.x;
    if (i >= WPAD * WPAD) return;
    int t = i / WPAD, d = i % WPAD;
    float v = 0.f;
    if (t < W_DIM && d < W_DIM) {
        long long m = (2LL * t * d) % (2LL * W_DIM);
        float a = (float)m / (float)W_DIM;
        float s, c;
        sincospif(a, &s, &c);
        v = c + s;
    }
    g_casW[i] = v;
}

// Build pre-transposed tf32 MLP weights:
//   g_w1cat[blk][o][i], o,i in [0,128):
//     o<64 : i<64 -> w1a[i][o]      ; i>=64 -> w1b[i-64][o]
//     o>=64: i<64 -> w1b[i][o-64]   ; i>=64 -> w1a[i-64][o-64]
//   g_w2cat[blk][o][i], o in [0,64), i in [0,128):
//     i<64 -> w2a[i][o] ; i>=64 -> w2b[i-64][o]
// where w1a = w1[0]+w1[1], w1b = w1[0]-w1[1] (same for w2).
__global__ void prep_mlp_weights(const float* __restrict__ w1,
                                 const float* __restrict__ w2) {
    const int NW1 = NB * 128 * 128;
    const int NW2 = NB * 64 * 128;
    int idx = blockIdx.x * blockDim.x + threadIdx.x;
    if (idx < NW1) {
        int blk = idx >> 14;
        int rem = idx & 16383;
        int o = rem >> 7, i = rem & 127;
        const float* w1p = w1 + blk * 4096;           // w1[0][blk]
        const float* w1q = w1 + (NB + blk) * 4096;    // w1[1][blk]
        float v;
        if (o < 64) {
            if (i < 64) v = w1p[i * 64 + o] + w1q[i * 64 + o];
            else        v = w1p[(i - 64) * 64 + o] - w1q[(i - 64) * 64 + o];
        } else {
            int oo = o - 64;
            if (i < 64) v = w1p[i * 64 + oo] - w1q[i * 64 + oo];
            else        v = w1p[(i - 64) * 64 + oo] + w1q[(i - 64) * 64 + oo];
        }
        g_w1cat[idx] = f2tf(v);
    } else if (idx < NW1 + NW2) {
        int j = idx - NW1;
        int blk = j >> 13;
        int rem = j & 8191;
        int o = rem >> 7, i = rem & 127;
        const float* w2p = w2 + blk * 4096;
        const float* w2q = w2 + (NB + blk) * 4096;
        float v;
        if (i < 64) v = w2p[i * 64 + o] + w2q[i * 64 + o];
        else        v = w2p[(i - 64) * 64 + o] - w2q[(i - 64) * 64 + o];
        g_w2cat[j] = f2tf(v);
    }
}

__global__ void zeropad_kernel(float* __restrict__ buf) {
    int i = blockIdx.x * blockDim.x + threadIdx.x;
    if (i >= H_DIM * C_DIM * (WPAD - W_DIM)) return;
    int hc = i / (WPAD - W_DIM);
    int r = i - hc * (WPAD - W_DIM);
    buf[(size_t)hc * WPAD + W_DIM + r] = 0.f;
}

// ---------------------------------------------------------------------------
// tf32 warp-MMA GEMM (proven in R6). BM=BN=128, BK=32, 8 warps, 64x32 warp tile.
// ---------------------------------------------------------------------------
#define SMSTR 36

__global__ void __launch_bounds__(256) tf32gemm_kernel(
    int M, int K, int aM,
    const float* __restrict__ A, int lda, long long sA,
    const float* __restrict__ Bt, int ldb, long long sB,
    float* __restrict__ C, int ldc, long long sC,
    float alpha, const float* __restrict__ Add, long long sAdd,
    int epi_mode)
{
    __shared__ uint32_t As[128 * SMSTR];
    __shared__ uint32_t Bs[128 * SMSTR];

    const int tid  = threadIdx.x;
    const int lane = tid & 31;
    const int wid  = tid >> 5;
    const int wm   = wid & 1;
    const int wn   = wid >> 1;
    const int bm   = blockIdx.y * 128;
    const int bn   = blockIdx.x * 128;
    const int bz   = blockIdx.z;

    A  += (size_t)bz * sA;
    Bt += (size_t)bz * sB;
    C  += (size_t)bz * sC;

    float acc[4][4][4];
#pragma unroll
    for (int mi = 0; mi < 4; mi++)
#pragma unroll
        for (int ni = 0; ni < 4; ni++)
#pragma unroll
            for (int q = 0; q < 4; q++) acc[mi][ni][q] = 0.f;

    float4 pa[4], pb[4];

#define PREFETCH(k0)                                                         \
    do {                                                                     \
        _Pragma("unroll")                                                    \
        for (int c = 0; c < 4; c++) {                                        \
            int id = tid + c * 256;                                          \
            int r = id >> 3, k4 = (id & 7) << 2;                             \
            int ra = bm + r;                                                 \
            if (ra >= aM) ra = aM - 1;                                       \
            pa[c] = *(const float4*)(A + (size_t)ra * lda + (k0) + k4);      \
            pb[c] = *(const float4*)(Bt + (size_t)(bn + r) * ldb + (k0) + k4); \
        }                                                                    \
    } while (0)

    PREFETCH(0);
    const int nT = K >> 5;

    for (int t = 0; t < nT; t++) {
#pragma unroll
        for (int c = 0; c < 4; c++) {
            int id = tid + c * 256;
            int r = id >> 3, k4 = (id & 7) << 2;
            uint32_t* a4 = &As[r * SMSTR + k4];
            a4[0] = f2tf(pa[c].x); a4[1] = f2tf(pa[c].y);
            a4[2] = f2tf(pa[c].z); a4[3] = f2tf(pa[c].w);
            uint32_t* b4 = &Bs[r * SMSTR + k4];
            b4[0] = f2tf(pb[c].x); b4[1] = f2tf(pb[c].y);
            b4[2] = f2tf(pb[c].z); b4[3] = f2tf(pb[c].w);
        }
        __syncthreads();

        if (t + 1 < nT) PREFETCH((t + 1) << 5);

#pragma unroll
        for (int kk = 0; kk < 4; kk++) {
            uint32_t af[4][4], bf[4][2];
            const int kc = kk * 8 + (lane & 3);
#pragma unroll
            for (int mi = 0; mi < 4; mi++) {
                int r0 = wm * 64 + mi * 16 + (lane >> 2);
                af[mi][0] = As[r0 * SMSTR + kc];
                af[mi][1] = As[(r0 + 8) * SMSTR + kc];
                af[mi][2] = As[r0 * SMSTR + kc + 4];
                af[mi][3] = As[(r0 + 8) * SMSTR + kc + 4];
            }
#pragma unroll
            for (int ni = 0; ni < 4; ni++) {
                int n0 = wn * 32 + ni * 8 + (lane >> 2);
                bf[ni][0] = Bs[n0 * SMSTR + kc];
                bf[ni][1] = Bs[n0 * SMSTR + kc + 4];
            }
#pragma unroll
            for (int mi = 0; mi < 4; mi++)
#pragma unroll
                for (int ni = 0; ni < 4; ni++)
                    mma_tf32(acc[mi][ni], af[mi], bf[ni]);
        }
        __syncthreads();
    }
#undef PREFETCH

    const float* addb = Add ? (Add + (size_t)bz * sAdd) : (const float*)0;
#pragma unroll
    for (int mi = 0; mi < 4; mi++) {
#pragma unroll
        for (int half = 0; half < 2; half++) {
            int r = wm * 64 + mi * 16 + (lane >> 2) + half * 8;
            int p = bm + r;
            if (p < M) {
                if (epi_mode == 0) {
                    float* cp = C + (size_t)p * ldc + bn;
                    const float* ap = addb ? (addb + (size_t)p * ldc + bn) : (const float*)0;
#pragma unroll
                    for (int ni = 0; ni < 4; ni++) {
                        int c0 = wn * 32 + ni * 8 + (lane & 3) * 2;
                        float2 v;
                        v.x = acc[mi][ni][half * 2 + 0] * alpha;
                        v.y = acc[mi][ni][half * 2 + 1] * alpha;
                        if (ap) {
                            float2 a2 = *(const float2*)(ap + c0);
                            v.x += a2.x; v.y += a2.y;
                        }
                        *(float2*)(cp + c0) = v;
                    }
                } else {
                    int h = p / W_DIM, w = p - h * W_DIM;
                    float* cp = C + (size_t)h * (C_DIM * WPAD) + w;
#pragma unroll
                    for (int ni = 0; ni < 4; ni++) {
                        int c0 = bn + wn * 32 + ni * 8 + (lane & 3) * 2;
                        cp[(size_t)c0 * WPAD]       = acc[mi][ni][half * 2 + 0];
                        cp[(size_t)(c0 + 1) * WPAD] = acc[mi][ni][half * 2 + 1];
                    }
                }
            }
        }
    }
}

// ---------------------------------------------------------------------------
// Tensor-core block-MLP + softshrink.
// Per CTA: 128 positions x block k. Three tf32 mma GEMMs entirely in smem:
//   L1 : [xh|xn](128x128) @ W1cat -> [o1k|o1n] (relu+bias)   K=128
//   L2a: [o1k|o1n] @ W2cat        -> o2k (bias, kept + smem)  K=128
//   L2b: o1n@w2a + o2k@w2b        -> o2n (two K=64 passes)
// y = softshrink(o2k + o2n). 8 warps: L1 warp tile 64x32, L2 64x16.
// ---------------------------------------------------------------------------
#define MS 132
#define O2S 68
#define MLP_TC_SMEM ((128 * MS + 128 * MS + 64 * MS + 128 * O2S + 256) * 4)  // 204800

__global__ void __launch_bounds__(256) mlp_tc_kernel(
    const float* __restrict__ xh,
    const float* __restrict__ b1,
    const float* __restrict__ b2,
    float* __restrict__ y)
{
    extern __shared__ uint32_t sm[];
    uint32_t* sA  = sm;                    // 128*MS  (A1, then o1)
    uint32_t* sW1 = sA + 128 * MS;         // 128*MS
    uint32_t* sW2 = sW1 + 128 * MS;        // 64*MS
    uint32_t* sO2 = sW2 + 64 * MS;         // 128*O2S (o2k)
    int* s_p  = (int*)(sO2 + 128 * O2S);
    int* s_pn = s_p + 128;

    const int tid  = threadIdx.x;
    const int lane = tid & 31;
    const int wid  = tid >> 5;
    const int wm   = wid & 1;
    const int wn   = wid >> 1;
    const int k    = blockIdx.y;
    const int p0   = blockIdx.x * 128;

    if (tid < 128) {
        int p = p0 + tid;
        if (p >= P_TOT) p = P_TOT - 1;
        int h = p / W_DIM, w = p - h * W_DIM;
        s_p[tid]  = p;
        s_pn[tid] = ((H_DIM - h) % H_DIM) * W_DIM + ((W_DIM - w) % W_DIM);
    }
    // weights -> smem (coalesced uint4)
    {
        const uint4* w1g = (const uint4*)(g_w1cat + k * 16384);
#pragma unroll
        for (int it = tid; it < 4096; it += 256) {
            int r = it >> 5, c4 = (it & 31) << 2;
            *(uint4*)&sW1[r * MS + c4] = w1g[it];
        }
        const uint4* w2g = (const uint4*)(g_w2cat + k * 8192);
#pragma unroll
        for (int it = tid; it < 2048; it += 256) {
            int r = it >> 5, c4 = (it & 31) << 2;
            *(uint4*)&sW2[r * MS + c4] = w2g[it];
        }
    }
    __syncthreads();

    // A1 = [xh | xn] tile (tf32)
#pragma unroll
    for (int it = tid; it < 4096; it += 256) {
        int r = it >> 5, c = (it & 31) << 2;
        const float* src = (c < 64)
            ? xh + (size_t)s_p[r] * C_DIM + k * BS + c
            : xh + (size_t)s_pn[r] * C_DIM + k * BS + (c - 64);
        float4 v = *(const float4*)src;
        uint4 u;
        u.x = f2tf(v.x); u.y = f2tf(v.y); u.z = f2tf(v.z); u.w = f2tf(v.w);
        *(uint4*)&sA[r * MS + c] = u;
    }
    __syncthreads();

    // ---- Layer 1: 128x128 = A1 @ W1cat ----
    float acc1[4][4][4];
#pragma unroll
    for (int mi = 0; mi < 4; mi++)
#pragma unroll
        for (int ni = 0; ni < 4; ni++)
#pragma unroll
            for (int q = 0; q < 4; q++) acc1[mi][ni][q] = 0.f;

#pragma unroll
    for (int kk = 0; kk < 16; kk++) {
        uint32_t af[4][4], bf[4][2];
        const int kc = kk * 8 + (lane & 3);
#pragma unroll
        for (int mi = 0; mi < 4; mi++) {
            int r0 = wm * 64 + mi * 16 + (lane >> 2);
            af[mi][0] = sA[r0 * MS + kc];
            af[mi][1] = sA[(r0 + 8) * MS + kc];
            af[mi][2] = sA[r0 * MS + kc + 4];
            af[mi][3] = sA[(r0 + 8) * MS + kc + 4];
        }
#pragma unroll
        for (int ni = 0; ni < 4; ni++) {
            int n0 = wn * 32 + ni * 8 + (lane >> 2);
            bf[ni][0] = sW1[n0 * MS + kc];
            bf[ni][1] = sW1[n0 * MS + kc + 4];
        }
#pragma unroll
        for (int mi = 0; mi < 4; mi++)
#pragma unroll
            for (int ni = 0; ni < 4; ni++)
                mma_tf32(acc1[mi][ni], af[mi], bf[ni]);
    }
    __syncthreads();   // all reads of sA done

    // bias + relu, o1 -> sA (tf32)
#pragma unroll
    for (int mi = 0; mi < 4; mi++)
#pragma unroll
        for (int half = 0; half < 2; half++) {
            int r = wm * 64 + mi * 16 + (lane >> 2) + half * 8;
#pragma unroll
            for (int ni = 0; ni < 4; ni++) {
                int c = wn * 32 + ni * 8 + (lane & 3) * 2;
                float bx = (c < 64) ? b1[k * BS + c] : b1[NB * BS + k * BS + (c - 64)];
                float by = (c + 1 < 64) ? b1[k * BS + c + 1] : b1[NB * BS + k * BS + (c + 1 - 64)];
                float vx = fmaxf(0.5f * acc1[mi][ni][half * 2 + 0] + bx, 0.f);
                float vy = fmaxf(0.5f * acc1[mi][ni][half * 2 + 1] + by, 0.f);
                sA[r * MS + c]     = f2tf(vx);
                sA[r * MS + c + 1] = f2tf(vy);
            }
        }
    __syncthreads();

    // ---- Layer 2a: o2k (128x64) = o1 @ W2cat ----
    float acc2[4][2][4];
#pragma unroll
    for (int mi = 0; mi < 4; mi++)
#pragma unroll
        for (int ni = 0; ni < 2; ni++)
#pragma unroll
            for (int q = 0; q < 4; q++) acc2[mi][ni][q] = 0.f;

#pragma unroll
    for (int kk = 0; kk < 16; kk++) {
        uint32_t af[4][4], bf[2][2];
        const int kc = kk * 8 + (lane & 3);
#pragma unroll
        for (int mi = 0; mi < 4; mi++) {
            int r0 = wm * 64 + mi * 16 + (lane >> 2);
            af[mi][0] = sA[r0 * MS + kc];
            af[mi][1] = sA[(r0 + 8) * MS + kc];
            af[mi][2] = sA[r0 * MS + kc + 4];
            af[mi][3] = sA[(r0 + 8) * MS + kc + 4];
        }
#pragma unroll
        for (int ni = 0; ni < 2; ni++) {
            int n0 = wn * 16 + ni * 8 + (lane >> 2);
            bf[ni][0] = sW2[n0 * MS + kc];
            bf[ni][1] = sW2[n0 * MS + kc + 4];
        }
#pragma unroll
        for (int mi = 0; mi < 4; mi++)
#pragma unroll
            for (int ni = 0; ni < 2; ni++)
                mma_tf32(acc2[mi][ni], af[mi], bf[ni]);
    }

    // o2k = 0.5*acc + b2k; keep in regs, store tf32 to sO2
    float v2k[4][2][4];
#pragma unroll
    for (int mi = 0; mi < 4; mi++)
#pragma unroll
        for (int half = 0; half < 2; half++) {
            int r = wm * 64 + mi * 16 + (lane >> 2) + half * 8;
#pragma unroll
            for (int ni = 0; ni < 2; ni++) {
                int c = wn * 16 + ni * 8 + (lane & 3) * 2;
                float vx = 0.5f * acc2[mi][ni][half * 2 + 0] + b2[k * BS + c];
                float vy = 0.5f * acc2[mi][ni][half * 2 + 1] + b2[k * BS + c + 1];
                v2k[mi][ni][half * 2 + 0] = vx;
                v2k[mi][ni][half * 2 + 1] = vy;
                sO2[r * O2S + c]     = f2tf(vx);
                sO2[r * O2S + c + 1] = f2tf(vy);
            }
        }
    __syncthreads();

    // ---- Layer 2b: o2n = o1n @ w2a + o2k @ w2b ----
    float accn[4][2][4];
#pragma unroll
    for (int mi = 0; mi < 4; mi++)
#pragma unroll
        for (int ni = 0; ni < 2; ni++)
#pragma unroll
            for (int q = 0; q < 4; q++) accn[mi][ni][q] = 0.f;

    // pass 1: A = o1n (sA cols 64..127), B = w2a part (sW2 k 0..63)
#pragma unroll
    for (int kk = 0; kk < 8; kk++) {
        uint32_t af[4][4], bf[2][2];
        const int kc = kk * 8 + (lane & 3);
#pragma unroll
        for (int mi = 0; mi < 4; mi++) {
            int r0 = wm * 64 + mi * 16 + (lane >> 2);
            af[mi][0] = sA[r0 * MS + 64 + kc];
            af[mi][1] = sA[(r0 + 8) * MS + 64 + kc];
            af[mi][2] = sA[r0 * MS + 64 + kc + 4];
            af[mi][3] = sA[(r0 + 8) * MS + 64 + kc + 4];
        }
#pragma unroll
        for (int ni = 0; ni < 2; ni++) {
            int n0 = wn * 16 + ni * 8 + (lane >> 2);
            bf[ni][0] = sW2[n0 * MS + kc];
            bf[ni][1] = sW2[n0 * MS + kc + 4];
        }
#pragma unroll
        for (int mi = 0; mi < 4; mi++)
#pragma unroll
            for (int ni = 0; ni < 2; ni++)
                mma_tf32(accn[mi][ni], af[mi], bf[ni]);
    }
    // pass 2: A = o2k (sO2), B = w2b part (sW2 k 64..127)
#pragma unroll
    for (int kk = 0; kk < 8; kk++) {
        uint32_t af[4][4], bf[2][2];
        const int kc = kk * 8 + (lane & 3);
#pragma unroll
        for (int mi = 0; mi < 4; mi++) {
            int r0 = wm * 64 + mi * 16 + (lane >> 2);
            af[mi][0] = sO2[r0 * O2S + kc];
            af[mi][1] = sO2[(r0 + 8) * O2S + kc];
            af[mi][2] = sO2[r0 * O2S + kc + 4];
            af[mi][3] = sO2[(r0 + 8) * O2S + kc + 4];
        }
#pragma unroll
        for (int ni = 0; ni < 2; ni++) {
            int n0 = wn * 16 + ni * 8 + (lane >> 2);
            bf[ni][0] = sW2[n0 * MS + 64 + kc];
            bf[ni][1] = sW2[n0 * MS + 64 + kc + 4];
        }
#pragma unroll
        for (int mi = 0; mi < 4; mi++)
#pragma unroll
            for (int ni = 0; ni < 2; ni++)
                mma_tf32(accn[mi][ni], af[mi], bf[ni]);
    }

    // final: y = softshrink(o2k + o2n)
#pragma unroll
    for (int mi = 0; mi < 4; mi++)
#pragma unroll
        for (int half = 0; half < 2; half++) {
            int r = wm * 64 + mi * 16 + (lane >> 2) + half * 8;
            int p = p0 + r;
            if (p < P_TOT) {
#pragma unroll
                for (int ni = 0; ni < 2; ni++) {
                    int c = wn * 16 + ni * 8 + (lane & 3) * 2;
                    float vx = v2k[mi][ni][half * 2 + 0]
                             + 0.5f * accn[mi][ni][half * 2 + 0] + b2[NB * BS + k * BS + c];
                    float vy = v2k[mi][ni][half * 2 + 1]
                             + 0.5f * accn[mi][ni][half * 2 + 1] + b2[NB * BS + k * BS + c + 1];
                    float ax = fabsf(vx) - SPARSITY;
                    float ay = fabsf(vy) - SPARSITY;
                    float2 rr;
                    rr.x = ax > 0.f ? copysignf(ax, vx) : 0.f;
                    rr.y = ay > 0.f ? copysignf(ay, vy) : 0.f;
                    *(float2*)(y + (size_t)p * C_DIM + k * BS + c) = rr;
                }
            }
        }
}

// ---------------------------------------------------------------------------
// kernel_launch
// ---------------------------------------------------------------------------
extern "C" void kernel_launch(void* const* d_in, const int* in_sizes, int n_in,
                              void* d_out, int out_size) {
    const float* x  = (const float*)d_in[0];
    const float* w1 = (const float*)d_in[1];
    const float* b1 = (const float*)d_in[2];
    const float* w2 = (const float*)d_in[3];
    const float* b2 = (const float*)d_in[4];
    float* out = (float*)d_out;

    float *bufA, *bufB, *casC, *casW;
    cudaGetSymbolAddress((void**)&bufA, g_bufA);
    cudaGetSymbolAddress((void**)&bufB, g_bufB);
    cudaGetSymbolAddress((void**)&casC, g_casC);
    cudaGetSymbolAddress((void**)&casW, g_casW);

    cudaFuncSetAttribute(mlp_tc_kernel, cudaFuncAttributeMaxDynamicSharedMemorySize,
                         MLP_TC_SMEM);

    init_cas_kernel<<<(C_DIM * C_DIM + 255) / 256, 256>>>(casC, C_DIM);
    init_casw_pad_kernel<<<(WPAD * WPAD + 255) / 256, 256>>>();
    {
        int nprep = NB * 128 * 128 + NB * 64 * 128;
        prep_mlp_weights<<<(nprep + 255) / 256, 256>>>(w1, w2);
    }

    const long long sPadH = (long long)C_DIM * WPAD;
    const long long sCmpH = (long long)W_DIM * C_DIM;
    const int nPad = H_DIM * C_DIM * (WPAD - W_DIM);

    zeropad_kernel<<<(nPad + 255) / 256, 256>>>(bufA);

    // GEMM1: T1t = (X @ casC) -> transposed-padded bufA
    tf32gemm_kernel<<<dim3(C_DIM / 128, (P_TOT + 127) / 128, 1), 256>>>(
        P_TOT, C_DIM, P_TOT,
        x, C_DIM, 0,
        casC, C_DIM, 0,
        bufA, 0, 0,
        1.0f, nullptr, 0, 1);

    // GEMM2: XH[h] = casW @ T1[h] -> compact bufB
    tf32gemm_kernel<<<dim3(C_DIM / 128, 3, H_DIM), 256>>>(
        W_DIM, WPAD, WPAD,
        casW, WPAD, 0,
        bufA, WPAD, sPadH,
        bufB, C_DIM, sCmpH,
        1.0f, nullptr, 0, 0);

    // Tensor-core block MLP + softshrink: bufB -> bufA
    mlp_tc_kernel<<<dim3((P_TOT + 127) / 128, NB), 256, MLP_TC_SMEM>>>(
        bufB, b1, b2, bufA);

    zeropad_kernel<<<(nPad + 255) / 256, 256>>>(bufB);

    // GEMM3: T2t = (Y @ casC) -> transposed-padded bufB
    tf32gemm_kernel<<<dim3(C_DIM / 128, (P_TOT + 127) / 128, 1), 256>>>(
        P_TOT, C_DIM, P_TOT,
        bufA, C_DIM, 0,
        casC, C_DIM, 0,
        bufB, 0, 0,
        1.0f, nullptr, 0, 1);

    // GEMM4: out[h] = casW @ T2[h] / (W*C) + x[h]
    tf32gemm_kernel<<<dim3(C_DIM / 128, 3, H_DIM), 256>>>(
        W_DIM, WPAD, WPAD,
        casW, WPAD, 0,
        bufB, WPAD, sPadH,
        out, C_DIM, sCmpH,
        1.0f / (float)(W_DIM * C_DIM), x, sCmpH, 0);
}

// round 8
// speedup vs baseline: 3.1866x; 1.2085x over previous
#include <cuda_runtime.h>
#include <cstdint>

// Problem constants
#define H_DIM 180
#define W_DIM 360
#define WPAD  384
#define C_DIM 512
#define P_TOT (H_DIM * W_DIM)           // 64800
#define PADELEM (H_DIM * C_DIM * WPAD)
#define NB 8
#define BS 64
#define SPARSITY 0.01f

// ---------------------------------------------------------------------------
// Scratch
// ---------------------------------------------------------------------------
__device__ float g_bufA[PADELEM];
__device__ float g_bufB[PADELEM];
__device__ float g_casC[C_DIM * C_DIM];
__device__ float g_casW[WPAD * WPAD];
__device__ uint32_t g_w1cat[NB * 128 * 128];
__device__ uint32_t g_w2cat[NB * 64 * 128];

// ---------------------------------------------------------------------------
// tf32 helpers (plain mma.sync — compiles for base sm_103).
// NOTE: tf32 mma reads only the top 19 bits of each operand, so raw fp32
// bit patterns are valid operands (truncation-rounding).
// ---------------------------------------------------------------------------
__device__ __forceinline__ uint32_t f2tf(float f) {
    uint32_t r;
    asm("cvt.rna.tf32.f32 %0, %1;" : "=r"(r) : "f"(f));
    return r;
}

__device__ __forceinline__ void mma_tf32(float* d, const uint32_t* a, const uint32_t* b) {
    asm volatile(
        "mma.sync.aligned.m16n8k8.row.col.f32.tf32.tf32.f32 "
        "{%0,%1,%2,%3}, {%4,%5,%6,%7}, {%8,%9}, {%0,%1,%2,%3};"
        : "+f"(d[0]), "+f"(d[1]), "+f"(d[2]), "+f"(d[3])
        : "r"(a[0]), "r"(a[1]), "r"(a[2]), "r"(a[3]), "r"(b[0]), "r"(b[1]));
}

#define CP_ASYNC16(dst, src) \
    asm volatile("cp.async.cg.shared.global [%0], [%1], 16;" \
                 :: "r"(dst), "l"(src) : "memory")
#define CP_COMMIT()  asm volatile("cp.async.commit_group;" ::: "memory")
#define CP_WAIT(n)   asm volatile("cp.async.wait_group %0;" :: "n"(n) : "memory")

// ---------------------------------------------------------------------------
// Init kernels
// ---------------------------------------------------------------------------
__global__ void init_cas_kernel(float* __restrict__ out, int n) {
    int i = blockIdx.x * blockDim.x + threadIdx.x;
    if (i >= n * n) return;
    int t = i / n, d = i % n;
    long long m = (2LL * t * d) % (2LL * n);
    float a = (float)m / (float)n;
    float s, c;
    sincospif(a, &s, &c);
    out[i] = c + s;
}

__global__ void init_casw_pad_kernel() {
    int i = blockIdx.x * blockDim.x + threadIdx.x;
    if (i >= WPAD * WPAD) return;
    int t = i / WPAD, d = i % WPAD;
    float v = 0.f;
    if (t < W_DIM && d < W_DIM) {
        long long m = (2LL * t * d) % (2LL * W_DIM);
        float a = (float)m / (float)W_DIM;
        float s, c;
        sincospif(a, &s, &c);
        v = c + s;
    }
    g_casW[i] = v;
}

__global__ void prep_mlp_weights(const float* __restrict__ w1,
                                 const float* __restrict__ w2) {
    const int NW1 = NB * 128 * 128;
    const int NW2 = NB * 64 * 128;
    int idx = blockIdx.x * blockDim.x + threadIdx.x;
    if (idx < NW1) {
        int blk = idx >> 14;
        int rem = idx & 16383;
        int o = rem >> 7, i = rem & 127;
        const float* w1p = w1 + blk * 4096;
        const float* w1q = w1 + (NB + blk) * 4096;
        float v;
        if (o < 64) {
            if (i < 64) v = w1p[i * 64 + o] + w1q[i * 64 + o];
            else        v = w1p[(i - 64) * 64 + o] - w1q[(i - 64) * 64 + o];
        } else {
            int oo = o - 64;
            if (i < 64) v = w1p[i * 64 + oo] - w1q[i * 64 + oo];
            else        v = w1p[(i - 64) * 64 + oo] + w1q[(i - 64) * 64 + oo];
        }
        g_w1cat[idx] = f2tf(v);
    } else if (idx < NW1 + NW2) {
        int j = idx - NW1;
        int blk = j >> 13;
        int rem = j & 8191;
        int o = rem >> 7, i = rem & 127;
        const float* w2p = w2 + blk * 4096;
        const float* w2q = w2 + (NB + blk) * 4096;
        float v;
        if (i < 64) v = w2p[i * 64 + o] + w2q[i * 64 + o];
        else        v = w2p[(i - 64) * 64 + o] - w2q[(i - 64) * 64 + o];
        g_w2cat[j] = f2tf(v);
    }
}

__global__ void zeropad_kernel(float* __restrict__ buf) {
    int i = blockIdx.x * blockDim.x + threadIdx.x;
    if (i >= H_DIM * C_DIM * (WPAD - W_DIM)) return;
    int hc = i / (WPAD - W_DIM);
    int r = i - hc * (WPAD - W_DIM);
    buf[(size_t)hc * WPAD + W_DIM + r] = 0.f;
}

// ---------------------------------------------------------------------------
// tf32 warp-MMA GEMM with 2-stage cp.async pipeline, raw-fp32 operands.
// BM=BN=128, BK=32, 8 warps (2x4), warp tile 64x32, m16n8k8.
// ---------------------------------------------------------------------------
#define SMSTR 36
#define TS (128 * SMSTR)                  // one operand tile (uint32 elems)
#define GEMM_SMEM (2 * 2 * TS * 4)        // 73,728 bytes

__global__ void __launch_bounds__(256) tf32gemm_kernel(
    int M, int K, int aM,
    const float* __restrict__ A, int lda, long long sA,
    const float* __restrict__ Bt, int ldb, long long sB,
    float* __restrict__ C, int ldc, long long sC,
    float alpha, const float* __restrict__ Add, long long sAdd,
    int epi_mode)
{
    extern __shared__ uint32_t smd[];
    const uint32_t sbase = (uint32_t)__cvta_generic_to_shared(smd);

    const int tid  = threadIdx.x;
    const int lane = tid & 31;
    const int wid  = tid >> 5;
    const int wm   = wid & 1;
    const int wn   = wid >> 1;
    const int bm   = blockIdx.y * 128;
    const int bn   = blockIdx.x * 128;
    const int bz   = blockIdx.z;

    A  += (size_t)bz * sA;
    Bt += (size_t)bz * sB;
    C  += (size_t)bz * sC;

    float acc[4][4][4];
#pragma unroll
    for (int mi = 0; mi < 4; mi++)
#pragma unroll
        for (int ni = 0; ni < 4; ni++)
#pragma unroll
            for (int q = 0; q < 4; q++) acc[mi][ni][q] = 0.f;

    // per-thread fixed load slots: r = tid>>3 (+32*c), k4 = (tid&7)*4
    const int r_ld = tid >> 3;
    const int k4_ld = (tid & 7) << 2;

#define LOADTILE(k0, s)                                                       \
    do {                                                                      \
        _Pragma("unroll")                                                     \
        for (int c = 0; c < 4; c++) {                                         \
            int r = r_ld + c * 32;                                            \
            int ra = bm + r;                                                  \
            if (ra >= aM) ra = aM - 1;                                        \
            uint32_t da = sbase + (((s) * 2 * TS) + r * SMSTR + k4_ld) * 4;   \
            CP_ASYNC16(da, A + (size_t)ra * lda + (k0) + k4_ld);              \
            uint32_t db = sbase + (((s) * 2 * TS + TS) + r * SMSTR + k4_ld) * 4; \
            CP_ASYNC16(db, Bt + (size_t)(bn + r) * ldb + (k0) + k4_ld);       \
        }                                                                     \
        CP_COMMIT();                                                          \
    } while (0)

    const int nT = K >> 5;
    LOADTILE(0, 0);

    for (int t = 0; t < nT; t++) {
        const int s = t & 1;
        if (t + 1 < nT) {
            LOADTILE((t + 1) << 5, (t + 1) & 1);
            CP_WAIT(1);
        } else {
            CP_WAIT(0);
        }
        __syncthreads();

        const uint32_t* As = smd + s * 2 * TS;
        const uint32_t* Bs = As + TS;

#pragma unroll
        for (int kk = 0; kk < 4; kk++) {
            uint32_t af[4][4], bf[4][2];
            const int kc = kk * 8 + (lane & 3);
#pragma unroll
            for (int mi = 0; mi < 4; mi++) {
                int r0 = wm * 64 + mi * 16 + (lane >> 2);
                af[mi][0] = As[r0 * SMSTR + kc];
                af[mi][1] = As[(r0 + 8) * SMSTR + kc];
                af[mi][2] = As[r0 * SMSTR + kc + 4];
                af[mi][3] = As[(r0 + 8) * SMSTR + kc + 4];
            }
#pragma unroll
            for (int ni = 0; ni < 4; ni++) {
                int n0 = wn * 32 + ni * 8 + (lane >> 2);
                bf[ni][0] = Bs[n0 * SMSTR + kc];
                bf[ni][1] = Bs[n0 * SMSTR + kc + 4];
            }
#pragma unroll
            for (int mi = 0; mi < 4; mi++)
#pragma unroll
                for (int ni = 0; ni < 4; ni++)
                    mma_tf32(acc[mi][ni], af[mi], bf[ni]);
        }
        __syncthreads();
    }
#undef LOADTILE

    const float* addb = Add ? (Add + (size_t)bz * sAdd) : (const float*)0;
#pragma unroll
    for (int mi = 0; mi < 4; mi++) {
#pragma unroll
        for (int half = 0; half < 2; half++) {
            int r = wm * 64 + mi * 16 + (lane >> 2) + half * 8;
            int p = bm + r;
            if (p < M) {
                if (epi_mode == 0) {
                    float* cp = C + (size_t)p * ldc + bn;
                    const float* ap = addb ? (addb + (size_t)p * ldc + bn) : (const float*)0;
#pragma unroll
                    for (int ni = 0; ni < 4; ni++) {
                        int c0 = wn * 32 + ni * 8 + (lane & 3) * 2;
                        float2 v;
                        v.x = acc[mi][ni][half * 2 + 0] * alpha;
                        v.y = acc[mi][ni][half * 2 + 1] * alpha;
                        if (ap) {
                            float2 a2 = *(const float2*)(ap + c0);
                            v.x += a2.x; v.y += a2.y;
                        }
                        *(float2*)(cp + c0) = v;
                    }
                } else {
                    int h = p / W_DIM, w = p - h * W_DIM;
                    float* cp = C + (size_t)h * (C_DIM * WPAD) + w;
#pragma unroll
                    for (int ni = 0; ni < 4; ni++) {
                        int c0 = bn + wn * 32 + ni * 8 + (lane & 3) * 2;
                        cp[(size_t)c0 * WPAD]       = acc[mi][ni][half * 2 + 0];
                        cp[(size_t)(c0 + 1) * WPAD] = acc[mi][ni][half * 2 + 1];
                    }
                }
            }
        }
    }
}

// ---------------------------------------------------------------------------
// Tensor-core block-MLP + softshrink (raw-fp32 operand bits, no cvt).
// ---------------------------------------------------------------------------
#define MS 132
#define O2S 68
#define MLP_TC_SMEM ((128 * MS + 128 * MS + 64 * MS + 128 * O2S + 256) * 4)

__global__ void __launch_bounds__(256) mlp_tc_kernel(
    const float* __restrict__ xh,
    const float* __restrict__ b1,
    const float* __restrict__ b2,
    float* __restrict__ y)
{
    extern __shared__ uint32_t sm[];
    uint32_t* sA  = sm;
    uint32_t* sW1 = sA + 128 * MS;
    uint32_t* sW2 = sW1 + 128 * MS;
    uint32_t* sO2 = sW2 + 64 * MS;
    int* s_p  = (int*)(sO2 + 128 * O2S);
    int* s_pn = s_p + 128;

    const int tid  = threadIdx.x;
    const int lane = tid & 31;
    const int wid  = tid >> 5;
    const int wm   = wid & 1;
    const int wn   = wid >> 1;
    const int k    = blockIdx.y;
    const int p0   = blockIdx.x * 128;

    if (tid < 128) {
        int p = p0 + tid;
        if (p >= P_TOT) p = P_TOT - 1;
        int h = p / W_DIM, w = p - h * W_DIM;
        s_p[tid]  = p;
        s_pn[tid] = ((H_DIM - h) % H_DIM) * W_DIM + ((W_DIM - w) % W_DIM);
    }
    {
        const uint4* w1g = (const uint4*)(g_w1cat + k * 16384);
#pragma unroll
        for (int it = tid; it < 4096; it += 256) {
            int r = it >> 5, c4 = (it & 31) << 2;
            *(uint4*)&sW1[r * MS + c4] = w1g[it];
        }
        const uint4* w2g = (const uint4*)(g_w2cat + k * 8192);
#pragma unroll
        for (int it = tid; it < 2048; it += 256) {
            int r = it >> 5, c4 = (it & 31) << 2;
            *(uint4*)&sW2[r * MS + c4] = w2g[it];
        }
    }
    __syncthreads();

    // A1 = [xh | xn] tile (raw fp32 bits)
#pragma unroll
    for (int it = tid; it < 4096; it += 256) {
        int r = it >> 5, c = (it & 31) << 2;
        const float* src = (c < 64)
            ? xh + (size_t)s_p[r] * C_DIM + k * BS + c
            : xh + (size_t)s_pn[r] * C_DIM + k * BS + (c - 64);
        *(float4*)&sA[r * MS + c] = *(const float4*)src;
    }
    __syncthreads();

    // ---- Layer 1 ----
    float acc1[4][4][4];
#pragma unroll
    for (int mi = 0; mi < 4; mi++)
#pragma unroll
        for (int ni = 0; ni < 4; ni++)
#pragma unroll
            for (int q = 0; q < 4; q++) acc1[mi][ni][q] = 0.f;

#pragma unroll
    for (int kk = 0; kk < 16; kk++) {
        uint32_t af[4][4], bf[4][2];
        const int kc = kk * 8 + (lane & 3);
#pragma unroll
        for (int mi = 0; mi < 4; mi++) {
            int r0 = wm * 64 + mi * 16 + (lane >> 2);
            af[mi][0] = sA[r0 * MS + kc];
            af[mi][1] = sA[(r0 + 8) * MS + kc];
            af[mi][2] = sA[r0 * MS + kc + 4];
            af[mi][3] = sA[(r0 + 8) * MS + kc + 4];
        }
#pragma unroll
        for (int ni = 0; ni < 4; ni++) {
            int n0 = wn * 32 + ni * 8 + (lane >> 2);
            bf[ni][0] = sW1[n0 * MS + kc];
            bf[ni][1] = sW1[n0 * MS + kc + 4];
        }
#pragma unroll
        for (int mi = 0; mi < 4; mi++)
#pragma unroll
            for (int ni = 0; ni < 4; ni++)
                mma_tf32(acc1[mi][ni], af[mi], bf[ni]);
    }
    __syncthreads();

    // bias + relu, o1 -> sA (raw bits)
#pragma unroll
    for (int mi = 0; mi < 4; mi++)
#pragma unroll
        for (int half = 0; half < 2; half++) {
            int r = wm * 64 + mi * 16 + (lane >> 2) + half * 8;
#pragma unroll
            for (int ni = 0; ni < 4; ni++) {
                int c = wn * 32 + ni * 8 + (lane & 3) * 2;
                float bx = (c < 64) ? b1[k * BS + c] : b1[NB * BS + k * BS + (c - 64)];
                float by = (c + 1 < 64) ? b1[k * BS + c + 1] : b1[NB * BS + k * BS + (c + 1 - 64)];
                float vx = fmaxf(0.5f * acc1[mi][ni][half * 2 + 0] + bx, 0.f);
                float vy = fmaxf(0.5f * acc1[mi][ni][half * 2 + 1] + by, 0.f);
                sA[r * MS + c]     = __float_as_uint(vx);
                sA[r * MS + c + 1] = __float_as_uint(vy);
            }
        }
    __syncthreads();

    // ---- Layer 2a: o2k ----
    float acc2[4][2][4];
#pragma unroll
    for (int mi = 0; mi < 4; mi++)
#pragma unroll
        for (int ni = 0; ni < 2; ni++)
#pragma unroll
            for (int q = 0; q < 4; q++) acc2[mi][ni][q] = 0.f;

#pragma unroll
    for (int kk = 0; kk < 16; kk++) {
        uint32_t af[4][4], bf[2][2];
        const int kc = kk * 8 + (lane & 3);
#pragma unroll
        for (int mi = 0; mi < 4; mi++) {
            int r0 = wm * 64 + mi * 16 + (lane >> 2);
            af[mi][0] = sA[r0 * MS + kc];
            af[mi][1] = sA[(r0 + 8) * MS + kc];
            af[mi][2] = sA[r0 * MS + kc + 4];
            af[mi][3] = sA[(r0 + 8) * MS + kc + 4];
        }
#pragma unroll
        for (int ni = 0; ni < 2; ni++) {
            int n0 = wn * 16 + ni * 8 + (lane >> 2);
            bf[ni][0] = sW2[n0 * MS + kc];
            bf[ni][1] = sW2[n0 * MS + kc + 4];
        }
#pragma unroll
        for (int mi = 0; mi < 4; mi++)
#pragma unroll
            for (int ni = 0; ni < 2; ni++)
                mma_tf32(acc2[mi][ni], af[mi], bf[ni]);
    }

    float v2k[4][2][4];
#pragma unroll
    for (int mi = 0; mi < 4; mi++)
#pragma unroll
        for (int half = 0; half < 2; half++) {
            int r = wm * 64 + mi * 16 + (lane >> 2) + half * 8;
#pragma unroll
            for (int ni = 0; ni < 2; ni++) {
                int c = wn * 16 + ni * 8 + (lane & 3) * 2;
                float vx = 0.5f * acc2[mi][ni][half * 2 + 0] + b2[k * BS + c];
                float vy = 0.5f * acc2[mi][ni][half * 2 + 1] + b2[k * BS + c + 1];
                v2k[mi][ni][half * 2 + 0] = vx;
                v2k[mi][ni][half * 2 + 1] = vy;
                sO2[r * O2S + c]     = __float_as_uint(vx);
                sO2[r * O2S + c + 1] = __float_as_uint(vy);
            }
        }
    __syncthreads();

    // ---- Layer 2b: o2n ----
    float accn[4][2][4];
#pragma unroll
    for (int mi = 0; mi < 4; mi++)
#pragma unroll
        for (int ni = 0; ni < 2; ni++)
#pragma unroll
            for (int q = 0; q < 4; q++) accn[mi][ni][q] = 0.f;

#pragma unroll
    for (int kk = 0; kk < 8; kk++) {
        uint32_t af[4][4], bf[2][2];
        const int kc = kk * 8 + (lane & 3);
#pragma unroll
        for (int mi = 0; mi < 4; mi++) {
            int r0 = wm * 64 + mi * 16 + (lane >> 2);
            af[mi][0] = sA[r0 * MS + 64 + kc];
            af[mi][1] = sA[(r0 + 8) * MS + 64 + kc];
            af[mi][2] = sA[r0 * MS + 64 + kc + 4];
            af[mi][3] = sA[(r0 + 8) * MS + 64 + kc + 4];
        }
#pragma unroll
        for (int ni = 0; ni < 2; ni++) {
            int n0 = wn * 16 + ni * 8 + (lane >> 2);
            bf[ni][0] = sW2[n0 * MS + kc];
            bf[ni][1] = sW2[n0 * MS + kc + 4];
        }
#pragma unroll
        for (int mi = 0; mi < 4; mi++)
#pragma unroll
            for (int ni = 0; ni < 2; ni++)
                mma_tf32(accn[mi][ni], af[mi], bf[ni]);
    }
#pragma unroll
    for (int kk = 0; kk < 8; kk++) {
        uint32_t af[4][4], bf[2][2];
        const int kc = kk * 8 + (lane & 3);
#pragma unroll
        for (int mi = 0; mi < 4; mi++) {
            int r0 = wm * 64 + mi * 16 + (lane >> 2);
            af[mi][0] = sO2[r0 * O2S + kc];
            af[mi][1] = sO2[(r0 + 8) * O2S + kc];
            af[mi][2] = sO2[r0 * O2S + kc + 4];
            af[mi][3] = sO2[(r0 + 8) * O2S + kc + 4];
        }
#pragma unroll
        for (int ni = 0; ni < 2; ni++) {
            int n0 = wn * 16 + ni * 8 + (lane >> 2);
            bf[ni][0] = sW2[n0 * MS + 64 + kc];
            bf[ni][1] = sW2[n0 * MS + 64 + kc + 4];
        }
#pragma unroll
        for (int mi = 0; mi < 4; mi++)
#pragma unroll
            for (int ni = 0; ni < 2; ni++)
                mma_tf32(accn[mi][ni], af[mi], bf[ni]);
    }

#pragma unroll
    for (int mi = 0; mi < 4; mi++)
#pragma unroll
        for (int half = 0; half < 2; half++) {
            int r = wm * 64 + mi * 16 + (lane >> 2) + half * 8;
            int p = p0 + r;
            if (p < P_TOT) {
#pragma unroll
                for (int ni = 0; ni < 2; ni++) {
                    int c = wn * 16 + ni * 8 + (lane & 3) * 2;
                    float vx = v2k[mi][ni][half * 2 + 0]
                             + 0.5f * accn[mi][ni][half * 2 + 0] + b2[NB * BS + k * BS + c];
                    float vy = v2k[mi][ni][half * 2 + 1]
                             + 0.5f * accn[mi][ni][half * 2 + 1] + b2[NB * BS + k * BS + c + 1];
                    float ax = fabsf(vx) - SPARSITY;
                    float ay = fabsf(vy) - SPARSITY;
                    float2 rr;
                    rr.x = ax > 0.f ? copysignf(ax, vx) : 0.f;
                    rr.y = ay > 0.f ? copysignf(ay, vy) : 0.f;
                    *(float2*)(y + (size_t)p * C_DIM + k * BS + c) = rr;
                }
            }
        }
}

// ---------------------------------------------------------------------------
// kernel_launch
// ---------------------------------------------------------------------------
extern "C" void kernel_launch(void* const* d_in, const int* in_sizes, int n_in,
                              void* d_out, int out_size) {
    const float* x  = (const float*)d_in[0];
    const float* w1 = (const float*)d_in[1];
    const float* b1 = (const float*)d_in[2];
    const float* w2 = (const float*)d_in[3];
    const float* b2 = (const float*)d_in[4];
    float* out = (float*)d_out;

    float *bufA, *bufB, *casC, *casW;
    cudaGetSymbolAddress((void**)&bufA, g_bufA);
    cudaGetSymbolAddress((void**)&bufB, g_bufB);
    cudaGetSymbolAddress((void**)&casC, g_casC);
    cudaGetSymbolAddress((void**)&casW, g_casW);

    cudaFuncSetAttribute(mlp_tc_kernel, cudaFuncAttributeMaxDynamicSharedMemorySize,
                         MLP_TC_SMEM);
    cudaFuncSetAttribute(tf32gemm_kernel, cudaFuncAttributeMaxDynamicSharedMemorySize,
                         GEMM_SMEM);

    init_cas_kernel<<<(C_DIM * C_DIM + 255) / 256, 256>>>(casC, C_DIM);
    init_casw_pad_kernel<<<(WPAD * WPAD + 255) / 256, 256>>>();
    {
        int nprep = NB * 128 * 128 + NB * 64 * 128;
        prep_mlp_weights<<<(nprep + 255) / 256, 256>>>(w1, w2);
    }

    const long long sPadH = (long long)C_DIM * WPAD;
    const long long sCmpH = (long long)W_DIM * C_DIM;
    const int nPad = H_DIM * C_DIM * (WPAD - W_DIM);

    zeropad_kernel<<<(nPad + 255) / 256, 256>>>(bufA);

    // GEMM1: T1t = (X @ casC) -> transposed-padded bufA
    tf32gemm_kernel<<<dim3(C_DIM / 128, (P_TOT + 127) / 128, 1), 256, GEMM_SMEM>>>(
        P_TOT, C_DIM, P_TOT,
        x, C_DIM, 0,
        casC, C_DIM, 0,
        bufA, 0, 0,
        1.0f, nullptr, 0, 1);

    // GEMM2: XH[h] = casW @ T1[h] -> compact bufB
    tf32gemm_kernel<<<dim3(C_DIM / 128, 3, H_DIM), 256, GEMM_SMEM>>>(
        W_DIM, WPAD, WPAD,
        casW, WPAD, 0,
        bufA, WPAD, sPadH,
        bufB, C_DIM, sCmpH,
        1.0f, nullptr, 0, 0);

    // Tensor-core block MLP + softshrink: bufB -> bufA
    mlp_tc_kernel<<<dim3((P_TOT + 127) / 128, NB), 256, MLP_TC_SMEM>>>(
        bufB, b1, b2, bufA);

    zeropad_kernel<<<(nPad + 255) / 256, 256>>>(bufB);

    // GEMM3: T2t = (Y @ casC) -> transposed-padded bufB
    tf32gemm_kernel<<<dim3(C_DIM / 128, (P_TOT + 127) / 128, 1), 256, GEMM_SMEM>>>(
        P_TOT, C_DIM, P_TOT,
        bufA, C_DIM, 0,
        casC, C_DIM, 0,
        bufB, 0, 0,
        1.0f, nullptr, 0, 1);

    // GEMM4: out[h] = casW @ T2[h] / (W*C) + x[h]
    tf32gemm_kernel<<<dim3(C_DIM / 128, 3, H_DIM), 256, GEMM_SMEM>>>(
        W_DIM, WPAD, WPAD,
        casW, WPAD, 0,
        bufB, WPAD, sPadH,
        out, C_DIM, sCmpH,
        1.0f / (float)(W_DIM * C_DIM), x, sCmpH, 0);
}

// round 9
// speedup vs baseline: 3.2611x; 1.0234x over previous
#include <cuda_runtime.h>
#include <cstdint>

// Problem constants
#define H_DIM 180
#define W_DIM 360
#define WPAD  384
#define C_DIM 512
#define P_TOT (H_DIM * W_DIM)           // 64800
#define PADELEM (H_DIM * C_DIM * WPAD)
#define NB 8
#define BS 64
#define SPARSITY 0.01f

// ---------------------------------------------------------------------------
// Scratch
// ---------------------------------------------------------------------------
__device__ float g_bufA[PADELEM];
__device__ float g_bufB[PADELEM];
__device__ float g_casC[C_DIM * C_DIM];
__device__ float g_casW[WPAD * WPAD];
__device__ uint32_t g_w1cat[NB * 128 * 128];
__device__ uint32_t g_w2cat[NB * 64 * 128];

// ---------------------------------------------------------------------------
// tf32 helpers (plain mma.sync — compiles for base sm_103).
// ---------------------------------------------------------------------------
__device__ __forceinline__ uint32_t f2tf(float f) {
    uint32_t r;
    asm("cvt.rna.tf32.f32 %0, %1;" : "=r"(r) : "f"(f));
    return r;
}

__device__ __forceinline__ void mma_tf32(float* d, const uint32_t* a, const uint32_t* b) {
    asm volatile(
        "mma.sync.aligned.m16n8k8.row.col.f32.tf32.tf32.f32 "
        "{%0,%1,%2,%3}, {%4,%5,%6,%7}, {%8,%9}, {%0,%1,%2,%3};"
        : "+f"(d[0]), "+f"(d[1]), "+f"(d[2]), "+f"(d[3])
        : "r"(a[0]), "r"(a[1]), "r"(a[2]), "r"(a[3]), "r"(b[0]), "r"(b[1]));
}

#define CP_ASYNC16(dst, src) \
    asm volatile("cp.async.cg.shared.global [%0], [%1], 16;" \
                 :: "r"(dst), "l"(src) : "memory")
#define CP_COMMIT()  asm volatile("cp.async.commit_group;" ::: "memory")
#define CP_WAIT(n)   asm volatile("cp.async.wait_group %0;" :: "n"(n) : "memory")

// ---------------------------------------------------------------------------
// Init kernels
// ---------------------------------------------------------------------------
__global__ void init_cas_kernel(float* __restrict__ out, int n) {
    int i = blockIdx.x * blockDim.x + threadIdx.x;
    if (i >= n * n) return;
    int t = i / n, d = i % n;
    long long m = (2LL * t * d) % (2LL * n);
    float a = (float)m / (float)n;
    float s, c;
    sincospif(a, &s, &c);
    out[i] = c + s;
}

__global__ void init_casw_pad_kernel() {
    int i = blockIdx.x * blockDim.x + threadIdx.x;
    if (i >= WPAD * WPAD) return;
    int t = i / WPAD, d = i % WPAD;
    float v = 0.f;
    if (t < W_DIM && d < W_DIM) {
        long long m = (2LL * t * d) % (2LL * W_DIM);
        float a = (float)m / (float)W_DIM;
        float s, c;
        sincospif(a, &s, &c);
        v = c + s;
    }
    g_casW[i] = v;
}

__global__ void prep_mlp_weights(const float* __restrict__ w1,
                                 const float* __restrict__ w2) {
    const int NW1 = NB * 128 * 128;
    const int NW2 = NB * 64 * 128;
    int idx = blockIdx.x * blockDim.x + threadIdx.x;
    if (idx < NW1) {
        int blk = idx >> 14;
        int rem = idx & 16383;
        int o = rem >> 7, i = rem & 127;
        const float* w1p = w1 + blk * 4096;
        const float* w1q = w1 + (NB + blk) * 4096;
        float v;
        if (o < 64) {
            if (i < 64) v = w1p[i * 64 + o] + w1q[i * 64 + o];
            else        v = w1p[(i - 64) * 64 + o] - w1q[(i - 64) * 64 + o];
        } else {
            int oo = o - 64;
            if (i < 64) v = w1p[i * 64 + oo] - w1q[i * 64 + oo];
            else        v = w1p[(i - 64) * 64 + oo] + w1q[(i - 64) * 64 + oo];
        }
        g_w1cat[idx] = f2tf(v);
    } else if (idx < NW1 + NW2) {
        int j = idx - NW1;
        int blk = j >> 13;
        int rem = j & 8191;
        int o = rem >> 7, i = rem & 127;
        const float* w2p = w2 + blk * 4096;
        const float* w2q = w2 + (NB + blk) * 4096;
        float v;
        if (i < 64) v = w2p[i * 64 + o] + w2q[i * 64 + o];
        else        v = w2p[(i - 64) * 64 + o] - w2q[(i - 64) * 64 + o];
        g_w2cat[j] = f2tf(v);
    }
}

__global__ void zeropad_kernel(float* __restrict__ buf) {
    int i = blockIdx.x * blockDim.x + threadIdx.x;
    if (i >= H_DIM * C_DIM * (WPAD - W_DIM)) return;
    int hc = i / (WPAD - W_DIM);
    int r = i - hc * (WPAD - W_DIM);
    buf[(size_t)hc * WPAD + W_DIM + r] = 0.f;
}

// ---------------------------------------------------------------------------
// tf32 warp-MMA GEMM, 2-stage cp.async, raw-fp32 operands.
// BM=BN=128, BK=32, 4 warps (2x2), warp tile 64x64 (halves smem fragment
// re-reads vs the 8-warp 64x32 config: A and B each read 2x, not 4x/2x).
// ---------------------------------------------------------------------------
#define SMSTR 36
#define TS (128 * SMSTR)                  // one operand tile (uint32 elems)
#define GEMM_SMEM (2 * 2 * TS * 4)        // 73,728 bytes

__global__ void __launch_bounds__(128) tf32gemm_kernel(
    int M, int K, int aM,
    const float* __restrict__ A, int lda, long long sA,
    const float* __restrict__ Bt, int ldb, long long sB,
    float* __restrict__ C, int ldc, long long sC,
    float alpha, const float* __restrict__ Add, long long sAdd,
    int epi_mode)
{
    extern __shared__ uint32_t smd[];
    const uint32_t sbase = (uint32_t)__cvta_generic_to_shared(smd);

    const int tid  = threadIdx.x;
    const int lane = tid & 31;
    const int wid  = tid >> 5;
    const int wm   = wid & 1;       // warp row (2)
    const int wn   = wid >> 1;      // warp col (2)
    const int bm   = blockIdx.y * 128;
    const int bn   = blockIdx.x * 128;
    const int bz   = blockIdx.z;

    A  += (size_t)bz * sA;
    Bt += (size_t)bz * sB;
    C  += (size_t)bz * sC;

    float acc[4][8][4];
#pragma unroll
    for (int mi = 0; mi < 4; mi++)
#pragma unroll
        for (int ni = 0; ni < 8; ni++)
#pragma unroll
            for (int q = 0; q < 4; q++) acc[mi][ni][q] = 0.f;

    const int r_ld = tid >> 3;            // 0..15
    const int k4_ld = (tid & 7) << 2;     // 0..28

#define LOADTILE(k0, s)                                                        \
    do {                                                                       \
        _Pragma("unroll")                                                      \
        for (int c = 0; c < 8; c++) {                                          \
            int r = r_ld + c * 16;                                             \
            int ra = bm + r;                                                   \
            if (ra >= aM) ra = aM - 1;                                         \
            uint32_t da = sbase + (((s) * 2 * TS) + r * SMSTR + k4_ld) * 4;    \
            CP_ASYNC16(da, A + (size_t)ra * lda + (k0) + k4_ld);               \
            uint32_t db = sbase + (((s) * 2 * TS + TS) + r * SMSTR + k4_ld) * 4; \
            CP_ASYNC16(db, Bt + (size_t)(bn + r) * ldb + (k0) + k4_ld);        \
        }                                                                      \
        CP_COMMIT();                                                           \
    } while (0)

    const int nT = K >> 5;
    LOADTILE(0, 0);

    for (int t = 0; t < nT; t++) {
        const int s = t & 1;
        if (t + 1 < nT) {
            LOADTILE((t + 1) << 5, (t + 1) & 1);
            CP_WAIT(1);
        } else {
            CP_WAIT(0);
        }
        __syncthreads();

        const uint32_t* As = smd + s * 2 * TS;
        const uint32_t* Bs = As + TS;

#pragma unroll
        for (int kk = 0; kk < 4; kk++) {
            uint32_t af[4][4], bf[8][2];
            const int kc = kk * 8 + (lane & 3);
#pragma unroll
            for (int mi = 0; mi < 4; mi++) {
                int r0 = wm * 64 + mi * 16 + (lane >> 2);
                af[mi][0] = As[r0 * SMSTR + kc];
                af[mi][1] = As[(r0 + 8) * SMSTR + kc];
                af[mi][2] = As[r0 * SMSTR + kc + 4];
                af[mi][3] = As[(r0 + 8) * SMSTR + kc + 4];
            }
#pragma unroll
            for (int ni = 0; ni < 8; ni++) {
                int n0 = wn * 64 + ni * 8 + (lane >> 2);
                bf[ni][0] = Bs[n0 * SMSTR + kc];
                bf[ni][1] = Bs[n0 * SMSTR + kc + 4];
            }
#pragma unroll
            for (int mi = 0; mi < 4; mi++)
#pragma unroll
                for (int ni = 0; ni < 8; ni++)
                    mma_tf32(acc[mi][ni], af[mi], bf[ni]);
        }
        __syncthreads();
    }
#undef LOADTILE

    const float* addb = Add ? (Add + (size_t)bz * sAdd) : (const float*)0;
#pragma unroll
    for (int mi = 0; mi < 4; mi++) {
#pragma unroll
        for (int half = 0; half < 2; half++) {
            int r = wm * 64 + mi * 16 + (lane >> 2) + half * 8;
            int p = bm + r;
            if (p < M) {
                if (epi_mode == 0) {
                    float* cp = C + (size_t)p * ldc + bn;
                    const float* ap = addb ? (addb + (size_t)p * ldc + bn) : (const float*)0;
#pragma unroll
                    for (int ni = 0; ni < 8; ni++) {
                        int c0 = wn * 64 + ni * 8 + (lane & 3) * 2;
                        float2 v;
                        v.x = acc[mi][ni][half * 2 + 0] * alpha;
                        v.y = acc[mi][ni][half * 2 + 1] * alpha;
                        if (ap) {
                            float2 a2 = *(const float2*)(ap + c0);
                            v.x += a2.x; v.y += a2.y;
                        }
                        *(float2*)(cp + c0) = v;
                    }
                } else {
                    int h = p / W_DIM, w = p - h * W_DIM;
                    float* cp = C + (size_t)h * (C_DIM * WPAD) + w;
#pragma unroll
                    for (int ni = 0; ni < 8; ni++) {
                        int c0 = bn + wn * 64 + ni * 8 + (lane & 3) * 2;
                        cp[(size_t)c0 * WPAD]       = acc[mi][ni][half * 2 + 0];
                        cp[(size_t)(c0 + 1) * WPAD] = acc[mi][ni][half * 2 + 1];
                    }
                }
            }
        }
    }
}

// ---------------------------------------------------------------------------
// Tensor-core block-MLP + softshrink (raw-fp32 operand bits).
// ---------------------------------------------------------------------------
#define MS 132
#define O2S 68
#define MLP_TC_SMEM ((128 * MS + 128 * MS + 64 * MS + 128 * O2S + 256) * 4)

__global__ void __launch_bounds__(256) mlp_tc_kernel(
    const float* __restrict__ xh,
    const float* __restrict__ b1,
    const float* __restrict__ b2,
    float* __restrict__ y)
{
    extern __shared__ uint32_t sm[];
    uint32_t* sA  = sm;
    uint32_t* sW1 = sA + 128 * MS;
    uint32_t* sW2 = sW1 + 128 * MS;
    uint32_t* sO2 = sW2 + 64 * MS;
    int* s_p  = (int*)(sO2 + 128 * O2S);
    int* s_pn = s_p + 128;

    const int tid  = threadIdx.x;
    const int lane = tid & 31;
    const int wid  = tid >> 5;
    const int wm   = wid & 1;
    const int wn   = wid >> 1;
    const int k    = blockIdx.y;
    const int p0   = blockIdx.x * 128;

    if (tid < 128) {
        int p = p0 + tid;
        if (p >= P_TOT) p = P_TOT - 1;
        int h = p / W_DIM, w = p - h * W_DIM;
        s_p[tid]  = p;
        s_pn[tid] = ((H_DIM - h) % H_DIM) * W_DIM + ((W_DIM - w) % W_DIM);
    }
    {
        const uint4* w1g = (const uint4*)(g_w1cat + k * 16384);
#pragma unroll
        for (int it = tid; it < 4096; it += 256) {
            int r = it >> 5, c4 = (it & 31) << 2;
            *(uint4*)&sW1[r * MS + c4] = w1g[it];
        }
        const uint4* w2g = (const uint4*)(g_w2cat + k * 8192);
#pragma unroll
        for (int it = tid; it < 2048; it += 256) {
            int r = it >> 5, c4 = (it & 31) << 2;
            *(uint4*)&sW2[r * MS + c4] = w2g[it];
        }
    }
    __syncthreads();

#pragma unroll
    for (int it = tid; it < 4096; it += 256) {
        int r = it >> 5, c = (it & 31) << 2;
        const float* src = (c < 64)
            ? xh + (size_t)s_p[r] * C_DIM + k * BS + c
            : xh + (size_t)s_pn[r] * C_DIM + k * BS + (c - 64);
        *(float4*)&sA[r * MS + c] = *(const float4*)src;
    }
    __syncthreads();

    // ---- Layer 1 ----
    float acc1[4][4][4];
#pragma unroll
    for (int mi = 0; mi < 4; mi++)
#pragma unroll
        for (int ni = 0; ni < 4; ni++)
#pragma unroll
            for (int q = 0; q < 4; q++) acc1[mi][ni][q] = 0.f;

#pragma unroll
    for (int kk = 0; kk < 16; kk++) {
        uint32_t af[4][4], bf[4][2];
        const int kc = kk * 8 + (lane & 3);
#pragma unroll
        for (int mi = 0; mi < 4; mi++) {
            int r0 = wm * 64 + mi * 16 + (lane >> 2);
            af[mi][0] = sA[r0 * MS + kc];
            af[mi][1] = sA[(r0 + 8) * MS + kc];
            af[mi][2] = sA[r0 * MS + kc + 4];
            af[mi][3] = sA[(r0 + 8) * MS + kc + 4];
        }
#pragma unroll
        for (int ni = 0; ni < 4; ni++) {
            int n0 = wn * 32 + ni * 8 + (lane >> 2);
            bf[ni][0] = sW1[n0 * MS + kc];
            bf[ni][1] = sW1[n0 * MS + kc + 4];
        }
#pragma unroll
        for (int mi = 0; mi < 4; mi++)
#pragma unroll
            for (int ni = 0; ni < 4; ni++)
                mma_tf32(acc1[mi][ni], af[mi], bf[ni]);
    }
    __syncthreads();

#pragma unroll
    for (int mi = 0; mi < 4; mi++)
#pragma unroll
        for (int half = 0; half < 2; half++) {
            int r = wm * 64 + mi * 16 + (lane >> 2) + half * 8;
#pragma unroll
            for (int ni = 0; ni < 4; ni++) {
                int c = wn * 32 + ni * 8 + (lane & 3) * 2;
                float bx = (c < 64) ? b1[k * BS + c] : b1[NB * BS + k * BS + (c - 64)];
                float by = (c + 1 < 64) ? b1[k * BS + c + 1] : b1[NB * BS + k * BS + (c + 1 - 64)];
                float vx = fmaxf(0.5f * acc1[mi][ni][half * 2 + 0] + bx, 0.f);
                float vy = fmaxf(0.5f * acc1[mi][ni][half * 2 + 1] + by, 0.f);
                sA[r * MS + c]     = __float_as_uint(vx);
                sA[r * MS + c + 1] = __float_as_uint(vy);
            }
        }
    __syncthreads();

    // ---- Layer 2a: o2k ----
    float acc2[4][2][4];
#pragma unroll
    for (int mi = 0; mi < 4; mi++)
#pragma unroll
        for (int ni = 0; ni < 2; ni++)
#pragma unroll
            for (int q = 0; q < 4; q++) acc2[mi][ni][q] = 0.f;

#pragma unroll
    for (int kk = 0; kk < 16; kk++) {
        uint32_t af[4][4], bf[2][2];
        const int kc = kk * 8 + (lane & 3);
#pragma unroll
        for (int mi = 0; mi < 4; mi++) {
            int r0 = wm * 64 + mi * 16 + (lane >> 2);
            af[mi][0] = sA[r0 * MS + kc];
            af[mi][1] = sA[(r0 + 8) * MS + kc];
            af[mi][2] = sA[r0 * MS + kc + 4];
            af[mi][3] = sA[(r0 + 8) * MS + kc + 4];
        }
#pragma unroll
        for (int ni = 0; ni < 2; ni++) {
            int n0 = wn * 16 + ni * 8 + (lane >> 2);
            bf[ni][0] = sW2[n0 * MS + kc];
            bf[ni][1] = sW2[n0 * MS + kc + 4];
        }
#pragma unroll
        for (int mi = 0; mi < 4; mi++)
#pragma unroll
            for (int ni = 0; ni < 2; ni++)
                mma_tf32(acc2[mi][ni], af[mi], bf[ni]);
    }

    float v2k[4][2][4];
#pragma unroll
    for (int mi = 0; mi < 4; mi++)
#pragma unroll
        for (int half = 0; half < 2; half++) {
            int r = wm * 64 + mi * 16 + (lane >> 2) + half * 8;
#pragma unroll
            for (int ni = 0; ni < 2; ni++) {
                int c = wn * 16 + ni * 8 + (lane & 3) * 2;
                float vx = 0.5f * acc2[mi][ni][half * 2 + 0] + b2[k * BS + c];
                float vy = 0.5f * acc2[mi][ni][half * 2 + 1] + b2[k * BS + c + 1];
                v2k[mi][ni][half * 2 + 0] = vx;
                v2k[mi][ni][half * 2 + 1] = vy;
                sO2[r * O2S + c]     = __float_as_uint(vx);
                sO2[r * O2S + c + 1] = __float_as_uint(vy);
            }
        }
    __syncthreads();

    // ---- Layer 2b: o2n ----
    float accn[4][2][4];
#pragma unroll
    for (int mi = 0; mi < 4; mi++)
#pragma unroll
        for (int ni = 0; ni < 2; ni++)
#pragma unroll
            for (int q = 0; q < 4; q++) accn[mi][ni][q] = 0.f;

#pragma unroll
    for (int kk = 0; kk < 8; kk++) {
        uint32_t af[4][4], bf[2][2];
        const int kc = kk * 8 + (lane & 3);
#pragma unroll
        for (int mi = 0; mi < 4; mi++) {
            int r0 = wm * 64 + mi * 16 + (lane >> 2);
            af[mi][0] = sA[r0 * MS + 64 + kc];
            af[mi][1] = sA[(r0 + 8) * MS + 64 + kc];
            af[mi][2] = sA[r0 * MS + 64 + kc + 4];
            af[mi][3] = sA[(r0 + 8) * MS + 64 + kc + 4];
        }
#pragma unroll
        for (int ni = 0; ni < 2; ni++) {
            int n0 = wn * 16 + ni * 8 + (lane >> 2);
            bf[ni][0] = sW2[n0 * MS + kc];
            bf[ni][1] = sW2[n0 * MS + kc + 4];
        }
#pragma unroll
        for (int mi = 0; mi < 4; mi++)
#pragma unroll
            for (int ni = 0; ni < 2; ni++)
                mma_tf32(accn[mi][ni], af[mi], bf[ni]);
    }
#pragma unroll
    for (int kk = 0; kk < 8; kk++) {
        uint32_t af[4][4], bf[2][2];
        const int kc = kk * 8 + (lane & 3);
#pragma unroll
        for (int mi = 0; mi < 4; mi++) {
            int r0 = wm * 64 + mi * 16 + (lane >> 2);
            af[mi][0] = sO2[r0 * O2S + kc];
            af[mi][1] = sO2[(r0 + 8) * O2S + kc];
            af[mi][2] = sO2[r0 * O2S + kc + 4];
            af[mi][3] = sO2[(r0 + 8) * O2S + kc + 4];
        }
#pragma unroll
        for (int ni = 0; ni < 2; ni++) {
            int n0 = wn * 16 + ni * 8 + (lane >> 2);
            bf[ni][0] = sW2[n0 * MS + 64 + kc];
            bf[ni][1] = sW2[n0 * MS + 64 + kc + 4];
        }
#pragma unroll
        for (int mi = 0; mi < 4; mi++)
#pragma unroll
            for (int ni = 0; ni < 2; ni++)
                mma_tf32(accn[mi][ni], af[mi], bf[ni]);
    }

#pragma unroll
    for (int mi = 0; mi < 4; mi++)
#pragma unroll
        for (int half = 0; half < 2; half++) {
            int r = wm * 64 + mi * 16 + (lane >> 2) + half * 8;
            int p = p0 + r;
            if (p < P_TOT) {
#pragma unroll
                for (int ni = 0; ni < 2; ni++) {
                    int c = wn * 16 + ni * 8 + (lane & 3) * 2;
                    float vx = v2k[mi][ni][half * 2 + 0]
                             + 0.5f * accn[mi][ni][half * 2 + 0] + b2[NB * BS + k * BS + c];
                    float vy = v2k[mi][ni][half * 2 + 1]
                             + 0.5f * accn[mi][ni][half * 2 + 1] + b2[NB * BS + k * BS + c + 1];
                    float ax = fabsf(vx) - SPARSITY;
                    float ay = fabsf(vy) - SPARSITY;
                    float2 rr;
                    rr.x = ax > 0.f ? copysignf(ax, vx) : 0.f;
                    rr.y = ay > 0.f ? copysignf(ay, vy) : 0.f;
                    *(float2*)(y + (size_t)p * C_DIM + k * BS + c) = rr;
                }
            }
        }
}

// ---------------------------------------------------------------------------
// kernel_launch
// ---------------------------------------------------------------------------
extern "C" void kernel_launch(void* const* d_in, const int* in_sizes, int n_in,
                              void* d_out, int out_size) {
    const float* x  = (const float*)d_in[0];
    const float* w1 = (const float*)d_in[1];
    const float* b1 = (const float*)d_in[2];
    const float* w2 = (const float*)d_in[3];
    const float* b2 = (const float*)d_in[4];
    float* out = (float*)d_out;

    float *bufA, *bufB, *casC, *casW;
    cudaGetSymbolAddress((void**)&bufA, g_bufA);
    cudaGetSymbolAddress((void**)&bufB, g_bufB);
    cudaGetSymbolAddress((void**)&casC, g_casC);
    cudaGetSymbolAddress((void**)&casW, g_casW);

    cudaFuncSetAttribute(mlp_tc_kernel, cudaFuncAttributeMaxDynamicSharedMemorySize,
                         MLP_TC_SMEM);
    cudaFuncSetAttribute(tf32gemm_kernel, cudaFuncAttributeMaxDynamicSharedMemorySize,
                         GEMM_SMEM);

    init_cas_kernel<<<(C_DIM * C_DIM + 255) / 256, 256>>>(casC, C_DIM);
    init_casw_pad_kernel<<<(WPAD * WPAD + 255) / 256, 256>>>();
    {
        int nprep = NB * 128 * 128 + NB * 64 * 128;
        prep_mlp_weights<<<(nprep + 255) / 256, 256>>>(w1, w2);
    }

    const long long sPadH = (long long)C_DIM * WPAD;
    const long long sCmpH = (long long)W_DIM * C_DIM;
    const int nPad = H_DIM * C_DIM * (WPAD - W_DIM);

    zeropad_kernel<<<(nPad + 255) / 256, 256>>>(bufA);

    // GEMM1: T1t = (X @ casC) -> transposed-padded bufA
    tf32gemm_kernel<<<dim3(C_DIM / 128, (P_TOT + 127) / 128, 1), 128, GEMM_SMEM>>>(
        P_TOT, C_DIM, P_TOT,
        x, C_DIM, 0,
        casC, C_DIM, 0,
        bufA, 0, 0,
        1.0f, nullptr, 0, 1);

    // GEMM2: XH[h] = casW @ T1[h] -> compact bufB
    tf32gemm_kernel<<<dim3(C_DIM / 128, 3, H_DIM), 128, GEMM_SMEM>>>(
        W_DIM, WPAD, WPAD,
        casW, WPAD, 0,
        bufA, WPAD, sPadH,
        bufB, C_DIM, sCmpH,
        1.0f, nullptr, 0, 0);

    // Tensor-core block MLP + softshrink: bufB -> bufA
    mlp_tc_kernel<<<dim3((P_TOT + 127) / 128, NB), 256, MLP_TC_SMEM>>>(
        bufB, b1, b2, bufA);

    zeropad_kernel<<<(nPad + 255) / 256, 256>>>(bufB);

    // GEMM3: T2t = (Y @ casC) -> transposed-padded bufB
    tf32gemm_kernel<<<dim3(C_DIM / 128, (P_TOT + 127) / 128, 1), 128, GEMM_SMEM>>>(
        P_TOT, C_DIM, P_TOT,
        bufA, C_DIM, 0,
        casC, C_DIM, 0,
        bufB, 0, 0,
        1.0f, nullptr, 0, 1);

    // GEMM4: out[h] = casW @ T2[h] / (W*C) + x[h]
    tf32gemm_kernel<<<dim3(C_DIM / 128, 3, H_DIM), 128, GEMM_SMEM>>>(
        W_DIM, WPAD, WPAD,
        casW, WPAD, 0,
        bufB, WPAD, sPadH,
        out, C_DIM, sCmpH,
        1.0f / (float)(W_DIM * C_DIM), x, sCmpH, 0);
}

// round 11
// speedup vs baseline: 5.1707x; 1.5856x over previous
#include <cuda_runtime.h>
#include <cuda_bf16.h>
#include <cstdint>

// Problem constants
#define H_DIM 180
#define W_DIM 360
#define WPAD  384
#define C_DIM 512
#define P_TOT (H_DIM * W_DIM)           // 64800
#define NELEM (P_TOT * C_DIM)
#define PADELEM (H_DIM * C_DIM * WPAD)
#define NB 8
#define BS 64
#define SPARSITY 0.01f

typedef __nv_bfloat16 bf16;

// ---------------------------------------------------------------------------
// Scratch (bf16 activations)
// ---------------------------------------------------------------------------
__device__ bf16 g_bufA[PADELEM];
__device__ bf16 g_bufB[PADELEM];
__device__ bf16 g_xbf[NELEM];
__device__ bf16 g_casC[C_DIM * C_DIM];
__device__ bf16 g_casW[WPAD * WPAD];
__device__ uint32_t g_w1cat[NB * 128 * 64];   // [blk][o][ipair] bf16x2
__device__ uint32_t g_w2cat[NB * 64 * 64];    // [blk][o][ipair] bf16x2

// ---------------------------------------------------------------------------
// bf16 helpers (plain mma.sync m16n8k16 — compiles for base sm_103)
// ---------------------------------------------------------------------------
__device__ __forceinline__ uint32_t packbf(float lo, float hi) {
    uint32_t r;
    asm("cvt.rn.bf16x2.f32 %0, %1, %2;" : "=r"(r) : "f"(hi), "f"(lo));
    return r;
}

__device__ __forceinline__ void mma_bf16(float* d, const uint32_t* a, const uint32_t* b) {
    asm volatile(
        "mma.sync.aligned.m16n8k16.row.col.f32.bf16.bf16.f32 "
        "{%0,%1,%2,%3}, {%4,%5,%6,%7}, {%8,%9}, {%0,%1,%2,%3};"
        : "+f"(d[0]), "+f"(d[1]), "+f"(d[2]), "+f"(d[3])
        : "r"(a[0]), "r"(a[1]), "r"(a[2]), "r"(a[3]), "r"(b[0]), "r"(b[1]));
}

#define CP_ASYNC16(dst, src) \
    asm volatile("cp.async.cg.shared.global [%0], [%1], 16;" \
                 :: "r"(dst), "l"(src) : "memory")
#define CP_COMMIT()  asm volatile("cp.async.commit_group;" ::: "memory")
#define CP_WAIT(n)   asm volatile("cp.async.wait_group %0;" :: "n"(n) : "memory")

// ---------------------------------------------------------------------------
// Init kernels
// ---------------------------------------------------------------------------
__global__ void init_cas_kernel(bf16* __restrict__ out, int n) {
    int i = blockIdx.x * blockDim.x + threadIdx.x;
    if (i >= n * n) return;
    int t = i / n, d = i % n;
    long long m = (2LL * t * d) % (2LL * n);
    float a = (float)m / (float)n;
    float s, c;
    sincospif(a, &s, &c);
    out[i] = __float2bfloat16_rn(c + s);
}

__global__ void init_casw_pad_kernel() {
    int i = blockIdx.x * blockDim.x + threadIdx.x;
    if (i >= WPAD * WPAD) return;
    int t = i / WPAD, d = i % WPAD;
    float v = 0.f;
    if (t < W_DIM && d < W_DIM) {
        long long m = (2LL * t * d) % (2LL * W_DIM);
        float a = (float)m / (float)W_DIM;
        float s, c;
        sincospif(a, &s, &c);
        v = c + s;
    }
    g_casW[i] = __float2bfloat16_rn(v);
}

__global__ void convert_x_kernel(const float* __restrict__ x) {
    int i = blockIdx.x * blockDim.x + threadIdx.x;   // processes 4 elems
    if (i >= NELEM / 4) return;
    float4 v = *(const float4*)(x + i * 4);
    uint2 u;
    u.x = packbf(v.x, v.y);
    u.y = packbf(v.z, v.w);
    *(uint2*)((char*)g_xbf + i * 8) = u;
}

// Packed bf16-pair MLP weights, pre-transposed (see R7 derivation).
__global__ void prep_mlp_weights(const float* __restrict__ w1,
                                 const float* __restrict__ w2) {
    const int NW1 = NB * 128 * 64;
    const int NW2 = NB * 64 * 64;
    int idx = blockIdx.x * blockDim.x + threadIdx.x;
    if (idx < NW1) {
        int blk = idx >> 13;
        int rem = idx & 8191;
        int o = rem >> 6, j = rem & 63;
        const float* w1p = w1 + blk * 4096;
        const float* w1q = w1 + (NB + blk) * 4096;
        float v[2];
#pragma unroll
        for (int q = 0; q < 2; q++) {
            int i = 2 * j + q;
            if (o < 64) {
                if (i < 64) v[q] = w1p[i * 64 + o] + w1q[i * 64 + o];
                else        v[q] = w1p[(i - 64) * 64 + o] - w1q[(i - 64) * 64 + o];
            } else {
                int oo = o - 64;
                if (i < 64) v[q] = w1p[i * 64 + oo] - w1q[i * 64 + oo];
                else        v[q] = w1p[(i - 64) * 64 + oo] + w1q[(i - 64) * 64 + oo];
            }
        }
        g_w1cat[idx] = packbf(v[0], v[1]);
    } else if (idx < NW1 + NW2) {
        int jx = idx - NW1;
        int blk = jx >> 12;
        int rem = jx & 4095;
        int o = rem >> 6, j = rem & 63;
        const float* w2p = w2 + blk * 4096;
        const float* w2q = w2 + (NB + blk) * 4096;
        float v[2];
#pragma unroll
        for (int q = 0; q < 2; q++) {
            int i = 2 * j + q;
            if (i < 64) v[q] = w2p[i * 64 + o] + w2q[i * 64 + o];
            else        v[q] = w2p[(i - 64) * 64 + o] - w2q[(i - 64) * 64 + o];
        }
        g_w2cat[jx] = packbf(v[0], v[1]);
    }
}

// zero pad w in [360,384) of a [h][c][wpad] bf16 buffer (12 uint32 per row)
__global__ void zeropad_kernel(bf16* __restrict__ buf) {
    int i = blockIdx.x * blockDim.x + threadIdx.x;
    if (i >= H_DIM * C_DIM * 12) return;
    int hc = i / 12;
    int r = i - hc * 12;
    ((uint32_t*)buf)[(size_t)hc * (WPAD / 2) + 180 + r] = 0u;
}

// ---------------------------------------------------------------------------
// bf16 warp-MMA GEMM, 2-stage cp.async, m16n8k16.
// BM=BN=128, BK=32, 4 warps (2x2), warp tile 64x64.
// ---------------------------------------------------------------------------
#define STR 20
#define TS2 (128 * STR)
#define GEMM_SMEM (2 * 2 * TS2 * 4)       // 40,960 bytes

__global__ void __launch_bounds__(128) bf16gemm_kernel(
    int M, int K, int aM,
    const bf16* __restrict__ A, int lda, long long sA,
    const bf16* __restrict__ Bt, int ldb, long long sB,
    void* __restrict__ Cv, int ldc, long long sC,
    float alpha, const float* __restrict__ Add, long long sAdd,
    int epi_mode)
{
    extern __shared__ uint32_t smd[];
    const uint32_t sbase = (uint32_t)__cvta_generic_to_shared(smd);

    const int tid  = threadIdx.x;
    const int lane = tid & 31;
    const int wid  = tid >> 5;
    const int wm   = wid & 1;
    const int wn   = wid >> 1;
    const int bm   = blockIdx.y * 128;
    const int bn   = blockIdx.x * 128;
    const int bz   = blockIdx.z;

    A  += (size_t)bz * sA;
    Bt += (size_t)bz * sB;

    float acc[4][8][4];
#pragma unroll
    for (int mi = 0; mi < 4; mi++)
#pragma unroll
        for (int ni = 0; ni < 8; ni++)
#pragma unroll
            for (int q = 0; q < 4; q++) acc[mi][ni][q] = 0.f;

    const int r_ld = tid >> 2;            // 0..31
    const int k8   = (tid & 3) << 3;      // bf16 offset 0,8,16,24

#define LOADTILE(k0, s)                                                        \
    do {                                                                       \
        _Pragma("unroll")                                                      \
        for (int c = 0; c < 4; c++) {                                          \
            int r = r_ld + c * 32;                                             \
            int ra = bm + r;                                                   \
            if (ra >= aM) ra = aM - 1;                                         \
            uint32_t da = sbase + (((s) * 2 * TS2) + r * STR + (k8 >> 1)) * 4; \
            CP_ASYNC16(da, A + (size_t)ra * lda + (k0) + k8);                  \
            uint32_t db = sbase + (((s) * 2 * TS2 + TS2) + r * STR + (k8 >> 1)) * 4; \
            CP_ASYNC16(db, Bt + (size_t)(bn + r) * ldb + (k0) + k8);           \
        }                                                                      \
        CP_COMMIT();                                                           \
    } while (0)

    const int nT = K >> 5;
    LOADTILE(0, 0);

    for (int t = 0; t < nT; t++) {
        const int s = t & 1;
        if (t + 1 < nT) {
            LOADTILE((t + 1) << 5, (t + 1) & 1);
            CP_WAIT(1);
        } else {
            CP_WAIT(0);
        }
        __syncthreads();

        const uint32_t* As = smd + s * 2 * TS2;
        const uint32_t* Bs = As + TS2;

#pragma unroll
        for (int kk = 0; kk < 2; kk++) {             // two k16 steps per BK=32
            uint32_t af[4][4], bf[8][2];
            const int kp = kk * 8 + (lane & 3);
#pragma unroll
            for (int mi = 0; mi < 4; mi++) {
                int r0 = wm * 64 + mi * 16 + (lane >> 2);
                af[mi][0] = As[r0 * STR + kp];
                af[mi][1] = As[(r0 + 8) * STR + kp];
                af[mi][2] = As[r0 * STR + kp + 4];
                af[mi][3] = As[(r0 + 8) * STR + kp + 4];
            }
#pragma unroll
            for (int ni = 0; ni < 8; ni++) {
                int n0 = wn * 64 + ni * 8 + (lane >> 2);
                bf[ni][0] = Bs[n0 * STR + kp];
                bf[ni][1] = Bs[n0 * STR + kp + 4];
            }
#pragma unroll
            for (int mi = 0; mi < 4; mi++)
#pragma unroll
                for (int ni = 0; ni < 8; ni++)
                    mma_bf16(acc[mi][ni], af[mi], bf[ni]);
        }
        __syncthreads();
    }
#undef LOADTILE

    const float* addb = Add ? (Add + (size_t)bz * sAdd) : (const float*)0;
#pragma unroll
    for (int mi = 0; mi < 4; mi++) {
#pragma unroll
        for (int half = 0; half < 2; half++) {
            int r = wm * 64 + mi * 16 + (lane >> 2) + half * 8;
            int p = bm + r;
            if (p >= M) continue;
            if (epi_mode == 0) {
                float* cp = (float*)Cv + (size_t)bz * sC + (size_t)p * ldc + bn;
                const float* ap = addb ? (addb + (size_t)p * ldc + bn) : (const float*)0;
#pragma unroll
                for (int ni = 0; ni < 8; ni++) {
                    int c0 = wn * 64 + ni * 8 + (lane & 3) * 2;
                    float2 v;
                    v.x = acc[mi][ni][half * 2 + 0] * alpha;
                    v.y = acc[mi][ni][half * 2 + 1] * alpha;
                    if (ap) {
                        float2 a2 = *(const float2*)(ap + c0);
                        v.x += a2.x; v.y += a2.y;
                    }
                    *(float2*)(cp + c0) = v;
                }
            } else if (epi_mode == 2) {
                bf16* cp = (bf16*)Cv + (size_t)bz * sC + (size_t)p * ldc + bn;
#pragma unroll
                for (int ni = 0; ni < 8; ni++) {
                    int c0 = wn * 64 + ni * 8 + (lane & 3) * 2;
                    *(uint32_t*)(cp + c0) =
                        packbf(acc[mi][ni][half * 2 + 0], acc[mi][ni][half * 2 + 1]);
                }
            } else {
                int h = p / W_DIM, w = p - h * W_DIM;
                bf16* cp = (bf16*)Cv + (size_t)h * (C_DIM * WPAD) + w;
#pragma unroll
                for (int ni = 0; ni < 8; ni++) {
                    int c0 = bn + wn * 64 + ni * 8 + (lane & 3) * 2;
                    cp[(size_t)c0 * WPAD]       = __float2bfloat16_rn(acc[mi][ni][half * 2 + 0]);
                    cp[(size_t)(c0 + 1) * WPAD] = __float2bfloat16_rn(acc[mi][ni][half * 2 + 1]);
                }
            }
        }
    }
}

// ---------------------------------------------------------------------------
// bf16 tensor-core block-MLP + softshrink. 256 threads, 8 warps (2x4).
// ---------------------------------------------------------------------------
#define MS2 68
#define O2S2 36
#define MLP_TC_SMEM ((128 * MS2 + 128 * MS2 + 64 * MS2 + 128 * O2S2 + 256) * 4)

__global__ void __launch_bounds__(256) mlp_tc_kernel(
    const bf16* __restrict__ xh,
    const float* __restrict__ b1,
    const float* __restrict__ b2,
    bf16* __restrict__ y)
{
    extern __shared__ uint32_t sm[];
    uint32_t* sA  = sm;                      // 128 x MS2 (A1/o1, bf16 pairs)
    uint32_t* sW1 = sA + 128 * MS2;          // 128 x MS2
    uint32_t* sW2 = sW1 + 128 * MS2;         // 64 x MS2
    uint32_t* sO2 = sW2 + 64 * MS2;          // 128 x O2S2
    int* s_p  = (int*)(sO2 + 128 * O2S2);
    int* s_pn = s_p + 128;

    const int tid  = threadIdx.x;
    const int lane = tid & 31;
    const int wid  = tid >> 5;
    const int wm   = wid & 1;
    const int wn   = wid >> 1;
    const int k    = blockIdx.y;
    const int p0   = blockIdx.x * 128;

    if (tid < 128) {
        int p = p0 + tid;
        if (p >= P_TOT) p = P_TOT - 1;
        int h = p / W_DIM, w = p - h * W_DIM;
        s_p[tid]  = p;
        s_pn[tid] = ((H_DIM - h) % H_DIM) * W_DIM + ((W_DIM - w) % W_DIM);
    }
    {
        const uint4* w1g = (const uint4*)(g_w1cat + k * 8192);
#pragma unroll
        for (int it = tid; it < 2048; it += 256) {
            int r = it >> 4, c4 = (it & 15) << 2;
            *(uint4*)&sW1[r * MS2 + c4] = w1g[it];
        }
        const uint4* w2g = (const uint4*)(g_w2cat + k * 4096);
#pragma unroll
        for (int it = tid; it < 1024; it += 256) {
            int r = it >> 4, c4 = (it & 15) << 2;
            *(uint4*)&sW2[r * MS2 + c4] = w2g[it];
        }
    }
    __syncthreads();

    // A1 = [xh | xn] tile, bf16 pairs. FIXED: cover all 128 bf16 cols
    // (4096 iterations x 4 cols), not 2048 (which left cols 64..127 garbage).
#pragma unroll
    for (int it = tid; it < 4096; it += 256) {
        int r = it >> 5;
        int c = (it & 31) * 4;               // bf16 col 0..124 step 4
        const bf16* src = (c < 64)
            ? xh + (size_t)s_p[r] * C_DIM + k * BS + c
            : xh + (size_t)s_pn[r] * C_DIM + k * BS + (c - 64);
        *(uint2*)&sA[r * MS2 + (c >> 1)] = *(const uint2*)src;
    }
    __syncthreads();

    // ---- Layer 1: [o1k|o1n] = A1 @ W1cat, K=128 (8 k16 steps) ----
    float acc1[4][4][4];
#pragma unroll
    for (int mi = 0; mi < 4; mi++)
#pragma unroll
        for (int ni = 0; ni < 4; ni++)
#pragma unroll
            for (int q = 0; q < 4; q++) acc1[mi][ni][q] = 0.f;

#pragma unroll
    for (int kk = 0; kk < 8; kk++) {
        uint32_t af[4][4], bf[4][2];
        const int kp = kk * 8 + (lane & 3);
#pragma unroll
        for (int mi = 0; mi < 4; mi++) {
            int r0 = wm * 64 + mi * 16 + (lane >> 2);
            af[mi][0] = sA[r0 * MS2 + kp];
            af[mi][1] = sA[(r0 + 8) * MS2 + kp];
            af[mi][2] = sA[r0 * MS2 + kp + 4];
            af[mi][3] = sA[(r0 + 8) * MS2 + kp + 4];
        }
#pragma unroll
        for (int ni = 0; ni < 4; ni++) {
            int n0 = wn * 32 + ni * 8 + (lane >> 2);
            bf[ni][0] = sW1[n0 * MS2 + kp];
            bf[ni][1] = sW1[n0 * MS2 + kp + 4];
        }
#pragma unroll
        for (int mi = 0; mi < 4; mi++)
#pragma unroll
            for (int ni = 0; ni < 4; ni++)
                mma_bf16(acc1[mi][ni], af[mi], bf[ni]);
    }
    __syncthreads();

    // bias + relu -> sA (bf16 pairs)
#pragma unroll
    for (int mi = 0; mi < 4; mi++)
#pragma unroll
        for (int half = 0; half < 2; half++) {
            int r = wm * 64 + mi * 16 + (lane >> 2) + half * 8;
#pragma unroll
            for (int ni = 0; ni < 4; ni++) {
                int c = wn * 32 + ni * 8 + (lane & 3) * 2;
                float bx = (c < 64) ? b1[k * BS + c] : b1[NB * BS + k * BS + (c - 64)];
                float by = (c + 1 < 64) ? b1[k * BS + c + 1] : b1[NB * BS + k * BS + (c + 1 - 64)];
                float vx = fmaxf(0.5f * acc1[mi][ni][half * 2 + 0] + bx, 0.f);
                float vy = fmaxf(0.5f * acc1[mi][ni][half * 2 + 1] + by, 0.f);
                sA[r * MS2 + (c >> 1)] = packbf(vx, vy);
            }
        }
    __syncthreads();

    // ---- Layer 2a: o2k = o1 @ W2cat, K=128 ----
    float acc2[4][2][4];
#pragma unroll
    for (int mi = 0; mi < 4; mi++)
#pragma unroll
        for (int ni = 0; ni < 2; ni++)
#pragma unroll
            for (int q = 0; q < 4; q++) acc2[mi][ni][q] = 0.f;

#pragma unroll
    for (int kk = 0; kk < 8; kk++) {
        uint32_t af[4][4], bf[2][2];
        const int kp = kk * 8 + (lane & 3);
#pragma unroll
        for (int mi = 0; mi < 4; mi++) {
            int r0 = wm * 64 + mi * 16 + (lane >> 2);
            af[mi][0] = sA[r0 * MS2 + kp];
            af[mi][1] = sA[(r0 + 8) * MS2 + kp];
            af[mi][2] = sA[r0 * MS2 + kp + 4];
            af[mi][3] = sA[(r0 + 8) * MS2 + kp + 4];
        }
#pragma unroll
        for (int ni = 0; ni < 2; ni++) {
            int n0 = wn * 16 + ni * 8 + (lane >> 2);
            bf[ni][0] = sW2[n0 * MS2 + kp];
            bf[ni][1] = sW2[n0 * MS2 + kp + 4];
        }
#pragma unroll
        for (int mi = 0; mi < 4; mi++)
#pragma unroll
            for (int ni = 0; ni < 2; ni++)
                mma_bf16(acc2[mi][ni], af[mi], bf[ni]);
    }

    float v2k[4][2][4];
#pragma unroll
    for (int mi = 0; mi < 4; mi++)
#pragma unroll
        for (int half = 0; half < 2; half++) {
            int r = wm * 64 + mi * 16 + (lane >> 2) + half * 8;
#pragma unroll
            for (int ni = 0; ni < 2; ni++) {
                int c = wn * 16 + ni * 8 + (lane & 3) * 2;
                float vx = 0.5f * acc2[mi][ni][half * 2 + 0] + b2[k * BS + c];
                float vy = 0.5f * acc2[mi][ni][half * 2 + 1] + b2[k * BS + c + 1];
                v2k[mi][ni][half * 2 + 0] = vx;
                v2k[mi][ni][half * 2 + 1] = vy;
                sO2[r * O2S2 + (c >> 1)] = packbf(vx, vy);
            }
        }
    __syncthreads();

    // ---- Layer 2b: o2n = o1n @ w2a + o2k @ w2b (two K=64 passes) ----
    float accn[4][2][4];
#pragma unroll
    for (int mi = 0; mi < 4; mi++)
#pragma unroll
        for (int ni = 0; ni < 2; ni++)
#pragma unroll
            for (int q = 0; q < 4; q++) accn[mi][ni][q] = 0.f;

#pragma unroll
    for (int kk = 0; kk < 4; kk++) {
        uint32_t af[4][4], bf[2][2];
        const int kp = kk * 8 + (lane & 3);
#pragma unroll
        for (int mi = 0; mi < 4; mi++) {
            int r0 = wm * 64 + mi * 16 + (lane >> 2);
            af[mi][0] = sA[r0 * MS2 + 32 + kp];
            af[mi][1] = sA[(r0 + 8) * MS2 + 32 + kp];
            af[mi][2] = sA[r0 * MS2 + 32 + kp + 4];
            af[mi][3] = sA[(r0 + 8) * MS2 + 32 + kp + 4];
        }
#pragma unroll
        for (int ni = 0; ni < 2; ni++) {
            int n0 = wn * 16 + ni * 8 + (lane >> 2);
            bf[ni][0] = sW2[n0 * MS2 + kp];
            bf[ni][1] = sW2[n0 * MS2 + kp + 4];
        }
#pragma unroll
        for (int mi = 0; mi < 4; mi++)
#pragma unroll
            for (int ni = 0; ni < 2; ni++)
                mma_bf16(accn[mi][ni], af[mi], bf[ni]);
    }
#pragma unroll
    for (int kk = 0; kk < 4; kk++) {
        uint32_t af[4][4], bf[2][2];
        const int kp = kk * 8 + (lane & 3);
#pragma unroll
        for (int mi = 0; mi < 4; mi++) {
            int r0 = wm * 64 + mi * 16 + (lane >> 2);
            af[mi][0] = sO2[r0 * O2S2 + kp];
            af[mi][1] = sO2[(r0 + 8) * O2S2 + kp];
            af[mi][2] = sO2[r0 * O2S2 + kp + 4];
            af[mi][3] = sO2[(r0 + 8) * O2S2 + kp + 4];
        }
#pragma unroll
        for (int ni = 0; ni < 2; ni++) {
            int n0 = wn * 16 + ni * 8 + (lane >> 2);
            bf[ni][0] = sW2[n0 * MS2 + 32 + kp];
            bf[ni][1] = sW2[n0 * MS2 + 32 + kp + 4];
        }
#pragma unroll
        for (int mi = 0; mi < 4; mi++)
#pragma unroll
            for (int ni = 0; ni < 2; ni++)
                mma_bf16(accn[mi][ni], af[mi], bf[ni]);
    }

    // y = softshrink(o2k + o2n)  (bf16 compact)
#pragma unroll
    for (int mi = 0; mi < 4; mi++)
#pragma unroll
        for (int half = 0; half < 2; half++) {
            int r = wm * 64 + mi * 16 + (lane >> 2) + half * 8;
            int p = p0 + r;
            if (p < P_TOT) {
#pragma unroll
                for (int ni = 0; ni < 2; ni++) {
                    int c = wn * 16 + ni * 8 + (lane & 3) * 2;
                    float vx = v2k[mi][ni][half * 2 + 0]
                             + 0.5f * accn[mi][ni][half * 2 + 0] + b2[NB * BS + k * BS + c];
                    float vy = v2k[mi][ni][half * 2 + 1]
                             + 0.5f * accn[mi][ni][half * 2 + 1] + b2[NB * BS + k * BS + c + 1];
                    float ax = fabsf(vx) - SPARSITY;
                    float ay = fabsf(vy) - SPARSITY;
                    float rx = ax > 0.f ? copysignf(ax, vx) : 0.f;
                    float ry = ay > 0.f ? copysignf(ay, vy) : 0.f;
                    *(uint32_t*)(y + (size_t)p * C_DIM + k * BS + c) = packbf(rx, ry);
                }
            }
        }
}

// ---------------------------------------------------------------------------
// kernel_launch
// ---------------------------------------------------------------------------
extern "C" void kernel_launch(void* const* d_in, const int* in_sizes, int n_in,
                              void* d_out, int out_size) {
    const float* x  = (const float*)d_in[0];
    const float* w1 = (const float*)d_in[1];
    const float* b1 = (const float*)d_in[2];
    const float* w2 = (const float*)d_in[3];
    const float* b2 = (const float*)d_in[4];
    float* out = (float*)d_out;

    bf16 *bufA, *bufB, *casC, *casW, *xbf;
    cudaGetSymbolAddress((void**)&bufA, g_bufA);
    cudaGetSymbolAddress((void**)&bufB, g_bufB);
    cudaGetSymbolAddress((void**)&casC, g_casC);
    cudaGetSymbolAddress((void**)&casW, g_casW);
    cudaGetSymbolAddress((void**)&xbf,  g_xbf);

    cudaFuncSetAttribute(mlp_tc_kernel, cudaFuncAttributeMaxDynamicSharedMemorySize,
                         MLP_TC_SMEM);
    cudaFuncSetAttribute(bf16gemm_kernel, cudaFuncAttributeMaxDynamicSharedMemorySize,
                         GEMM_SMEM);

    init_cas_kernel<<<(C_DIM * C_DIM + 255) / 256, 256>>>(casC, C_DIM);
    init_casw_pad_kernel<<<(WPAD * WPAD + 255) / 256, 256>>>();
    convert_x_kernel<<<(NELEM / 4 + 255) / 256, 256>>>(x);
    {
        int nprep = NB * 128 * 64 + NB * 64 * 64;
        prep_mlp_weights<<<(nprep + 255) / 256, 256>>>(w1, w2);
    }

    const long long sPadH = (long long)C_DIM * WPAD;
    const long long sCmpH = (long long)W_DIM * C_DIM;
    const int nPad = H_DIM * C_DIM * 12;

    zeropad_kernel<<<(nPad + 255) / 256, 256>>>(bufA);

    // GEMM1: T1t = (X @ casC) -> transposed-padded bf16 bufA
    bf16gemm_kernel<<<dim3(C_DIM / 128, (P_TOT + 127) / 128, 1), 128, GEMM_SMEM>>>(
        P_TOT, C_DIM, P_TOT,
        xbf, C_DIM, 0,
        casC, C_DIM, 0,
        bufA, 0, 0,
        1.0f, nullptr, 0, 1);

    // GEMM2: XH[h] = casW @ T1[h] -> compact bf16 bufB
    bf16gemm_kernel<<<dim3(C_DIM / 128, 3, H_DIM), 128, GEMM_SMEM>>>(
        W_DIM, WPAD, WPAD,
        casW, WPAD, 0,
        bufA, WPAD, sPadH,
        bufB, C_DIM, sCmpH,
        1.0f, nullptr, 0, 2);

    // bf16 tensor-core block MLP + softshrink: bufB -> bufA (compact)
    mlp_tc_kernel<<<dim3((P_TOT + 127) / 128, NB), 256, MLP_TC_SMEM>>>(
        bufB, b1, b2, bufA);

    zeropad_kernel<<<(nPad + 255) / 256, 256>>>(bufB);

    // GEMM3: T2t = (Y @ casC) -> transposed-padded bf16 bufB
    bf16gemm_kernel<<<dim3(C_DIM / 128, (P_TOT + 127) / 128, 1), 128, GEMM_SMEM>>>(
        P_TOT, C_DIM, P_TOT,
        bufA, C_DIM, 0,
        casC, C_DIM, 0,
        bufB, 0, 0,
        1.0f, nullptr, 0, 1);

    // GEMM4: out[h] = casW @ T2[h] / (W*C) + x[h]  (fp32 out, exact fp32 bias)
    bf16gemm_kernel<<<dim3(C_DIM / 128, 3, H_DIM), 128, GEMM_SMEM>>>(
        W_DIM, WPAD, WPAD,
        casW, WPAD, 0,
        bufB, WPAD, sPadH,
        out, C_DIM, sCmpH,
        1.0f / (float)(W_DIM * C_DIM), x, sCmpH, 0);
}

// round 13
// speedup vs baseline: 5.6248x; 1.0878x over previous
#include <cuda_runtime.h>
#include <cuda_bf16.h>
#include <cstdint>

// Problem constants
#define H_DIM 180
#define W_DIM 360
#define WPAD  384
#define C_DIM 512
#define P_TOT (H_DIM * W_DIM)           // 64800
#define NELEM (P_TOT * C_DIM)
#define PADELEM (H_DIM * C_DIM * WPAD)
#define NB 8
#define BS 64
#define SPARSITY 0.01f

typedef __nv_bfloat16 bf16;

// ---------------------------------------------------------------------------
// Scratch (bf16 activations)
// ---------------------------------------------------------------------------
__device__ bf16 g_bufA[PADELEM];
__device__ bf16 g_bufB[PADELEM];
__device__ bf16 g_xbf[NELEM];
__device__ bf16 g_casC[C_DIM * C_DIM];
__device__ bf16 g_casW[WPAD * WPAD];
__device__ uint32_t g_w1cat[NB * 128 * 64];   // [blk][o][ipair] bf16x2
__device__ uint32_t g_w2cat[NB * 64 * 64];    // [blk][o][ipair] bf16x2

// ---------------------------------------------------------------------------
// bf16 helpers (plain mma.sync m16n8k16 — compiles for base sm_103)
// ---------------------------------------------------------------------------
__device__ __forceinline__ uint32_t packbf(float lo, float hi) {
    uint32_t r;
    asm("cvt.rn.bf16x2.f32 %0, %1, %2;" : "=r"(r) : "f"(hi), "f"(lo));
    return r;
}

__device__ __forceinline__ void mma_bf16(float* d, const uint32_t* a, const uint32_t* b) {
    asm volatile(
        "mma.sync.aligned.m16n8k16.row.col.f32.bf16.bf16.f32 "
        "{%0,%1,%2,%3}, {%4,%5,%6,%7}, {%8,%9}, {%0,%1,%2,%3};"
        : "+f"(d[0]), "+f"(d[1]), "+f"(d[2]), "+f"(d[3])
        : "r"(a[0]), "r"(a[1]), "r"(a[2]), "r"(a[3]), "r"(b[0]), "r"(b[1]));
}

#define CP_ASYNC16(dst, src) \
    asm volatile("cp.async.cg.shared.global [%0], [%1], 16;" \
                 :: "r"(dst), "l"(src) : "memory")
#define CP_COMMIT()  asm volatile("cp.async.commit_group;" ::: "memory")
#define CP_WAIT(n)   asm volatile("cp.async.wait_group %0;" :: "n"(n) : "memory")

// ---------------------------------------------------------------------------
// Init kernels
// ---------------------------------------------------------------------------
__global__ void init_cas_kernel(bf16* __restrict__ out, int n) {
    int i = blockIdx.x * blockDim.x + threadIdx.x;
    if (i >= n * n) return;
    int t = i / n, d = i % n;
    long long m = (2LL * t * d) % (2LL * n);
    float a = (float)m / (float)n;
    float s, c;
    sincospif(a, &s, &c);
    out[i] = __float2bfloat16_rn(c + s);
}

__global__ void init_casw_pad_kernel() {
    int i = blockIdx.x * blockDim.x + threadIdx.x;
    if (i >= WPAD * WPAD) return;
    int t = i / WPAD, d = i % WPAD;
    float v = 0.f;
    if (t < W_DIM && d < W_DIM) {
        long long m = (2LL * t * d) % (2LL * W_DIM);
        float a = (float)m / (float)W_DIM;
        float s, c;
        sincospif(a, &s, &c);
        v = c + s;
    }
    g_casW[i] = __float2bfloat16_rn(v);
}

__global__ void convert_x_kernel(const float* __restrict__ x) {
    int i = blockIdx.x * blockDim.x + threadIdx.x;   // processes 4 elems
    if (i >= NELEM / 4) return;
    float4 v = *(const float4*)(x + i * 4);
    uint2 u;
    u.x = packbf(v.x, v.y);
    u.y = packbf(v.z, v.w);
    *(uint2*)((char*)g_xbf + i * 8) = u;
}

// Packed bf16-pair MLP weights, pre-transposed (see R7 derivation).
__global__ void prep_mlp_weights(const float* __restrict__ w1,
                                 const float* __restrict__ w2) {
    const int NW1 = NB * 128 * 64;
    const int NW2 = NB * 64 * 64;
    int idx = blockIdx.x * blockDim.x + threadIdx.x;
    if (idx < NW1) {
        int blk = idx >> 13;
        int rem = idx & 8191;
        int o = rem >> 6, j = rem & 63;
        const float* w1p = w1 + blk * 4096;
        const float* w1q = w1 + (NB + blk) * 4096;
        float v[2];
#pragma unroll
        for (int q = 0; q < 2; q++) {
            int i = 2 * j + q;
            if (o < 64) {
                if (i < 64) v[q] = w1p[i * 64 + o] + w1q[i * 64 + o];
                else        v[q] = w1p[(i - 64) * 64 + o] - w1q[(i - 64) * 64 + o];
            } else {
                int oo = o - 64;
                if (i < 64) v[q] = w1p[i * 64 + oo] - w1q[i * 64 + oo];
                else        v[q] = w1p[(i - 64) * 64 + oo] + w1q[(i - 64) * 64 + oo];
            }
        }
        g_w1cat[idx] = packbf(v[0], v[1]);
    } else if (idx < NW1 + NW2) {
        int jx = idx - NW1;
        int blk = jx >> 12;
        int rem = jx & 4095;
        int o = rem >> 6, j = rem & 63;
        const float* w2p = w2 + blk * 4096;
        const float* w2q = w2 + (NB + blk) * 4096;
        float v[2];
#pragma unroll
        for (int q = 0; q < 2; q++) {
            int i = 2 * j + q;
            if (i < 64) v[q] = w2p[i * 64 + o] + w2q[i * 64 + o];
            else        v[q] = w2p[(i - 64) * 64 + o] - w2q[(i - 64) * 64 + o];
        }
        g_w2cat[jx] = packbf(v[0], v[1]);
    }
}

// zero pad w in [360,384) of a [h][c][wpad] bf16 buffer (12 uint32 per row)
__global__ void zeropad_kernel(bf16* __restrict__ buf) {
    int i = blockIdx.x * blockDim.x + threadIdx.x;
    if (i >= H_DIM * C_DIM * 12) return;
    int hc = i / 12;
    int r = i - hc * 12;
    ((uint32_t*)buf)[(size_t)hc * (WPAD / 2) + 180 + r] = 0u;
}

// ---------------------------------------------------------------------------
// bf16 warp-MMA GEMM, 2-stage cp.async, m16n8k16.
// BM=BN=128, BK=64 (halved sync/commit tax vs BK=32), 4 warps (2x2),
// warp tile 64x64. Row stride 36 uint32 (64 bf16 + pad): addresses
// r*36+kp ≡ r*4+kp (mod 32) -> conflict-free fragment loads.
// ---------------------------------------------------------------------------
#define STR 36
#define TS2 (128 * STR)
#define GEMM_SMEM (2 * 2 * TS2 * 4)       // 73,728 bytes

__global__ void __launch_bounds__(128) bf16gemm_kernel(
    int M, int K, int aM,
    const bf16* __restrict__ A, int lda, long long sA,
    const bf16* __restrict__ Bt, int ldb, long long sB,
    void* __restrict__ Cv, int ldc, long long sC,
    float alpha, const float* __restrict__ Add, long long sAdd,
    int epi_mode)
{
    extern __shared__ uint32_t smd[];
    const uint32_t sbase = (uint32_t)__cvta_generic_to_shared(smd);

    const int tid  = threadIdx.x;
    const int lane = tid & 31;
    const int wid  = tid >> 5;
    const int wm   = wid & 1;
    const int wn   = wid >> 1;
    const int bm   = blockIdx.y * 128;
    const int bn   = blockIdx.x * 128;
    const int bz   = blockIdx.z;

    A  += (size_t)bz * sA;
    Bt += (size_t)bz * sB;

    float acc[4][8][4];
#pragma unroll
    for (int mi = 0; mi < 4; mi++)
#pragma unroll
        for (int ni = 0; ni < 8; ni++)
#pragma unroll
            for (int q = 0; q < 4; q++) acc[mi][ni][q] = 0.f;

    const int r_ld = tid >> 3;            // 0..15
    const int kch  = (tid & 7) << 3;      // bf16 offset within 64: 0,8,...,56

#define LOADTILE(k0, s)                                                        \
    do {                                                                       \
        _Pragma("unroll")                                                      \
        for (int c = 0; c < 8; c++) {                                          \
            int r = r_ld + c * 16;                                             \
            int ra = bm + r;                                                   \
            if (ra >= aM) ra = aM - 1;                                         \
            uint32_t da = sbase + (((s) * 2 * TS2) + r * STR + (kch >> 1)) * 4; \
            CP_ASYNC16(da, A + (size_t)ra * lda + (k0) + kch);                 \
            uint32_t db = sbase + (((s) * 2 * TS2 + TS2) + r * STR + (kch >> 1)) * 4; \
            CP_ASYNC16(db, Bt + (size_t)(bn + r) * ldb + (k0) + kch);          \
        }                                                                      \
        CP_COMMIT();                                                           \
    } while (0)

    const int nT = K >> 6;
    LOADTILE(0, 0);

    for (int t = 0; t < nT; t++) {
        const int s = t & 1;
        if (t + 1 < nT) {
            LOADTILE((t + 1) << 6, (t + 1) & 1);
            CP_WAIT(1);
        } else {
            CP_WAIT(0);
        }
        __syncthreads();

        const uint32_t* As = smd + s * 2 * TS2;
        const uint32_t* Bs = As + TS2;

#pragma unroll
        for (int kk = 0; kk < 4; kk++) {             // four k16 steps per BK=64
            uint32_t af[4][4], bf[8][2];
            const int kp = kk * 8 + (lane & 3);
#pragma unroll
            for (int mi = 0; mi < 4; mi++) {
                int r0 = wm * 64 + mi * 16 + (lane >> 2);
                af[mi][0] = As[r0 * STR + kp];
                af[mi][1] = As[(r0 + 8) * STR + kp];
                af[mi][2] = As[r0 * STR + kp + 4];
                af[mi][3] = As[(r0 + 8) * STR + kp + 4];
            }
#pragma unroll
            for (int ni = 0; ni < 8; ni++) {
                int n0 = wn * 64 + ni * 8 + (lane >> 2);
                bf[ni][0] = Bs[n0 * STR + kp];
                bf[ni][1] = Bs[n0 * STR + kp + 4];
            }
#pragma unroll
            for (int mi = 0; mi < 4; mi++)
#pragma unroll
                for (int ni = 0; ni < 8; ni++)
                    mma_bf16(acc[mi][ni], af[mi], bf[ni]);
        }
        __syncthreads();
    }
#undef LOADTILE

    const float* addb = Add ? (Add + (size_t)bz * sAdd) : (const float*)0;
#pragma unroll
    for (int mi = 0; mi < 4; mi++) {
#pragma unroll
        for (int half = 0; half < 2; half++) {
            int r = wm * 64 + mi * 16 + (lane >> 2) + half * 8;
            int p = bm + r;
            if (p >= M) continue;
            if (epi_mode == 0) {
                float* cp = (float*)Cv + (size_t)bz * sC + (size_t)p * ldc + bn;
                const float* ap = addb ? (addb + (size_t)p * ldc + bn) : (const float*)0;
#pragma unroll
                for (int ni = 0; ni < 8; ni++) {
                    int c0 = wn * 64 + ni * 8 + (lane & 3) * 2;
                    float2 v;
                    v.x = acc[mi][ni][half * 2 + 0] * alpha;
                    v.y = acc[mi][ni][half * 2 + 1] * alpha;
                    if (ap) {
                        float2 a2 = *(const float2*)(ap + c0);
                        v.x += a2.x; v.y += a2.y;
                    }
                    *(float2*)(cp + c0) = v;
                }
            } else if (epi_mode == 2) {
                bf16* cp = (bf16*)Cv + (size_t)bz * sC + (size_t)p * ldc + bn;
#pragma unroll
                for (int ni = 0; ni < 8; ni++) {
                    int c0 = wn * 64 + ni * 8 + (lane & 3) * 2;
                    *(uint32_t*)(cp + c0) =
                        packbf(acc[mi][ni][half * 2 + 0], acc[mi][ni][half * 2 + 1]);
                }
            } else {
                int h = p / W_DIM, w = p - h * W_DIM;
                bf16* cp = (bf16*)Cv + (size_t)h * (C_DIM * WPAD) + w;
#pragma unroll
                for (int ni = 0; ni < 8; ni++) {
                    int c0 = bn + wn * 64 + ni * 8 + (lane & 3) * 2;
                    cp[(size_t)c0 * WPAD]       = __float2bfloat16_rn(acc[mi][ni][half * 2 + 0]);
                    cp[(size_t)(c0 + 1) * WPAD] = __float2bfloat16_rn(acc[mi][ni][half * 2 + 1]);
                }
            }
        }
    }
}

// ---------------------------------------------------------------------------
// bf16 tensor-core block-MLP + softshrink (proven in R11). 256 threads.
// ---------------------------------------------------------------------------
#define MS2 68
#define O2S2 36
#define MLP_TC_SMEM ((128 * MS2 + 128 * MS2 + 64 * MS2 + 128 * O2S2 + 256) * 4)

__global__ void __launch_bounds__(256) mlp_tc_kernel(
    const bf16* __restrict__ xh,
    const float* __restrict__ b1,
    const float* __restrict__ b2,
    bf16* __restrict__ y)
{
    extern __shared__ uint32_t sm[];
    uint32_t* sA  = sm;
    uint32_t* sW1 = sA + 128 * MS2;
    uint32_t* sW2 = sW1 + 128 * MS2;
    uint32_t* sO2 = sW2 + 64 * MS2;
    int* s_p  = (int*)(sO2 + 128 * O2S2);
    int* s_pn = s_p + 128;

    const int tid  = threadIdx.x;
    const int lane = tid & 31;
    const int wid  = tid >> 5;
    const int wm   = wid & 1;
    const int wn   = wid >> 1;
    const int k    = blockIdx.y;
    const int p0   = blockIdx.x * 128;

    if (tid < 128) {
        int p = p0 + tid;
        if (p >= P_TOT) p = P_TOT - 1;
        int h = p / W_DIM, w = p - h * W_DIM;
        s_p[tid]  = p;
        s_pn[tid] = ((H_DIM - h) % H_DIM) * W_DIM + ((W_DIM - w) % W_DIM);
    }
    {
        const uint4* w1g = (const uint4*)(g_w1cat + k * 8192);
#pragma unroll
        for (int it = tid; it < 2048; it += 256) {
            int r = it >> 4, c4 = (it & 15) << 2;
            *(uint4*)&sW1[r * MS2 + c4] = w1g[it];
        }
        const uint4* w2g = (const uint4*)(g_w2cat + k * 4096);
#pragma unroll
        for (int it = tid; it < 1024; it += 256) {
            int r = it >> 4, c4 = (it & 15) << 2;
            *(uint4*)&sW2[r * MS2 + c4] = w2g[it];
        }
    }
    __syncthreads();

    // A1 = [xh | xn] tile, bf16 pairs (all 128 cols)
#pragma unroll
    for (int it = tid; it < 4096; it += 256) {
        int r = it >> 5;
        int c = (it & 31) * 4;
        const bf16* src = (c < 64)
            ? xh + (size_t)s_p[r] * C_DIM + k * BS + c
            : xh + (size_t)s_pn[r] * C_DIM + k * BS + (c - 64);
        *(uint2*)&sA[r * MS2 + (c >> 1)] = *(const uint2*)src;
    }
    __syncthreads();

    // ---- Layer 1 ----
    float acc1[4][4][4];
#pragma unroll
    for (int mi = 0; mi < 4; mi++)
#pragma unroll
        for (int ni = 0; ni < 4; ni++)
#pragma unroll
            for (int q = 0; q < 4; q++) acc1[mi][ni][q] = 0.f;

#pragma unroll
    for (int kk = 0; kk < 8; kk++) {
        uint32_t af[4][4], bf[4][2];
        const int kp = kk * 8 + (lane & 3);
#pragma unroll
        for (int mi = 0; mi < 4; mi++) {
            int r0 = wm * 64 + mi * 16 + (lane >> 2);
            af[mi][0] = sA[r0 * MS2 + kp];
            af[mi][1] = sA[(r0 + 8) * MS2 + kp];
            af[mi][2] = sA[r0 * MS2 + kp + 4];
            af[mi][3] = sA[(r0 + 8) * MS2 + kp + 4];
        }
#pragma unroll
        for (int ni = 0; ni < 4; ni++) {
            int n0 = wn * 32 + ni * 8 + (lane >> 2);
            bf[ni][0] = sW1[n0 * MS2 + kp];
            bf[ni][1] = sW1[n0 * MS2 + kp + 4];
        }
#pragma unroll
        for (int mi = 0; mi < 4; mi++)
#pragma unroll
            for (int ni = 0; ni < 4; ni++)
                mma_bf16(acc1[mi][ni], af[mi], bf[ni]);
    }
    __syncthreads();

    // bias + relu -> sA
#pragma unroll
    for (int mi = 0; mi < 4; mi++)
#pragma unroll
        for (int half = 0; half < 2; half++) {
            int r = wm * 64 + mi * 16 + (lane >> 2) + half * 8;
#pragma unroll
            for (int ni = 0; ni < 4; ni++) {
                int c = wn * 32 + ni * 8 + (lane & 3) * 2;
                float bx = (c < 64) ? b1[k * BS + c] : b1[NB * BS + k * BS + (c - 64)];
                float by = (c + 1 < 64) ? b1[k * BS + c + 1] : b1[NB * BS + k * BS + (c + 1 - 64)];
                float vx = fmaxf(0.5f * acc1[mi][ni][half * 2 + 0] + bx, 0.f);
                float vy = fmaxf(0.5f * acc1[mi][ni][half * 2 + 1] + by, 0.f);
                sA[r * MS2 + (c >> 1)] = packbf(vx, vy);
            }
        }
    __syncthreads();

    // ---- Layer 2a: o2k ----
    float acc2[4][2][4];
#pragma unroll
    for (int mi = 0; mi < 4; mi++)
#pragma unroll
        for (int ni = 0; ni < 2; ni++)
#pragma unroll
            for (int q = 0; q < 4; q++) acc2[mi][ni][q] = 0.f;

#pragma unroll
    for (int kk = 0; kk < 8; kk++) {
        uint32_t af[4][4], bf[2][2];
        const int kp = kk * 8 + (lane & 3);
#pragma unroll
        for (int mi = 0; mi < 4; mi++) {
            int r0 = wm * 64 + mi * 16 + (lane >> 2);
            af[mi][0] = sA[r0 * MS2 + kp];
            af[mi][1] = sA[(r0 + 8) * MS2 + kp];
            af[mi][2] = sA[r0 * MS2 + kp + 4];
            af[mi][3] = sA[(r0 + 8) * MS2 + kp + 4];
        }
#pragma unroll
        for (int ni = 0; ni < 2; ni++) {
            int n0 = wn * 16 + ni * 8 + (lane >> 2);
            bf[ni][0] = sW2[n0 * MS2 + kp];
            bf[ni][1] = sW2[n0 * MS2 + kp + 4];
        }
#pragma unroll
        for (int mi = 0; mi < 4; mi++)
#pragma unroll
            for (int ni = 0; ni < 2; ni++)
                mma_bf16(acc2[mi][ni], af[mi], bf[ni]);
    }

    float v2k[4][2][4];
#pragma unroll
    for (int mi = 0; mi < 4; mi++)
#pragma unroll
        for (int half = 0; half < 2; half++) {
            int r = wm * 64 + mi * 16 + (lane >> 2) + half * 8;
#pragma unroll
            for (int ni = 0; ni < 2; ni++) {
                int c = wn * 16 + ni * 8 + (lane & 3) * 2;
                float vx = 0.5f * acc2[mi][ni][half * 2 + 0] + b2[k * BS + c];
                float vy = 0.5f * acc2[mi][ni][half * 2 + 1] + b2[k * BS + c + 1];
                v2k[mi][ni][half * 2 + 0] = vx;
                v2k[mi][ni][half * 2 + 1] = vy;
                sO2[r * O2S2 + (c >> 1)] = packbf(vx, vy);
            }
        }
    __syncthreads();

    // ---- Layer 2b: o2n ----
    float accn[4][2][4];
#pragma unroll
    for (int mi = 0; mi < 4; mi++)
#pragma unroll
        for (int ni = 0; ni < 2; ni++)
#pragma unroll
            for (int q = 0; q < 4; q++) accn[mi][ni][q] = 0.f;

#pragma unroll
    for (int kk = 0; kk < 4; kk++) {
        uint32_t af[4][4], bf[2][2];
        const int kp = kk * 8 + (lane & 3);
#pragma unroll
        for (int mi = 0; mi < 4; mi++) {
            int r0 = wm * 64 + mi * 16 + (lane >> 2);
            af[mi][0] = sA[r0 * MS2 + 32 + kp];
            af[mi][1] = sA[(r0 + 8) * MS2 + 32 + kp];
            af[mi][2] = sA[r0 * MS2 + 32 + kp + 4];
            af[mi][3] = sA[(r0 + 8) * MS2 + 32 + kp + 4];
        }
#pragma unroll
        for (int ni = 0; ni < 2; ni++) {
            int n0 = wn * 16 + ni * 8 + (lane >> 2);
            bf[ni][0] = sW2[n0 * MS2 + kp];
            bf[ni][1] = sW2[n0 * MS2 + kp + 4];
        }
#pragma unroll
        for (int mi = 0; mi < 4; mi++)
#pragma unroll
            for (int ni = 0; ni < 2; ni++)
                mma_bf16(accn[mi][ni], af[mi], bf[ni]);
    }
#pragma unroll
    for (int kk = 0; kk < 4; kk++) {
        uint32_t af[4][4], bf[2][2];
        const int kp = kk * 8 + (lane & 3);
#pragma unroll
        for (int mi = 0; mi < 4; mi++) {
            int r0 = wm * 64 + mi * 16 + (lane >> 2);
            af[mi][0] = sO2[r0 * O2S2 + kp];
            af[mi][1] = sO2[(r0 + 8) * O2S2 + kp];
            af[mi][2] = sO2[r0 * O2S2 + kp + 4];
            af[mi][3] = sO2[(r0 + 8) * O2S2 + kp + 4];
        }
#pragma unroll
        for (int ni = 0; ni < 2; ni++) {
            int n0 = wn * 16 + ni * 8 + (lane >> 2);
            bf[ni][0] = sW2[n0 * MS2 + 32 + kp];
            bf[ni][1] = sW2[n0 * MS2 + 32 + kp + 4];
        }
#pragma unroll
        for (int mi = 0; mi < 4; mi++)
#pragma unroll
            for (int ni = 0; ni < 2; ni++)
                mma_bf16(accn[mi][ni], af[mi], bf[ni]);
    }

    // y = softshrink(o2k + o2n)
#pragma unroll
    for (int mi = 0; mi < 4; mi++)
#pragma unroll
        for (int half = 0; half < 2; half++) {
            int r = wm * 64 + mi * 16 + (lane >> 2) + half * 8;
            int p = p0 + r;
            if (p < P_TOT) {
#pragma unroll
                for (int ni = 0; ni < 2; ni++) {
                    int c = wn * 16 + ni * 8 + (lane & 3) * 2;
                    float vx = v2k[mi][ni][half * 2 + 0]
                             + 0.5f * accn[mi][ni][half * 2 + 0] + b2[NB * BS + k * BS + c];
                    float vy = v2k[mi][ni][half * 2 + 1]
                             + 0.5f * accn[mi][ni][half * 2 + 1] + b2[NB * BS + k * BS + c + 1];
                    float ax = fabsf(vx) - SPARSITY;
                    float ay = fabsf(vy) - SPARSITY;
                    float rx = ax > 0.f ? copysignf(ax, vx) : 0.f;
                    float ry = ay > 0.f ? copysignf(ay, vy) : 0.f;
                    *(uint32_t*)(y + (size_t)p * C_DIM + k * BS + c) = packbf(rx, ry);
                }
            }
        }
}

// ---------------------------------------------------------------------------
// kernel_launch
// ---------------------------------------------------------------------------
extern "C" void kernel_launch(void* const* d_in, const int* in_sizes, int n_in,
                              void* d_out, int out_size) {
    const float* x  = (const float*)d_in[0];
    const float* w1 = (const float*)d_in[1];
    const float* b1 = (const float*)d_in[2];
    const float* w2 = (const float*)d_in[3];
    const float* b2 = (const float*)d_in[4];
    float* out = (float*)d_out;

    bf16 *bufA, *bufB, *casC, *casW, *xbf;
    cudaGetSymbolAddress((void**)&bufA, g_bufA);
    cudaGetSymbolAddress((void**)&bufB, g_bufB);
    cudaGetSymbolAddress((void**)&casC, g_casC);
    cudaGetSymbolAddress((void**)&casW, g_casW);
    cudaGetSymbolAddress((void**)&xbf,  g_xbf);

    cudaFuncSetAttribute(mlp_tc_kernel, cudaFuncAttributeMaxDynamicSharedMemorySize,
                         MLP_TC_SMEM);
    cudaFuncSetAttribute(bf16gemm_kernel, cudaFuncAttributeMaxDynamicSharedMemorySize,
                         GEMM_SMEM);

    init_cas_kernel<<<(C_DIM * C_DIM + 255) / 256, 256>>>(casC, C_DIM);
    init_casw_pad_kernel<<<(WPAD * WPAD + 255) / 256, 256>>>();
    convert_x_kernel<<<(NELEM / 4 + 255) / 256, 256>>>(x);
    {
        int nprep = NB * 128 * 64 + NB * 64 * 64;
        prep_mlp_weights<<<(nprep + 255) / 256, 256>>>(w1, w2);
    }

    const long long sPadH = (long long)C_DIM * WPAD;
    const long long sCmpH = (long long)W_DIM * C_DIM;
    const int nPad = H_DIM * C_DIM * 12;

    zeropad_kernel<<<(nPad + 255) / 256, 256>>>(bufA);

    // GEMM1: T1t = (X @ casC) -> transposed-padded bf16 bufA
    bf16gemm_kernel<<<dim3(C_DIM / 128, (P_TOT + 127) / 128, 1), 128, GEMM_SMEM>>>(
        P_TOT, C_DIM, P_TOT,
        xbf, C_DIM, 0,
        casC, C_DIM, 0,
        bufA, 0, 0,
        1.0f, nullptr, 0, 1);

    // GEMM2: XH[h] = casW @ T1[h] -> compact bf16 bufB
    bf16gemm_kernel<<<dim3(C_DIM / 128, 3, H_DIM), 128, GEMM_SMEM>>>(
        W_DIM, WPAD, WPAD,
        casW, WPAD, 0,
        bufA, WPAD, sPadH,
        bufB, C_DIM, sCmpH,
        1.0f, nullptr, 0, 2);

    // bf16 tensor-core block MLP + softshrink: bufB -> bufA (compact)
    mlp_tc_kernel<<<dim3((P_TOT + 127) / 128, NB), 256, MLP_TC_SMEM>>>(
        bufB, b1, b2, bufA);

    zeropad_kernel<<<(nPad + 255) / 256, 256>>>(bufB);

    // GEMM3: T2t = (Y @ casC) -> transposed-padded bf16 bufB
    bf16gemm_kernel<<<dim3(C_DIM / 128, (P_TOT + 127) / 128, 1), 128, GEMM_SMEM>>>(
        P_TOT, C_DIM, P_TOT,
        bufA, C_DIM, 0,
        casC, C_DIM, 0,
        bufB, 0, 0,
        1.0f, nullptr, 0, 1);

    // GEMM4: out[h] = casW @ T2[h] / (W*C) + x[h]  (fp32 out, exact fp32 bias)
    bf16gemm_kernel<<<dim3(C_DIM / 128, 3, H_DIM), 128, GEMM_SMEM>>>(
        W_DIM, WPAD, WPAD,
        casW, WPAD, 0,
        bufB, WPAD, sPadH,
        out, C_DIM, sCmpH,
        1.0f / (float)(W_DIM * C_DIM), x, sCmpH, 0);
}

// round 14
// speedup vs baseline: 5.6975x; 1.0129x over previous
#include <cuda_runtime.h>
#include <cuda_bf16.h>
#include <cstdint>

// Problem constants
#define H_DIM 180
#define W_DIM 360
#define WPAD  384
#define C_DIM 512
#define P_TOT (H_DIM * W_DIM)           // 64800
#define NELEM (P_TOT * C_DIM)
#define PADELEM (H_DIM * C_DIM * WPAD)
#define NB 8
#define BS 64
#define SPARSITY 0.01f

typedef __nv_bfloat16 bf16;

// ---------------------------------------------------------------------------
// Scratch (bf16 activations)
// ---------------------------------------------------------------------------
__device__ bf16 g_bufA[PADELEM];
__device__ bf16 g_bufB[PADELEM];
__device__ bf16 g_xbf[NELEM];
__device__ bf16 g_casC[C_DIM * C_DIM];
__device__ bf16 g_casW[WPAD * WPAD];
__device__ uint32_t g_w1cat[NB * 128 * 64];   // [blk][o][ipair] bf16x2
__device__ uint32_t g_w2cat[NB * 64 * 64];    // [blk][o][ipair] bf16x2

// ---------------------------------------------------------------------------
// bf16 helpers (plain mma.sync m16n8k16 — compiles for base sm_103)
// ---------------------------------------------------------------------------
__device__ __forceinline__ uint32_t packbf(float lo, float hi) {
    uint32_t r;
    asm("cvt.rn.bf16x2.f32 %0, %1, %2;" : "=r"(r) : "f"(hi), "f"(lo));
    return r;
}

__device__ __forceinline__ void mma_bf16(float* d, const uint32_t* a, const uint32_t* b) {
    asm volatile(
        "mma.sync.aligned.m16n8k16.row.col.f32.bf16.bf16.f32 "
        "{%0,%1,%2,%3}, {%4,%5,%6,%7}, {%8,%9}, {%0,%1,%2,%3};"
        : "+f"(d[0]), "+f"(d[1]), "+f"(d[2]), "+f"(d[3])
        : "r"(a[0]), "r"(a[1]), "r"(a[2]), "r"(a[3]), "r"(b[0]), "r"(b[1]));
}

#define CP_ASYNC16(dst, src) \
    asm volatile("cp.async.cg.shared.global [%0], [%1], 16;" \
                 :: "r"(dst), "l"(src) : "memory")
#define CP_COMMIT()  asm volatile("cp.async.commit_group;" ::: "memory")
#define CP_WAIT(n)   asm volatile("cp.async.wait_group %0;" :: "n"(n) : "memory")

// ---------------------------------------------------------------------------
// Init kernels
// ---------------------------------------------------------------------------
__global__ void init_cas_kernel(bf16* __restrict__ out, int n) {
    int i = blockIdx.x * blockDim.x + threadIdx.x;
    if (i >= n * n) return;
    int t = i / n, d = i % n;
    long long m = (2LL * t * d) % (2LL * n);
    float a = (float)m / (float)n;
    float s, c;
    sincospif(a, &s, &c);
    out[i] = __float2bfloat16_rn(c + s);
}

__global__ void init_casw_pad_kernel() {
    int i = blockIdx.x * blockDim.x + threadIdx.x;
    if (i >= WPAD * WPAD) return;
    int t = i / WPAD, d = i % WPAD;
    float v = 0.f;
    if (t < W_DIM && d < W_DIM) {
        long long m = (2LL * t * d) % (2LL * W_DIM);
        float a = (float)m / (float)W_DIM;
        float s, c;
        sincospif(a, &s, &c);
        v = c + s;
    }
    g_casW[i] = __float2bfloat16_rn(v);
}

__global__ void convert_x_kernel(const float* __restrict__ x) {
    int i = blockIdx.x * blockDim.x + threadIdx.x;   // processes 4 elems
    if (i >= NELEM / 4) return;
    float4 v = *(const float4*)(x + i * 4);
    uint2 u;
    u.x = packbf(v.x, v.y);
    u.y = packbf(v.z, v.w);
    *(uint2*)((char*)g_xbf + i * 8) = u;
}

// Packed bf16-pair MLP weights, pre-transposed (see R7 derivation).
__global__ void prep_mlp_weights(const float* __restrict__ w1,
                                 const float* __restrict__ w2) {
    const int NW1 = NB * 128 * 64;
    const int NW2 = NB * 64 * 64;
    int idx = blockIdx.x * blockDim.x + threadIdx.x;
    if (idx < NW1) {
        int blk = idx >> 13;
        int rem = idx & 8191;
        int o = rem >> 6, j = rem & 63;
        const float* w1p = w1 + blk * 4096;
        const float* w1q = w1 + (NB + blk) * 4096;
        float v[2];
#pragma unroll
        for (int q = 0; q < 2; q++) {
            int i = 2 * j + q;
            if (o < 64) {
                if (i < 64) v[q] = w1p[i * 64 + o] + w1q[i * 64 + o];
                else        v[q] = w1p[(i - 64) * 64 + o] - w1q[(i - 64) * 64 + o];
            } else {
                int oo = o - 64;
                if (i < 64) v[q] = w1p[i * 64 + oo] - w1q[i * 64 + oo];
                else        v[q] = w1p[(i - 64) * 64 + oo] + w1q[(i - 64) * 64 + oo];
            }
        }
        g_w1cat[idx] = packbf(v[0], v[1]);
    } else if (idx < NW1 + NW2) {
        int jx = idx - NW1;
        int blk = jx >> 12;
        int rem = jx & 4095;
        int o = rem >> 6, j = rem & 63;
        const float* w2p = w2 + blk * 4096;
        const float* w2q = w2 + (NB + blk) * 4096;
        float v[2];
#pragma unroll
        for (int q = 0; q < 2; q++) {
            int i = 2 * j + q;
            if (i < 64) v[q] = w2p[i * 64 + o] + w2q[i * 64 + o];
            else        v[q] = w2p[(i - 64) * 64 + o] - w2q[(i - 64) * 64 + o];
        }
        g_w2cat[jx] = packbf(v[0], v[1]);
    }
}

// zero pad w in [360,384) of a [h][c][wpad] bf16 buffer (12 uint32 per row)
__global__ void zeropad_kernel(bf16* __restrict__ buf) {
    int i = blockIdx.x * blockDim.x + threadIdx.x;
    if (i >= H_DIM * C_DIM * 12) return;
    int hc = i / 12;
    int r = i - hc * 12;
    ((uint32_t*)buf)[(size_t)hc * (WPAD / 2) + 180 + r] = 0u;
}

// ---------------------------------------------------------------------------
// bf16 warp-MMA GEMM, 2-stage cp.async, m16n8k16.
// BM=BN=128, BK=64, 4 warps (2x2), warp tile 64x64, stride-36 smem.
//   epi_mode 0: fp32 compact store (*alpha, +Add fp32), guard row<M
//   epi_mode 1: smem-transposed store into [h=bz][c][wpad]; tile is
//               single-h (batched over z); stores guarded w<W_DIM, coalesced.
//   epi_mode 2: bf16 compact [p][c]
// ---------------------------------------------------------------------------
#define STR 36
#define TS2 (128 * STR)
#define GEMM_SMEM (2 * 2 * TS2 * 4)       // 73,728 bytes
#define TSTR 136                           // transposed-tile row stride (bf16)

__global__ void __launch_bounds__(128) bf16gemm_kernel(
    int M, int K, int aM,
    const bf16* __restrict__ A, int lda, long long sA,
    const bf16* __restrict__ Bt, int ldb, long long sB,
    void* __restrict__ Cv, int ldc, long long sC,
    float alpha, const float* __restrict__ Add, long long sAdd,
    int epi_mode)
{
    extern __shared__ uint32_t smd[];
    const uint32_t sbase = (uint32_t)__cvta_generic_to_shared(smd);

    const int tid  = threadIdx.x;
    const int lane = tid & 31;
    const int wid  = tid >> 5;
    const int wm   = wid & 1;
    const int wn   = wid >> 1;
    const int bm   = blockIdx.y * 128;
    const int bn   = blockIdx.x * 128;
    const int bz   = blockIdx.z;

    A  += (size_t)bz * sA;
    Bt += (size_t)bz * sB;

    float acc[4][8][4];
#pragma unroll
    for (int mi = 0; mi < 4; mi++)
#pragma unroll
        for (int ni = 0; ni < 8; ni++)
#pragma unroll
            for (int q = 0; q < 4; q++) acc[mi][ni][q] = 0.f;

    const int r_ld = tid >> 3;            // 0..15
    const int kch  = (tid & 7) << 3;      // bf16 offset within 64: 0,8,...,56

#define LOADTILE(k0, s)                                                        \
    do {                                                                       \
        _Pragma("unroll")                                                      \
        for (int c = 0; c < 8; c++) {                                          \
            int r = r_ld + c * 16;                                             \
            int ra = bm + r;                                                   \
            if (ra >= aM) ra = aM - 1;                                         \
            uint32_t da = sbase + (((s) * 2 * TS2) + r * STR + (kch >> 1)) * 4; \
            CP_ASYNC16(da, A + (size_t)ra * lda + (k0) + kch);                 \
            uint32_t db = sbase + (((s) * 2 * TS2 + TS2) + r * STR + (kch >> 1)) * 4; \
            CP_ASYNC16(db, Bt + (size_t)(bn + r) * ldb + (k0) + kch);          \
        }                                                                      \
        CP_COMMIT();                                                           \
    } while (0)

    const int nT = K >> 6;
    LOADTILE(0, 0);

    for (int t = 0; t < nT; t++) {
        const int s = t & 1;
        if (t + 1 < nT) {
            LOADTILE((t + 1) << 6, (t + 1) & 1);
            CP_WAIT(1);
        } else {
            CP_WAIT(0);
        }
        __syncthreads();

        const uint32_t* As = smd + s * 2 * TS2;
        const uint32_t* Bs = As + TS2;

#pragma unroll
        for (int kk = 0; kk < 4; kk++) {
            uint32_t af[4][4], bf[8][2];
            const int kp = kk * 8 + (lane & 3);
#pragma unroll
            for (int mi = 0; mi < 4; mi++) {
                int r0 = wm * 64 + mi * 16 + (lane >> 2);
                af[mi][0] = As[r0 * STR + kp];
                af[mi][1] = As[(r0 + 8) * STR + kp];
                af[mi][2] = As[r0 * STR + kp + 4];
                af[mi][3] = As[(r0 + 8) * STR + kp + 4];
            }
#pragma unroll
            for (int ni = 0; ni < 8; ni++) {
                int n0 = wn * 64 + ni * 8 + (lane >> 2);
                bf[ni][0] = Bs[n0 * STR + kp];
                bf[ni][1] = Bs[n0 * STR + kp + 4];
            }
#pragma unroll
            for (int mi = 0; mi < 4; mi++)
#pragma unroll
                for (int ni = 0; ni < 8; ni++)
                    mma_bf16(acc[mi][ni], af[mi], bf[ni]);
        }
        __syncthreads();
    }
#undef LOADTILE

    if (epi_mode == 1) {
        // smem-transpose epilogue: acc -> sT[c][w_local], then coalesced rows.
        bf16* sT = (bf16*)smd;
#pragma unroll
        for (int mi = 0; mi < 4; mi++)
#pragma unroll
            for (int half = 0; half < 2; half++) {
                int r = wm * 64 + mi * 16 + (lane >> 2) + half * 8;  // w_local
#pragma unroll
                for (int ni = 0; ni < 8; ni++) {
                    int c0 = wn * 64 + ni * 8 + (lane & 3) * 2;
                    sT[c0 * TSTR + r]       = __float2bfloat16_rn(acc[mi][ni][half * 2 + 0]);
                    sT[(c0 + 1) * TSTR + r] = __float2bfloat16_rn(acc[mi][ni][half * 2 + 1]);
                }
            }
        __syncthreads();
        bf16* cbase = (bf16*)Cv + (size_t)bz * (C_DIM * WPAD);
#pragma unroll
        for (int it = tid; it < 128 * 16; it += 128) {
            int cr = it >> 4;            // local c row
            int wl = (it & 15) * 8;      // chunk of 8 w
            int w = bm + wl;
            if (w < W_DIM) {             // 360 % 8 == 0 -> no mid-chunk wrap
                uint4 v = *(uint4*)&sT[cr * TSTR + wl];
                *(uint4*)(cbase + (size_t)(bn + cr) * WPAD + w) = v;
            }
        }
        return;
    }

    const float* addb = Add ? (Add + (size_t)bz * sAdd) : (const float*)0;
#pragma unroll
    for (int mi = 0; mi < 4; mi++) {
#pragma unroll
        for (int half = 0; half < 2; half++) {
            int r = wm * 64 + mi * 16 + (lane >> 2) + half * 8;
            int p = bm + r;
            if (p >= M) continue;
            if (epi_mode == 0) {
                float* cp = (float*)Cv + (size_t)bz * sC + (size_t)p * ldc + bn;
                const float* ap = addb ? (addb + (size_t)p * ldc + bn) : (const float*)0;
#pragma unroll
                for (int ni = 0; ni < 8; ni++) {
                    int c0 = wn * 64 + ni * 8 + (lane & 3) * 2;
                    float2 v;
                    v.x = acc[mi][ni][half * 2 + 0] * alpha;
                    v.y = acc[mi][ni][half * 2 + 1] * alpha;
                    if (ap) {
                        float2 a2 = *(const float2*)(ap + c0);
                        v.x += a2.x; v.y += a2.y;
                    }
                    *(float2*)(cp + c0) = v;
                }
            } else {
                bf16* cp = (bf16*)Cv + (size_t)bz * sC + (size_t)p * ldc + bn;
#pragma unroll
                for (int ni = 0; ni < 8; ni++) {
                    int c0 = wn * 64 + ni * 8 + (lane & 3) * 2;
                    *(uint32_t*)(cp + c0) =
                        packbf(acc[mi][ni][half * 2 + 0], acc[mi][ni][half * 2 + 1]);
                }
            }
        }
    }
}

// ---------------------------------------------------------------------------
// bf16 tensor-core block-MLP + softshrink (proven in R11). 256 threads.
// ---------------------------------------------------------------------------
#define MS2 68
#define O2S2 36
#define MLP_TC_SMEM ((128 * MS2 + 128 * MS2 + 64 * MS2 + 128 * O2S2 + 256) * 4)

__global__ void __launch_bounds__(256) mlp_tc_kernel(
    const bf16* __restrict__ xh,
    const float* __restrict__ b1,
    const float* __restrict__ b2,
    bf16* __restrict__ y)
{
    extern __shared__ uint32_t sm[];
    uint32_t* sA  = sm;
    uint32_t* sW1 = sA + 128 * MS2;
    uint32_t* sW2 = sW1 + 128 * MS2;
    uint32_t* sO2 = sW2 + 64 * MS2;
    int* s_p  = (int*)(sO2 + 128 * O2S2);
    int* s_pn = s_p + 128;

    const int tid  = threadIdx.x;
    const int lane = tid & 31;
    const int wid  = tid >> 5;
    const int wm   = wid & 1;
    const int wn   = wid >> 1;
    const int k    = blockIdx.y;
    const int p0   = blockIdx.x * 128;

    if (tid < 128) {
        int p = p0 + tid;
        if (p >= P_TOT) p = P_TOT - 1;
        int h = p / W_DIM, w = p - h * W_DIM;
        s_p[tid]  = p;
        s_pn[tid] = ((H_DIM - h) % H_DIM) * W_DIM + ((W_DIM - w) % W_DIM);
    }
    {
        const uint4* w1g = (const uint4*)(g_w1cat + k * 8192);
#pragma unroll
        for (int it = tid; it < 2048; it += 256) {
            int r = it >> 4, c4 = (it & 15) << 2;
            *(uint4*)&sW1[r * MS2 + c4] = w1g[it];
        }
        const uint4* w2g = (const uint4*)(g_w2cat + k * 4096);
#pragma unroll
        for (int it = tid; it < 1024; it += 256) {
            int r = it >> 4, c4 = (it & 15) << 2;
            *(uint4*)&sW2[r * MS2 + c4] = w2g[it];
        }
    }
    __syncthreads();

    // A1 = [xh | xn] tile, bf16 pairs (all 128 cols)
#pragma unroll
    for (int it = tid; it < 4096; it += 256) {
        int r = it >> 5;
        int c = (it & 31) * 4;
        const bf16* src = (c < 64)
            ? xh + (size_t)s_p[r] * C_DIM + k * BS + c
            : xh + (size_t)s_pn[r] * C_DIM + k * BS + (c - 64);
        *(uint2*)&sA[r * MS2 + (c >> 1)] = *(const uint2*)src;
    }
    __syncthreads();

    // ---- Layer 1 ----
    float acc1[4][4][4];
#pragma unroll
    for (int mi = 0; mi < 4; mi++)
#pragma unroll
        for (int ni = 0; ni < 4; ni++)
#pragma unroll
            for (int q = 0; q < 4; q++) acc1[mi][ni][q] = 0.f;

#pragma unroll
    for (int kk = 0; kk < 8; kk++) {
        uint32_t af[4][4], bf[4][2];
        const int kp = kk * 8 + (lane & 3);
#pragma unroll
        for (int mi = 0; mi < 4; mi++) {
            int r0 = wm * 64 + mi * 16 + (lane >> 2);
            af[mi][0] = sA[r0 * MS2 + kp];
            af[mi][1] = sA[(r0 + 8) * MS2 + kp];
            af[mi][2] = sA[r0 * MS2 + kp + 4];
            af[mi][3] = sA[(r0 + 8) * MS2 + kp + 4];
        }
#pragma unroll
        for (int ni = 0; ni < 4; ni++) {
            int n0 = wn * 32 + ni * 8 + (lane >> 2);
            bf[ni][0] = sW1[n0 * MS2 + kp];
            bf[ni][1] = sW1[n0 * MS2 + kp + 4];
        }
#pragma unroll
        for (int mi = 0; mi < 4; mi++)
#pragma unroll
            for (int ni = 0; ni < 4; ni++)
                mma_bf16(acc1[mi][ni], af[mi], bf[ni]);
    }
    __syncthreads();

    // bias + relu -> sA
#pragma unroll
    for (int mi = 0; mi < 4; mi++)
#pragma unroll
        for (int half = 0; half < 2; half++) {
            int r = wm * 64 + mi * 16 + (lane >> 2) + half * 8;
#pragma unroll
            for (int ni = 0; ni < 4; ni++) {
                int c = wn * 32 + ni * 8 + (lane & 3) * 2;
                float bx = (c < 64) ? b1[k * BS + c] : b1[NB * BS + k * BS + (c - 64)];
                float by = (c + 1 < 64) ? b1[k * BS + c + 1] : b1[NB * BS + k * BS + (c + 1 - 64)];
                float vx = fmaxf(0.5f * acc1[mi][ni][half * 2 + 0] + bx, 0.f);
                float vy = fmaxf(0.5f * acc1[mi][ni][half * 2 + 1] + by, 0.f);
                sA[r * MS2 + (c >> 1)] = packbf(vx, vy);
            }
        }
    __syncthreads();

    // ---- Layer 2a: o2k ----
    float acc2[4][2][4];
#pragma unroll
    for (int mi = 0; mi < 4; mi++)
#pragma unroll
        for (int ni = 0; ni < 2; ni++)
#pragma unroll
            for (int q = 0; q < 4; q++) acc2[mi][ni][q] = 0.f;

#pragma unroll
    for (int kk = 0; kk < 8; kk++) {
        uint32_t af[4][4], bf[2][2];
        const int kp = kk * 8 + (lane & 3);
#pragma unroll
        for (int mi = 0; mi < 4; mi++) {
            int r0 = wm * 64 + mi * 16 + (lane >> 2);
            af[mi][0] = sA[r0 * MS2 + kp];
            af[mi][1] = sA[(r0 + 8) * MS2 + kp];
            af[mi][2] = sA[r0 * MS2 + kp + 4];
            af[mi][3] = sA[(r0 + 8) * MS2 + kp + 4];
        }
#pragma unroll
        for (int ni = 0; ni < 2; ni++) {
            int n0 = wn * 16 + ni * 8 + (lane >> 2);
            bf[ni][0] = sW2[n0 * MS2 + kp];
            bf[ni][1] = sW2[n0 * MS2 + kp + 4];
        }
#pragma unroll
        for (int mi = 0; mi < 4; mi++)
#pragma unroll
            for (int ni = 0; ni < 2; ni++)
                mma_bf16(acc2[mi][ni], af[mi], bf[ni]);
    }

    float v2k[4][2][4];
#pragma unroll
    for (int mi = 0; mi < 4; mi++)
#pragma unroll
        for (int half = 0; half < 2; half++) {
            int r = wm * 64 + mi * 16 + (lane >> 2) + half * 8;
#pragma unroll
            for (int ni = 0; ni < 2; ni++) {
                int c = wn * 16 + ni * 8 + (lane & 3) * 2;
                float vx = 0.5f * acc2[mi][ni][half * 2 + 0] + b2[k * BS + c];
                float vy = 0.5f * acc2[mi][ni][half * 2 + 1] + b2[k * BS + c + 1];
                v2k[mi][ni][half * 2 + 0] = vx;
                v2k[mi][ni][half * 2 + 1] = vy;
                sO2[r * O2S2 + (c >> 1)] = packbf(vx, vy);
            }
        }
    __syncthreads();

    // ---- Layer 2b: o2n ----
    float accn[4][2][4];
#pragma unroll
    for (int mi = 0; mi < 4; mi++)
#pragma unroll
        for (int ni = 0; ni < 2; ni++)
#pragma unroll
            for (int q = 0; q < 4; q++) accn[mi][ni][q] = 0.f;

#pragma unroll
    for (int kk = 0; kk < 4; kk++) {
        uint32_t af[4][4], bf[2][2];
        const int kp = kk * 8 + (lane & 3);
#pragma unroll
        for (int mi = 0; mi < 4; mi++) {
            int r0 = wm * 64 + mi * 16 + (lane >> 2);
            af[mi][0] = sA[r0 * MS2 + 32 + kp];
            af[mi][1] = sA[(r0 + 8) * MS2 + 32 + kp];
            af[mi][2] = sA[r0 * MS2 + 32 + kp + 4];
            af[mi][3] = sA[(r0 + 8) * MS2 + 32 + kp + 4];
        }
#pragma unroll
        for (int ni = 0; ni < 2; ni++) {
            int n0 = wn * 16 + ni * 8 + (lane >> 2);
            bf[ni][0] = sW2[n0 * MS2 + kp];
            bf[ni][1] = sW2[n0 * MS2 + kp + 4];
        }
#pragma unroll
        for (int mi = 0; mi < 4; mi++)
#pragma unroll
            for (int ni = 0; ni < 2; ni++)
                mma_bf16(accn[mi][ni], af[mi], bf[ni]);
    }
#pragma unroll
    for (int kk = 0; kk < 4; kk++) {
        uint32_t af[4][4], bf[2][2];
        const int kp = kk * 8 + (lane & 3);
#pragma unroll
        for (int mi = 0; mi < 4; mi++) {
            int r0 = wm * 64 + mi * 16 + (lane >> 2);
            af[mi][0] = sO2[r0 * O2S2 + kp];
            af[mi][1] = sO2[(r0 + 8) * O2S2 + kp];
            af[mi][2] = sO2[r0 * O2S2 + kp + 4];
            af[mi][3] = sO2[(r0 + 8) * O2S2 + kp + 4];
        }
#pragma unroll
        for (int ni = 0; ni < 2; ni++) {
            int n0 = wn * 16 + ni * 8 + (lane >> 2);
            bf[ni][0] = sW2[n0 * MS2 + 32 + kp];
            bf[ni][1] = sW2[n0 * MS2 + 32 + kp + 4];
        }
#pragma unroll
        for (int mi = 0; mi < 4; mi++)
#pragma unroll
            for (int ni = 0; ni < 2; ni++)
                mma_bf16(accn[mi][ni], af[mi], bf[ni]);
    }

    // y = softshrink(o2k + o2n)
#pragma unroll
    for (int mi = 0; mi < 4; mi++)
#pragma unroll
        for (int half = 0; half < 2; half++) {
            int r = wm * 64 + mi * 16 + (lane >> 2) + half * 8;
            int p = p0 + r;
            if (p < P_TOT) {
#pragma unroll
                for (int ni = 0; ni < 2; ni++) {
                    int c = wn * 16 + ni * 8 + (lane & 3) * 2;
                    float vx = v2k[mi][ni][half * 2 + 0]
                             + 0.5f * accn[mi][ni][half * 2 + 0] + b2[NB * BS + k * BS + c];
                    float vy = v2k[mi][ni][half * 2 + 1]
                             + 0.5f * accn[mi][ni][half * 2 + 1] + b2[NB * BS + k * BS + c + 1];
                    float ax = fabsf(vx) - SPARSITY;
                    float ay = fabsf(vy) - SPARSITY;
                    float rx = ax > 0.f ? copysignf(ax, vx) : 0.f;
                    float ry = ay > 0.f ? copysignf(ay, vy) : 0.f;
                    *(uint32_t*)(y + (size_t)p * C_DIM + k * BS + c) = packbf(rx, ry);
                }
            }
        }
}

// ---------------------------------------------------------------------------
// kernel_launch
// ---------------------------------------------------------------------------
extern "C" void kernel_launch(void* const* d_in, const int* in_sizes, int n_in,
                              void* d_out, int out_size) {
    const float* x  = (const float*)d_in[0];
    const float* w1 = (const float*)d_in[1];
    const float* b1 = (const float*)d_in[2];
    const float* w2 = (const float*)d_in[3];
    const float* b2 = (const float*)d_in[4];
    float* out = (float*)d_out;

    bf16 *bufA, *bufB, *casC, *casW, *xbf;
    cudaGetSymbolAddress((void**)&bufA, g_bufA);
    cudaGetSymbolAddress((void**)&bufB, g_bufB);
    cudaGetSymbolAddress((void**)&casC, g_casC);
    cudaGetSymbolAddress((void**)&casW, g_casW);
    cudaGetSymbolAddress((void**)&xbf,  g_xbf);

    cudaFuncSetAttribute(mlp_tc_kernel, cudaFuncAttributeMaxDynamicSharedMemorySize,
                         MLP_TC_SMEM);
    cudaFuncSetAttribute(bf16gemm_kernel, cudaFuncAttributeMaxDynamicSharedMemorySize,
                         GEMM_SMEM);

    init_cas_kernel<<<(C_DIM * C_DIM + 255) / 256, 256>>>(casC, C_DIM);
    init_casw_pad_kernel<<<(WPAD * WPAD + 255) / 256, 256>>>();
    convert_x_kernel<<<(NELEM / 4 + 255) / 256, 256>>>(x);
    {
        int nprep = NB * 128 * 64 + NB * 64 * 64;
        prep_mlp_weights<<<(nprep + 255) / 256, 256>>>(w1, w2);
    }

    const long long sPadH = (long long)C_DIM * WPAD;
    const long long sCmpH = (long long)W_DIM * C_DIM;
    const int nPad = H_DIM * C_DIM * 12;

    zeropad_kernel<<<(nPad + 255) / 256, 256>>>(bufA);

    // GEMM1 (batched over h): T1t[h] = (X[h] @ casC)^T -> padded bufA
    bf16gemm_kernel<<<dim3(C_DIM / 128, 3, H_DIM), 128, GEMM_SMEM>>>(
        W_DIM, C_DIM, W_DIM,
        xbf, C_DIM, (long long)W_DIM * C_DIM,
        casC, C_DIM, 0,
        bufA, 0, 0,
        1.0f, nullptr, 0, 1);

    // GEMM2: XH[h] = casW @ T1[h] -> compact bf16 bufB
    bf16gemm_kernel<<<dim3(C_DIM / 128, 3, H_DIM), 128, GEMM_SMEM>>>(
        W_DIM, WPAD, WPAD,
        casW, WPAD, 0,
        bufA, WPAD, sPadH,
        bufB, C_DIM, sCmpH,
        1.0f, nullptr, 0, 2);

    // bf16 tensor-core block MLP + softshrink: bufB -> bufA (compact)
    mlp_tc_kernel<<<dim3((P_TOT + 127) / 128, NB), 256, MLP_TC_SMEM>>>(
        bufB, b1, b2, bufA);

    zeropad_kernel<<<(nPad + 255) / 256, 256>>>(bufB);

    // GEMM3 (batched over h): T2t[h] = (Y[h] @ casC)^T -> padded bufB
    bf16gemm_kernel<<<dim3(C_DIM / 128, 3, H_DIM), 128, GEMM_SMEM>>>(
        W_DIM, C_DIM, W_DIM,
        bufA, C_DIM, (long long)W_DIM * C_DIM,
        casC, C_DIM, 0,
        bufB, 0, 0,
        1.0f, nullptr, 0, 1);

    // GEMM4: out[h] = casW @ T2[h] / (W*C) + x[h]  (fp32 out, exact fp32 bias)
    bf16gemm_kernel<<<dim3(C_DIM / 128, 3, H_DIM), 128, GEMM_SMEM>>>(
        W_DIM, WPAD, WPAD,
        casW, WPAD, 0,
        bufB, WPAD, sPadH,
        out, C_DIM, sCmpH,
        1.0f / (float)(W_DIM * C_DIM), x, sCmpH, 0);
}

// round 16
// speedup vs baseline: 5.8637x; 1.0292x over previous
#include <cuda_runtime.h>
#include <cuda_bf16.h>
#include <cstdint>

// Problem constants
#define H_DIM 180
#define W_DIM 360
#define WPAD  384
#define C_DIM 512
#define P_TOT (H_DIM * W_DIM)           // 64800
#define NELEM (P_TOT * C_DIM)
#define PADELEM (H_DIM * C_DIM * WPAD)
#define NB 8
#define BS 64
#define SPARSITY 0.01f

typedef __nv_bfloat16 bf16;

// ---------------------------------------------------------------------------
// Scratch (bf16 activations)
// ---------------------------------------------------------------------------
__device__ bf16 g_bufA[PADELEM];
__device__ bf16 g_bufB[PADELEM];
__device__ bf16 g_xbf[NELEM];
__device__ bf16 g_casC[C_DIM * C_DIM];
__device__ bf16 g_casW[WPAD * WPAD];
__device__ uint32_t g_w1cat[NB * 128 * 64];   // [blk][o][ipair] bf16x2
__device__ uint32_t g_w2cat[NB * 64 * 64];    // [blk][o][ipair] bf16x2

// ---------------------------------------------------------------------------
// bf16 helpers (plain mma.sync m16n8k16 — compiles for base sm_103)
// ---------------------------------------------------------------------------
__device__ __forceinline__ uint32_t packbf(float lo, float hi) {
    uint32_t r;
    asm("cvt.rn.bf16x2.f32 %0, %1, %2;" : "=r"(r) : "f"(hi), "f"(lo));
    return r;
}

__device__ __forceinline__ void mma_bf16(float* d, const uint32_t* a, const uint32_t* b) {
    asm volatile(
        "mma.sync.aligned.m16n8k16.row.col.f32.bf16.bf16.f32 "
        "{%0,%1,%2,%3}, {%4,%5,%6,%7}, {%8,%9}, {%0,%1,%2,%3};"
        : "+f"(d[0]), "+f"(d[1]), "+f"(d[2]), "+f"(d[3])
        : "r"(a[0]), "r"(a[1]), "r"(a[2]), "r"(a[3]), "r"(b[0]), "r"(b[1]));
}

#define CP_ASYNC16(dst, src) \
    asm volatile("cp.async.cg.shared.global [%0], [%1], 16;" \
                 :: "r"(dst), "l"(src) : "memory")
#define CP_COMMIT()  asm volatile("cp.async.commit_group;" ::: "memory")
#define CP_WAIT(n)   asm volatile("cp.async.wait_group %0;" :: "n"(n) : "memory")

// ---------------------------------------------------------------------------
// Init kernels
// ---------------------------------------------------------------------------
__global__ void init_cas_kernel(bf16* __restrict__ out, int n) {
    int i = blockIdx.x * blockDim.x + threadIdx.x;
    if (i >= n * n) return;
    int t = i / n, d = i % n;
    long long m = (2LL * t * d) % (2LL * n);
    float a = (float)m / (float)n;
    float s, c;
    sincospif(a, &s, &c);
    out[i] = __float2bfloat16_rn(c + s);
}

__global__ void init_casw_pad_kernel() {
    int i = blockIdx.x * blockDim.x + threadIdx.x;
    if (i >= WPAD * WPAD) return;
    int t = i / WPAD, d = i % WPAD;
    float v = 0.f;
    if (t < W_DIM && d < W_DIM) {
        long long m = (2LL * t * d) % (2LL * W_DIM);
        float a = (float)m / (float)W_DIM;
        float s, c;
        sincospif(a, &s, &c);
        v = c + s;
    }
    g_casW[i] = __float2bfloat16_rn(v);
}

__global__ void convert_x_kernel(const float* __restrict__ x) {
    int i = blockIdx.x * blockDim.x + threadIdx.x;   // processes 4 elems
    if (i >= NELEM / 4) return;
    float4 v = *(const float4*)(x + i * 4);
    uint2 u;
    u.x = packbf(v.x, v.y);
    u.y = packbf(v.z, v.w);
    *(uint2*)((char*)g_xbf + i * 8) = u;
}

// Packed bf16-pair MLP weights, pre-transposed (see R7 derivation).
__global__ void prep_mlp_weights(const float* __restrict__ w1,
                                 const float* __restrict__ w2) {
    const int NW1 = NB * 128 * 64;
    const int NW2 = NB * 64 * 64;
    int idx = blockIdx.x * blockDim.x + threadIdx.x;
    if (idx < NW1) {
        int blk = idx >> 13;
        int rem = idx & 8191;
        int o = rem >> 6, j = rem & 63;
        const float* w1p = w1 + blk * 4096;
        const float* w1q = w1 + (NB + blk) * 4096;
        float v[2];
#pragma unroll
        for (int q = 0; q < 2; q++) {
            int i = 2 * j + q;
            if (o < 64) {
                if (i < 64) v[q] = w1p[i * 64 + o] + w1q[i * 64 + o];
                else        v[q] = w1p[(i - 64) * 64 + o] - w1q[(i - 64) * 64 + o];
            } else {
                int oo = o - 64;
                if (i < 64) v[q] = w1p[i * 64 + oo] - w1q[i * 64 + oo];
                else        v[q] = w1p[(i - 64) * 64 + oo] + w1q[(i - 64) * 64 + oo];
            }
        }
        g_w1cat[idx] = packbf(v[0], v[1]);
    } else if (idx < NW1 + NW2) {
        int jx = idx - NW1;
        int blk = jx >> 12;
        int rem = jx & 4095;
        int o = rem >> 6, j = rem & 63;
        const float* w2p = w2 + blk * 4096;
        const float* w2q = w2 + (NB + blk) * 4096;
        float v[2];
#pragma unroll
        for (int q = 0; q < 2; q++) {
            int i = 2 * j + q;
            if (i < 64) v[q] = w2p[i * 64 + o] + w2q[i * 64 + o];
            else        v[q] = w2p[(i - 64) * 64 + o] - w2q[(i - 64) * 64 + o];
        }
        g_w2cat[jx] = packbf(v[0], v[1]);
    }
}

// ---------------------------------------------------------------------------
// bf16 warp-MMA GEMM, 2-stage cp.async, m16n8k16.
// BM=BN=128, BK=64, 4 warps (2x2), warp tile 64x64, stride-36 smem.
//   epi_mode 0: fp32 compact store (*alpha, +Add fp32), guard row<M
//   epi_mode 1: smem-transposed store into [h][c][wpad] with flat M=P_TOT.
//               Each 8-wide chunk lies in a single h (h boundaries and chunk
//               starts are both 0 mod 8). Also zero-fills the w-pad columns
//               for all h this tile overlaps (replaces zeropad kernel).
//   epi_mode 2: bf16 compact [p][c]
// ---------------------------------------------------------------------------
#define STR 36
#define TS2 (128 * STR)
#define GEMM_SMEM (2 * 2 * TS2 * 4)       // 73,728 bytes
#define TSTR 136                           // transposed-tile row stride (bf16)

__global__ void __launch_bounds__(128) bf16gemm_kernel(
    int M, int K, int aM,
    const bf16* __restrict__ A, int lda, long long sA,
    const bf16* __restrict__ Bt, int ldb, long long sB,
    void* __restrict__ Cv, int ldc, long long sC,
    float alpha, const float* __restrict__ Add, long long sAdd,
    int epi_mode)
{
    extern __shared__ uint32_t smd[];
    const uint32_t sbase = (uint32_t)__cvta_generic_to_shared(smd);

    const int tid  = threadIdx.x;
    const int lane = tid & 31;
    const int wid  = tid >> 5;
    const int wm   = wid & 1;
    const int wn   = wid >> 1;
    const int bm   = blockIdx.y * 128;
    const int bn   = blockIdx.x * 128;
    const int bz   = blockIdx.z;

    A  += (size_t)bz * sA;
    Bt += (size_t)bz * sB;

    float acc[4][8][4];
#pragma unroll
    for (int mi = 0; mi < 4; mi++)
#pragma unroll
        for (int ni = 0; ni < 8; ni++)
#pragma unroll
            for (int q = 0; q < 4; q++) acc[mi][ni][q] = 0.f;

    const int r_ld = tid >> 3;            // 0..15
    const int kch  = (tid & 7) << 3;      // bf16 offset within 64: 0,8,...,56

#define LOADTILE(k0, s)                                                        \
    do {                                                                       \
        _Pragma("unroll")                                                      \
        for (int c = 0; c < 8; c++) {                                          \
            int r = r_ld + c * 16;                                             \
            int ra = bm + r;                                                   \
            if (ra >= aM) ra = aM - 1;                                         \
            uint32_t da = sbase + (((s) * 2 * TS2) + r * STR + (kch >> 1)) * 4; \
            CP_ASYNC16(da, A + (size_t)ra * lda + (k0) + kch);                 \
            uint32_t db = sbase + (((s) * 2 * TS2 + TS2) + r * STR + (kch >> 1)) * 4; \
            CP_ASYNC16(db, Bt + (size_t)(bn + r) * ldb + (k0) + kch);          \
        }                                                                      \
        CP_COMMIT();                                                           \
    } while (0)

    const int nT = K >> 6;
    LOADTILE(0, 0);

    for (int t = 0; t < nT; t++) {
        const int s = t & 1;
        if (t + 1 < nT) {
            LOADTILE((t + 1) << 6, (t + 1) & 1);
            CP_WAIT(1);
        } else {
            CP_WAIT(0);
        }
        __syncthreads();

        const uint32_t* As = smd + s * 2 * TS2;
        const uint32_t* Bs = As + TS2;

#pragma unroll
        for (int kk = 0; kk < 4; kk++) {
            uint32_t af[4][4], bf[8][2];
            const int kp = kk * 8 + (lane & 3);
#pragma unroll
            for (int mi = 0; mi < 4; mi++) {
                int r0 = wm * 64 + mi * 16 + (lane >> 2);
                af[mi][0] = As[r0 * STR + kp];
                af[mi][1] = As[(r0 + 8) * STR + kp];
                af[mi][2] = As[r0 * STR + kp + 4];
                af[mi][3] = As[(r0 + 8) * STR + kp + 4];
            }
#pragma unroll
            for (int ni = 0; ni < 8; ni++) {
                int n0 = wn * 64 + ni * 8 + (lane >> 2);
                bf[ni][0] = Bs[n0 * STR + kp];
                bf[ni][1] = Bs[n0 * STR + kp + 4];
            }
#pragma unroll
            for (int mi = 0; mi < 4; mi++)
#pragma unroll
                for (int ni = 0; ni < 8; ni++)
                    mma_bf16(acc[mi][ni], af[mi], bf[ni]);
        }
        __syncthreads();
    }
#undef LOADTILE

    if (epi_mode == 1) {
        // smem-transpose epilogue: acc -> sT[c][r_local], then coalesced rows.
        bf16* sT = (bf16*)smd;
#pragma unroll
        for (int mi = 0; mi < 4; mi++)
#pragma unroll
            for (int half = 0; half < 2; half++) {
                int r = wm * 64 + mi * 16 + (lane >> 2) + half * 8;
#pragma unroll
                for (int ni = 0; ni < 8; ni++) {
                    int c0 = wn * 64 + ni * 8 + (lane & 3) * 2;
                    sT[c0 * TSTR + r]       = __float2bfloat16_rn(acc[mi][ni][half * 2 + 0]);
                    sT[(c0 + 1) * TSTR + r] = __float2bfloat16_rn(acc[mi][ni][half * 2 + 1]);
                }
            }
        __syncthreads();
        bf16* cbase = (bf16*)Cv;
        // main stores: each 8-wide chunk is within one h (boundaries 0 mod 8)
#pragma unroll
        for (int it = tid; it < 128 * 16; it += 128) {
            int cr = it >> 4;            // local c row
            int rl = (it & 15) * 8;      // chunk of 8 local rows
            int p = bm + rl;
            if (p < P_TOT) {
                int h = p / W_DIM;
                int w = p - h * W_DIM;
                uint4 v = *(uint4*)&sT[cr * TSTR + rl];
                *(uint4*)(cbase + (size_t)h * (C_DIM * WPAD)
                          + (size_t)(bn + cr) * WPAD + w) = v;
            }
        }
        // zero-fill pad w in [360,384) for all h overlapped by this tile
        {
            uint4 z = make_uint4(0u, 0u, 0u, 0u);
            int h0 = bm / W_DIM;
            int h1 = (bm + 127 < P_TOT ? bm + 127 : P_TOT - 1) / W_DIM;
            for (int h = h0; h <= h1; h++) {
#pragma unroll
                for (int it = tid; it < 128 * 3; it += 128) {
                    int cr = it >> 2;        // wrong divisor guard below
                    // 3 chunks of 8 per c-row: decode as (cr, ch)
                    cr = it / 3;
                    int ch = it - cr * 3;
                    *(uint4*)(cbase + (size_t)h * (C_DIM * WPAD)
                              + (size_t)(bn + cr) * WPAD + W_DIM + ch * 8) = z;
                }
            }
        }
        return;
    }

    const float* addb = Add ? (Add + (size_t)bz * sAdd) : (const float*)0;
#pragma unroll
    for (int mi = 0; mi < 4; mi++) {
#pragma unroll
        for (int half = 0; half < 2; half++) {
            int r = wm * 64 + mi * 16 + (lane >> 2) + half * 8;
            int p = bm + r;
            if (p >= M) continue;
            if (epi_mode == 0) {
                float* cp = (float*)Cv + (size_t)bz * sC + (size_t)p * ldc + bn;
                const float* ap = addb ? (addb + (size_t)p * ldc + bn) : (const float*)0;
#pragma unroll
                for (int ni = 0; ni < 8; ni++) {
                    int c0 = wn * 64 + ni * 8 + (lane & 3) * 2;
                    float2 v;
                    v.x = acc[mi][ni][half * 2 + 0] * alpha;
                    v.y = acc[mi][ni][half * 2 + 1] * alpha;
                    if (ap) {
                        float2 a2 = *(const float2*)(ap + c0);
                        v.x += a2.x; v.y += a2.y;
                    }
                    *(float2*)(cp + c0) = v;
                }
            } else {
                bf16* cp = (bf16*)Cv + (size_t)bz * sC + (size_t)p * ldc + bn;
#pragma unroll
                for (int ni = 0; ni < 8; ni++) {
                    int c0 = wn * 64 + ni * 8 + (lane & 3) * 2;
                    *(uint32_t*)(cp + c0) =
                        packbf(acc[mi][ni][half * 2 + 0], acc[mi][ni][half * 2 + 1]);
                }
            }
        }
    }
}

// ---------------------------------------------------------------------------
// bf16 tensor-core block-MLP + softshrink (proven in R11). 256 threads.
// ---------------------------------------------------------------------------
#define MS2 68
#define O2S2 36
#define MLP_TC_SMEM ((128 * MS2 + 128 * MS2 + 64 * MS2 + 128 * O2S2 + 256) * 4)

__global__ void __launch_bounds__(256) mlp_tc_kernel(
    const bf16* __restrict__ xh,
    const float* __restrict__ b1,
    const float* __restrict__ b2,
    bf16* __restrict__ y)
{
    extern __shared__ uint32_t sm[];
    uint32_t* sA  = sm;
    uint32_t* sW1 = sA + 128 * MS2;
    uint32_t* sW2 = sW1 + 128 * MS2;
    uint32_t* sO2 = sW2 + 64 * MS2;
    int* s_p  = (int*)(sO2 + 128 * O2S2);
    int* s_pn = s_p + 128;

    const int tid  = threadIdx.x;
    const int lane = tid & 31;
    const int wid  = tid >> 5;
    const int wm   = wid & 1;
    const int wn   = wid >> 1;
    const int k    = blockIdx.y;
    const int p0   = blockIdx.x * 128;

    if (tid < 128) {
        int p = p0 + tid;
        if (p >= P_TOT) p = P_TOT - 1;
        int h = p / W_DIM, w = p - h * W_DIM;
        s_p[tid]  = p;
        s_pn[tid] = ((H_DIM - h) % H_DIM) * W_DIM + ((W_DIM - w) % W_DIM);
    }
    {
        const uint4* w1g = (const uint4*)(g_w1cat + k * 8192);
#pragma unroll
        for (int it = tid; it < 2048; it += 256) {
            int r = it >> 4, c4 = (it & 15) << 2;
            *(uint4*)&sW1[r * MS2 + c4] = w1g[it];
        }
        const uint4* w2g = (const uint4*)(g_w2cat + k * 4096);
#pragma unroll
        for (int it = tid; it < 1024; it += 256) {
            int r = it >> 4, c4 = (it & 15) << 2;
            *(uint4*)&sW2[r * MS2 + c4] = w2g[it];
        }
    }
    __syncthreads();

    // A1 = [xh | xn] tile, bf16 pairs (all 128 cols)
#pragma unroll
    for (int it = tid; it < 4096; it += 256) {
        int r = it >> 5;
        int c = (it & 31) * 4;
        const bf16* src = (c < 64)
            ? xh + (size_t)s_p[r] * C_DIM + k * BS + c
            : xh + (size_t)s_pn[r] * C_DIM + k * BS + (c - 64);
        *(uint2*)&sA[r * MS2 + (c >> 1)] = *(const uint2*)src;
    }
    __syncthreads();

    // ---- Layer 1 ----
    float acc1[4][4][4];
#pragma unroll
    for (int mi = 0; mi < 4; mi++)
#pragma unroll
        for (int ni = 0; ni < 4; ni++)
#pragma unroll
            for (int q = 0; q < 4; q++) acc1[mi][ni][q] = 0.f;

#pragma unroll
    for (int kk = 0; kk < 8; kk++) {
        uint32_t af[4][4], bf[4][2];
        const int kp = kk * 8 + (lane & 3);
#pragma unroll
        for (int mi = 0; mi < 4; mi++) {
            int r0 = wm * 64 + mi * 16 + (lane >> 2);
            af[mi][0] = sA[r0 * MS2 + kp];
            af[mi][1] = sA[(r0 + 8) * MS2 + kp];
            af[mi][2] = sA[r0 * MS2 + kp + 4];
            af[mi][3] = sA[(r0 + 8) * MS2 + kp + 4];
        }
#pragma unroll
        for (int ni = 0; ni < 4; ni++) {
            int n0 = wn * 32 + ni * 8 + (lane >> 2);
            bf[ni][0] = sW1[n0 * MS2 + kp];
            bf[ni][1] = sW1[n0 * MS2 + kp + 4];
        }
#pragma unroll
        for (int mi = 0; mi < 4; mi++)
#pragma unroll
            for (int ni = 0; ni < 4; ni++)
                mma_bf16(acc1[mi][ni], af[mi], bf[ni]);
    }
    __syncthreads();

    // bias + relu -> sA
#pragma unroll
    for (int mi = 0; mi < 4; mi++)
#pragma unroll
        for (int half = 0; half < 2; half++) {
            int r = wm * 64 + mi * 16 + (lane >> 2) + half * 8;
#pragma unroll
            for (int ni = 0; ni < 4; ni++) {
                int c = wn * 32 + ni * 8 + (lane & 3) * 2;
                float bx = (c < 64) ? b1[k * BS + c] : b1[NB * BS + k * BS + (c - 64)];
                float by = (c + 1 < 64) ? b1[k * BS + c + 1] : b1[NB * BS + k * BS + (c + 1 - 64)];
                float vx = fmaxf(0.5f * acc1[mi][ni][half * 2 + 0] + bx, 0.f);
                float vy = fmaxf(0.5f * acc1[mi][ni][half * 2 + 1] + by, 0.f);
                sA[r * MS2 + (c >> 1)] = packbf(vx, vy);
            }
        }
    __syncthreads();

    // ---- Layer 2a: o2k ----
    float acc2[4][2][4];
#pragma unroll
    for (int mi = 0; mi < 4; mi++)
#pragma unroll
        for (int ni = 0; ni < 2; ni++)
#pragma unroll
            for (int q = 0; q < 4; q++) acc2[mi][ni][q] = 0.f;

#pragma unroll
    for (int kk = 0; kk < 8; kk++) {
        uint32_t af[4][4], bf[2][2];
        const int kp = kk * 8 + (lane & 3);
#pragma unroll
        for (int mi = 0; mi < 4; mi++) {
            int r0 = wm * 64 + mi * 16 + (lane >> 2);
            af[mi][0] = sA[r0 * MS2 + kp];
            af[mi][1] = sA[(r0 + 8) * MS2 + kp];
            af[mi][2] = sA[r0 * MS2 + kp + 4];
            af[mi][3] = sA[(r0 + 8) * MS2 + kp + 4];
        }
#pragma unroll
        for (int ni = 0; ni < 2; ni++) {
            int n0 = wn * 16 + ni * 8 + (lane >> 2);
            bf[ni][0] = sW2[n0 * MS2 + kp];
            bf[ni][1] = sW2[n0 * MS2 + kp + 4];
        }
#pragma unroll
        for (int mi = 0; mi < 4; mi++)
#pragma unroll
            for (int ni = 0; ni < 2; ni++)
                mma_bf16(acc2[mi][ni], af[mi], bf[ni]);
    }

    float v2k[4][2][4];
#pragma unroll
    for (int mi = 0; mi < 4; mi++)
#pragma unroll
        for (int half = 0; half < 2; half++) {
            int r = wm * 64 + mi * 16 + (lane >> 2) + half * 8;
#pragma unroll
            for (int ni = 0; ni < 2; ni++) {
                int c = wn * 16 + ni * 8 + (lane & 3) * 2;
                float vx = 0.5f * acc2[mi][ni][half * 2 + 0] + b2[k * BS + c];
                float vy = 0.5f * acc2[mi][ni][half * 2 + 1] + b2[k * BS + c + 1];
                v2k[mi][ni][half * 2 + 0] = vx;
                v2k[mi][ni][half * 2 + 1] = vy;
                sO2[r * O2S2 + (c >> 1)] = packbf(vx, vy);
            }
        }
    __syncthreads();

    // ---- Layer 2b: o2n ----
    float accn[4][2][4];
#pragma unroll
    for (int mi = 0; mi < 4; mi++)
#pragma unroll
        for (int ni = 0; ni < 2; ni++)
#pragma unroll
            for (int q = 0; q < 4; q++) accn[mi][ni][q] = 0.f;

#pragma unroll
    for (int kk = 0; kk < 4; kk++) {
        uint32_t af[4][4], bf[2][2];
        const int kp = kk * 8 + (lane & 3);
#pragma unroll
        for (int mi = 0; mi < 4; mi++) {
            int r0 = wm * 64 + mi * 16 + (lane >> 2);
            af[mi][0] = sA[r0 * MS2 + 32 + kp];
            af[mi][1] = sA[(r0 + 8) * MS2 + 32 + kp];
            af[mi][2] = sA[r0 * MS2 + 32 + kp + 4];
            af[mi][3] = sA[(r0 + 8) * MS2 + 32 + kp + 4];
        }
#pragma unroll
        for (int ni = 0; ni < 2; ni++) {
            int n0 = wn * 16 + ni * 8 + (lane >> 2);
            bf[ni][0] = sW2[n0 * MS2 + kp];
            bf[ni][1] = sW2[n0 * MS2 + kp + 4];
        }
#pragma unroll
        for (int mi = 0; mi < 4; mi++)
#pragma unroll
            for (int ni = 0; ni < 2; ni++)
                mma_bf16(accn[mi][ni], af[mi], bf[ni]);
    }
#pragma unroll
    for (int kk = 0; kk < 4; kk++) {
        uint32_t af[4][4], bf[2][2];
        const int kp = kk * 8 + (lane & 3);
#pragma unroll
        for (int mi = 0; mi < 4; mi++) {
            int r0 = wm * 64 + mi * 16 + (lane >> 2);
            af[mi][0] = sO2[r0 * O2S2 + kp];
            af[mi][1] = sO2[(r0 + 8) * O2S2 + kp];
            af[mi][2] = sO2[r0 * O2S2 + kp + 4];
            af[mi][3] = sO2[(r0 + 8) * O2S2 + kp + 4];
        }
#pragma unroll
        for (int ni = 0; ni < 2; ni++) {
            int n0 = wn * 16 + ni * 8 + (lane >> 2);
            bf[ni][0] = sW2[n0 * MS2 + 32 + kp];
            bf[ni][1] = sW2[n0 * MS2 + 32 + kp + 4];
        }
#pragma unroll
        for (int mi = 0; mi < 4; mi++)
#pragma unroll
            for (int ni = 0; ni < 2; ni++)
                mma_bf16(accn[mi][ni], af[mi], bf[ni]);
    }

    // y = softshrink(o2k + o2n)
#pragma unroll
    for (int mi = 0; mi < 4; mi++)
#pragma unroll
        for (int half = 0; half < 2; half++) {
            int r = wm * 64 + mi * 16 + (lane >> 2) + half * 8;
            int p = p0 + r;
            if (p < P_TOT) {
#pragma unroll
                for (int ni = 0; ni < 2; ni++) {
                    int c = wn * 16 + ni * 8 + (lane & 3) * 2;
                    float vx = v2k[mi][ni][half * 2 + 0]
                             + 0.5f * accn[mi][ni][half * 2 + 0] + b2[NB * BS + k * BS + c];
                    float vy = v2k[mi][ni][half * 2 + 1]
                             + 0.5f * accn[mi][ni][half * 2 + 1] + b2[NB * BS + k * BS + c + 1];
                    float ax = fabsf(vx) - SPARSITY;
                    float ay = fabsf(vy) - SPARSITY;
                    float rx = ax > 0.f ? copysignf(ax, vx) : 0.f;
                    float ry = ay > 0.f ? copysignf(ay, vy) : 0.f;
                    *(uint32_t*)(y + (size_t)p * C_DIM + k * BS + c) = packbf(rx, ry);
                }
            }
        }
}

// ---------------------------------------------------------------------------
// kernel_launch
// ---------------------------------------------------------------------------
extern "C" void kernel_launch(void* const* d_in, const int* in_sizes, int n_in,
                              void* d_out, int out_size) {
    const float* x  = (const float*)d_in[0];
    const float* w1 = (const float*)d_in[1];
    const float* b1 = (const float*)d_in[2];
    const float* w2 = (const float*)d_in[3];
    const float* b2 = (const float*)d_in[4];
    float* out = (float*)d_out;

    bf16 *bufA, *bufB, *casC, *casW, *xbf;
    cudaGetSymbolAddress((void**)&bufA, g_bufA);
    cudaGetSymbolAddress((void**)&bufB, g_bufB);
    cudaGetSymbolAddress((void**)&casC, g_casC);
    cudaGetSymbolAddress((void**)&casW, g_casW);
    cudaGetSymbolAddress((void**)&xbf,  g_xbf);

    cudaFuncSetAttribute(mlp_tc_kernel, cudaFuncAttributeMaxDynamicSharedMemorySize,
                         MLP_TC_SMEM);
    cudaFuncSetAttribute(bf16gemm_kernel, cudaFuncAttributeMaxDynamicSharedMemorySize,
                         GEMM_SMEM);

    init_cas_kernel<<<(C_DIM * C_DIM + 255) / 256, 256>>>(casC, C_DIM);
    init_casw_pad_kernel<<<(WPAD * WPAD + 255) / 256, 256>>>();
    convert_x_kernel<<<(NELEM / 4 + 255) / 256, 256>>>(x);
    {
        int nprep = NB * 128 * 64 + NB * 64 * 64;
        prep_mlp_weights<<<(nprep + 255) / 256, 256>>>(w1, w2);
    }

    const long long sPadH = (long long)C_DIM * WPAD;
    const long long sCmpH = (long long)W_DIM * C_DIM;

    // GEMM1 (flat M): T1t = (X @ casC)^T -> padded bufA (pads zero-filled in epi)
    bf16gemm_kernel<<<dim3(C_DIM / 128, (P_TOT + 127) / 128, 1), 128, GEMM_SMEM>>>(
        P_TOT, C_DIM, P_TOT,
        xbf, C_DIM, 0,
        casC, C_DIM, 0,
        bufA, 0, 0,
        1.0f, nullptr, 0, 1);

    // GEMM2: XH[h] = casW @ T1[h] -> compact bf16 bufB
    bf16gemm_kernel<<<dim3(C_DIM / 128, 3, H_DIM), 128, GEMM_SMEM>>>(
        W_DIM, WPAD, WPAD,
        casW, WPAD, 0,
        bufA, WPAD, sPadH,
        bufB, C_DIM, sCmpH,
        1.0f, nullptr, 0, 2);

    // bf16 tensor-core block MLP + softshrink: bufB -> bufA (compact)
    mlp_tc_kernel<<<dim3((P_TOT + 127) / 128, NB), 256, MLP_TC_SMEM>>>(
        bufB, b1, b2, bufA);

    // GEMM3 (flat M): T2t = (Y @ casC)^T -> padded bufB (pads zero-filled in epi)
    bf16gemm_kernel<<<dim3(C_DIM / 128, (P_TOT + 127) / 128, 1), 128, GEMM_SMEM>>>(
        P_TOT, C_DIM, P_TOT,
        bufA, C_DIM, 0,
        casC, C_DIM, 0,
        bufB, 0, 0,
        1.0f, nullptr, 0, 1);

    // GEMM4: out[h] = casW @ T2[h] / (W*C) + x[h]  (fp32 out, exact fp32 bias)
    bf16gemm_kernel<<<dim3(C_DIM / 128, 3, H_DIM), 128, GEMM_SMEM>>>(
        W_DIM, WPAD, WPAD,
        casW, WPAD, 0,
        bufB, WPAD, sPadH,
        out, C_DIM, sCmpH,
        1.0f / (float)(W_DIM * C_DIM), x, sCmpH, 0);
}

// round 17
// speedup vs baseline: 5.9191x; 1.0094x over previous
#include <cuda_runtime.h>
#include <cuda_bf16.h>
#include <cstdint>

// Problem constants
#define H_DIM 180
#define W_DIM 360
#define WPAD  384
#define C_DIM 512
#define P_TOT (H_DIM * W_DIM)           // 64800
#define NELEM (P_TOT * C_DIM)
#define PADELEM (H_DIM * C_DIM * WPAD)
#define NB 8
#define BS 64
#define SPARSITY 0.01f

typedef __nv_bfloat16 bf16;

// ---------------------------------------------------------------------------
// Scratch (bf16 activations)
// ---------------------------------------------------------------------------
__device__ bf16 g_bufA[PADELEM];
__device__ bf16 g_bufB[PADELEM];
__device__ bf16 g_xbf[NELEM];
__device__ bf16 g_casC[C_DIM * C_DIM];
__device__ bf16 g_casW[WPAD * WPAD];
__device__ uint32_t g_w1cat[NB * 128 * 64];   // [blk][o][ipair] bf16x2
__device__ uint32_t g_w2cat[NB * 64 * 64];    // [blk][o][ipair] bf16x2

// ---------------------------------------------------------------------------
// bf16 helpers (plain mma.sync m16n8k16 — compiles for base sm_103)
// ---------------------------------------------------------------------------
__device__ __forceinline__ uint32_t packbf(float lo, float hi) {
    uint32_t r;
    asm("cvt.rn.bf16x2.f32 %0, %1, %2;" : "=r"(r) : "f"(hi), "f"(lo));
    return r;
}

__device__ __forceinline__ void mma_bf16(float* d, const uint32_t* a, const uint32_t* b) {
    asm volatile(
        "mma.sync.aligned.m16n8k16.row.col.f32.bf16.bf16.f32 "
        "{%0,%1,%2,%3}, {%4,%5,%6,%7}, {%8,%9}, {%0,%1,%2,%3};"
        : "+f"(d[0]), "+f"(d[1]), "+f"(d[2]), "+f"(d[3])
        : "r"(a[0]), "r"(a[1]), "r"(a[2]), "r"(a[3]), "r"(b[0]), "r"(b[1]));
}

#define CP_ASYNC16(dst, src) \
    asm volatile("cp.async.cg.shared.global [%0], [%1], 16;" \
                 :: "r"(dst), "l"(src) : "memory")
#define CP_COMMIT()  asm volatile("cp.async.commit_group;" ::: "memory")
#define CP_WAIT(n)   asm volatile("cp.async.wait_group %0;" :: "n"(n) : "memory")

// ---------------------------------------------------------------------------
// Init kernels
// ---------------------------------------------------------------------------
__global__ void init_cas_kernel(bf16* __restrict__ out, int n) {
    int i = blockIdx.x * blockDim.x + threadIdx.x;
    if (i >= n * n) return;
    int t = i / n, d = i % n;
    long long m = (2LL * t * d) % (2LL * n);
    float a = (float)m / (float)n;
    float s, c;
    sincospif(a, &s, &c);
    out[i] = __float2bfloat16_rn(c + s);
}

__global__ void init_casw_pad_kernel() {
    int i = blockIdx.x * blockDim.x + threadIdx.x;
    if (i >= WPAD * WPAD) return;
    int t = i / WPAD, d = i % WPAD;
    float v = 0.f;
    if (t < W_DIM && d < W_DIM) {
        long long m = (2LL * t * d) % (2LL * W_DIM);
        float a = (float)m / (float)W_DIM;
        float s, c;
        sincospif(a, &s, &c);
        v = c + s;
    }
    g_casW[i] = __float2bfloat16_rn(v);
}

__global__ void convert_x_kernel(const float* __restrict__ x) {
    int i = blockIdx.x * blockDim.x + threadIdx.x;   // processes 4 elems
    if (i >= NELEM / 4) return;
    float4 v = *(const float4*)(x + i * 4);
    uint2 u;
    u.x = packbf(v.x, v.y);
    u.y = packbf(v.z, v.w);
    *(uint2*)((char*)g_xbf + i * 8) = u;
}

// Packed bf16-pair MLP weights, pre-transposed (see R7 derivation).
__global__ void prep_mlp_weights(const float* __restrict__ w1,
                                 const float* __restrict__ w2) {
    const int NW1 = NB * 128 * 64;
    const int NW2 = NB * 64 * 64;
    int idx = blockIdx.x * blockDim.x + threadIdx.x;
    if (idx < NW1) {
        int blk = idx >> 13;
        int rem = idx & 8191;
        int o = rem >> 6, j = rem & 63;
        const float* w1p = w1 + blk * 4096;
        const float* w1q = w1 + (NB + blk) * 4096;
        float v[2];
#pragma unroll
        for (int q = 0; q < 2; q++) {
            int i = 2 * j + q;
            if (o < 64) {
                if (i < 64) v[q] = w1p[i * 64 + o] + w1q[i * 64 + o];
                else        v[q] = w1p[(i - 64) * 64 + o] - w1q[(i - 64) * 64 + o];
            } else {
                int oo = o - 64;
                if (i < 64) v[q] = w1p[i * 64 + oo] - w1q[i * 64 + oo];
                else        v[q] = w1p[(i - 64) * 64 + oo] + w1q[(i - 64) * 64 + oo];
            }
        }
        g_w1cat[idx] = packbf(v[0], v[1]);
    } else if (idx < NW1 + NW2) {
        int jx = idx - NW1;
        int blk = jx >> 12;
        int rem = jx & 4095;
        int o = rem >> 6, j = rem & 63;
        const float* w2p = w2 + blk * 4096;
        const float* w2q = w2 + (NB + blk) * 4096;
        float v[2];
#pragma unroll
        for (int q = 0; q < 2; q++) {
            int i = 2 * j + q;
            if (i < 64) v[q] = w2p[i * 64 + o] + w2q[i * 64 + o];
            else        v[q] = w2p[(i - 64) * 64 + o] - w2q[(i - 64) * 64 + o];
        }
        g_w2cat[jx] = packbf(v[0], v[1]);
    }
}

// ---------------------------------------------------------------------------
// bf16 warp-MMA GEMM, 2-stage cp.async, m16n8k16.
// BM=BN=128, BK=64, 4 warps (2x2), warp tile 64x64, stride-36 smem.
// ---------------------------------------------------------------------------
#define STR 36
#define TS2 (128 * STR)
#define GEMM_SMEM (2 * 2 * TS2 * 4)       // 73,728 bytes
#define TSTR 136                           // transposed-tile row stride (bf16)

__global__ void __launch_bounds__(128) bf16gemm_kernel(
    int M, int K, int aM,
    const bf16* __restrict__ A, int lda, long long sA,
    const bf16* __restrict__ Bt, int ldb, long long sB,
    void* __restrict__ Cv, int ldc, long long sC,
    float alpha, const float* __restrict__ Add, long long sAdd,
    int epi_mode)
{
    extern __shared__ uint32_t smd[];
    const uint32_t sbase = (uint32_t)__cvta_generic_to_shared(smd);

    const int tid  = threadIdx.x;
    const int lane = tid & 31;
    const int wid  = tid >> 5;
    const int wm   = wid & 1;
    const int wn   = wid >> 1;
    const int bm   = blockIdx.y * 128;
    const int bn   = blockIdx.x * 128;
    const int bz   = blockIdx.z;

    A  += (size_t)bz * sA;
    Bt += (size_t)bz * sB;

    float acc[4][8][4];
#pragma unroll
    for (int mi = 0; mi < 4; mi++)
#pragma unroll
        for (int ni = 0; ni < 8; ni++)
#pragma unroll
            for (int q = 0; q < 4; q++) acc[mi][ni][q] = 0.f;

    const int r_ld = tid >> 3;            // 0..15
    const int kch  = (tid & 7) << 3;      // bf16 offset within 64: 0,8,...,56

#define LOADTILE(k0, s)                                                        \
    do {                                                                       \
        _Pragma("unroll")                                                      \
        for (int c = 0; c < 8; c++) {                                          \
            int r = r_ld + c * 16;                                             \
            int ra = bm + r;                                                   \
            if (ra >= aM) ra = aM - 1;                                         \
            uint32_t da = sbase + (((s) * 2 * TS2) + r * STR + (kch >> 1)) * 4; \
            CP_ASYNC16(da, A + (size_t)ra * lda + (k0) + kch);                 \
            uint32_t db = sbase + (((s) * 2 * TS2 + TS2) + r * STR + (kch >> 1)) * 4; \
            CP_ASYNC16(db, Bt + (size_t)(bn + r) * ldb + (k0) + kch);          \
        }                                                                      \
        CP_COMMIT();                                                           \
    } while (0)

    const int nT = K >> 6;
    LOADTILE(0, 0);

    for (int t = 0; t < nT; t++) {
        const int s = t & 1;
        if (t + 1 < nT) {
            LOADTILE((t + 1) << 6, (t + 1) & 1);
            CP_WAIT(1);
        } else {
            CP_WAIT(0);
        }
        __syncthreads();

        const uint32_t* As = smd + s * 2 * TS2;
        const uint32_t* Bs = As + TS2;

#pragma unroll
        for (int kk = 0; kk < 4; kk++) {
            uint32_t af[4][4], bf[8][2];
            const int kp = kk * 8 + (lane & 3);
#pragma unroll
            for (int mi = 0; mi < 4; mi++) {
                int r0 = wm * 64 + mi * 16 + (lane >> 2);
                af[mi][0] = As[r0 * STR + kp];
                af[mi][1] = As[(r0 + 8) * STR + kp];
                af[mi][2] = As[r0 * STR + kp + 4];
                af[mi][3] = As[(r0 + 8) * STR + kp + 4];
            }
#pragma unroll
            for (int ni = 0; ni < 8; ni++) {
                int n0 = wn * 64 + ni * 8 + (lane >> 2);
                bf[ni][0] = Bs[n0 * STR + kp];
                bf[ni][1] = Bs[n0 * STR + kp + 4];
            }
#pragma unroll
            for (int mi = 0; mi < 4; mi++)
#pragma unroll
                for (int ni = 0; ni < 8; ni++)
                    mma_bf16(acc[mi][ni], af[mi], bf[ni]);
        }
        // tail barrier only needed if smem is reused (next tile or transpose epi)
        if (t + 1 < nT || epi_mode == 1) __syncthreads();
    }
#undef LOADTILE

    if (epi_mode == 1) {
        // smem-transpose epilogue: acc -> sT[c][r_local], then coalesced rows.
        bf16* sT = (bf16*)smd;
#pragma unroll
        for (int mi = 0; mi < 4; mi++)
#pragma unroll
            for (int half = 0; half < 2; half++) {
                int r = wm * 64 + mi * 16 + (lane >> 2) + half * 8;
#pragma unroll
                for (int ni = 0; ni < 8; ni++) {
                    int c0 = wn * 64 + ni * 8 + (lane & 3) * 2;
                    sT[c0 * TSTR + r]       = __float2bfloat16_rn(acc[mi][ni][half * 2 + 0]);
                    sT[(c0 + 1) * TSTR + r] = __float2bfloat16_rn(acc[mi][ni][half * 2 + 1]);
                }
            }
        __syncthreads();
        bf16* cbase = (bf16*)Cv;
#pragma unroll
        for (int it = tid; it < 128 * 16; it += 128) {
            int cr = it >> 4;            // local c row
            int rl = (it & 15) * 8;      // chunk of 8 local rows
            int p = bm + rl;
            if (p < P_TOT) {
                int h = p / W_DIM;
                int w = p - h * W_DIM;
                uint4 v = *(uint4*)&sT[cr * TSTR + rl];
                *(uint4*)(cbase + (size_t)h * (C_DIM * WPAD)
                          + (size_t)(bn + cr) * WPAD + w) = v;
            }
        }
        // zero-fill pad w in [360,384) for all h overlapped by this tile
        {
            uint4 z = make_uint4(0u, 0u, 0u, 0u);
            int h0 = bm / W_DIM;
            int h1 = (bm + 127 < P_TOT ? bm + 127 : P_TOT - 1) / W_DIM;
            for (int h = h0; h <= h1; h++) {
#pragma unroll
                for (int it = tid; it < 128 * 3; it += 128) {
                    int cr = it / 3;
                    int ch = it - cr * 3;
                    *(uint4*)(cbase + (size_t)h * (C_DIM * WPAD)
                              + (size_t)(bn + cr) * WPAD + W_DIM + ch * 8) = z;
                }
            }
        }
        return;
    }

    const float* addb = Add ? (Add + (size_t)bz * sAdd) : (const float*)0;
#pragma unroll
    for (int mi = 0; mi < 4; mi++) {
#pragma unroll
        for (int half = 0; half < 2; half++) {
            int r = wm * 64 + mi * 16 + (lane >> 2) + half * 8;
            int p = bm + r;
            if (p >= M) continue;
            if (epi_mode == 0) {
                float* cp = (float*)Cv + (size_t)bz * sC + (size_t)p * ldc + bn;
                const float* ap = addb ? (addb + (size_t)p * ldc + bn) : (const float*)0;
#pragma unroll
                for (int ni = 0; ni < 8; ni++) {
                    int c0 = wn * 64 + ni * 8 + (lane & 3) * 2;
                    float2 v;
                    v.x = acc[mi][ni][half * 2 + 0] * alpha;
                    v.y = acc[mi][ni][half * 2 + 1] * alpha;
                    if (ap) {
                        float2 a2 = *(const float2*)(ap + c0);
                        v.x += a2.x; v.y += a2.y;
                    }
                    *(float2*)(cp + c0) = v;
                }
            } else {
                bf16* cp = (bf16*)Cv + (size_t)bz * sC + (size_t)p * ldc + bn;
#pragma unroll
                for (int ni = 0; ni < 8; ni++) {
                    int c0 = wn * 64 + ni * 8 + (lane & 3) * 2;
                    *(uint32_t*)(cp + c0) =
                        packbf(acc[mi][ni][half * 2 + 0], acc[mi][ni][half * 2 + 1]);
                }
            }
        }
    }
}

// ---------------------------------------------------------------------------
// bf16 tensor-core block-MLP + softshrink. 256 threads, 8 warps (2x4).
// R17: single load barrier (indices computed in regs), fused L2a+L2b-pass1
// K-loop (independent accumulators -> 2x MMA ILP), 4 syncs total.
// ---------------------------------------------------------------------------
#define MS2 68
#define O2S2 36
#define MLP_TC_SMEM ((128 * MS2 + 128 * MS2 + 64 * MS2 + 128 * O2S2) * 4)

__global__ void __launch_bounds__(256) mlp_tc_kernel(
    const bf16* __restrict__ xh,
    const float* __restrict__ b1,
    const float* __restrict__ b2,
    bf16* __restrict__ y)
{
    extern __shared__ uint32_t sm[];
    uint32_t* sA  = sm;
    uint32_t* sW1 = sA + 128 * MS2;
    uint32_t* sW2 = sW1 + 128 * MS2;
    uint32_t* sO2 = sW2 + 64 * MS2;

    const int tid  = threadIdx.x;
    const int lane = tid & 31;
    const int wid  = tid >> 5;
    const int wm   = wid & 1;
    const int wn   = wid >> 1;
    const int k    = blockIdx.y;
    const int p0   = blockIdx.x * 128;

    // weights -> smem
    {
        const uint4* w1g = (const uint4*)(g_w1cat + k * 8192);
#pragma unroll
        for (int it = tid; it < 2048; it += 256) {
            int r = it >> 4, c4 = (it & 15) << 2;
            *(uint4*)&sW1[r * MS2 + c4] = w1g[it];
        }
        const uint4* w2g = (const uint4*)(g_w2cat + k * 4096);
#pragma unroll
        for (int it = tid; it < 1024; it += 256) {
            int r = it >> 4, c4 = (it & 15) << 2;
            *(uint4*)&sW2[r * MS2 + c4] = w2g[it];
        }
    }
    // A1 = [xh | xn] tile (indices computed in registers; no extra barrier)
#pragma unroll
    for (int it = tid; it < 4096; it += 256) {
        int r = it >> 5;
        int c = (it & 31) * 4;
        int p = p0 + r;
        if (p >= P_TOT) p = P_TOT - 1;
        const bf16* src;
        if (c < 64) {
            src = xh + (size_t)p * C_DIM + k * BS + c;
        } else {
            int h = p / W_DIM, w = p - h * W_DIM;
            int pn = ((H_DIM - h) % H_DIM) * W_DIM + ((W_DIM - w) % W_DIM);
            src = xh + (size_t)pn * C_DIM + k * BS + (c - 64);
        }
        *(uint2*)&sA[r * MS2 + (c >> 1)] = *(const uint2*)src;
    }
    __syncthreads();                                   // sync 1

    // ---- Layer 1 ----
    float acc1[4][4][4];
#pragma unroll
    for (int mi = 0; mi < 4; mi++)
#pragma unroll
        for (int ni = 0; ni < 4; ni++)
#pragma unroll
            for (int q = 0; q < 4; q++) acc1[mi][ni][q] = 0.f;

#pragma unroll
    for (int kk = 0; kk < 8; kk++) {
        uint32_t af[4][4], bf[4][2];
        const int kp = kk * 8 + (lane & 3);
#pragma unroll
        for (int mi = 0; mi < 4; mi++) {
            int r0 = wm * 64 + mi * 16 + (lane >> 2);
            af[mi][0] = sA[r0 * MS2 + kp];
            af[mi][1] = sA[(r0 + 8) * MS2 + kp];
            af[mi][2] = sA[r0 * MS2 + kp + 4];
            af[mi][3] = sA[(r0 + 8) * MS2 + kp + 4];
        }
#pragma unroll
        for (int ni = 0; ni < 4; ni++) {
            int n0 = wn * 32 + ni * 8 + (lane >> 2);
            bf[ni][0] = sW1[n0 * MS2 + kp];
            bf[ni][1] = sW1[n0 * MS2 + kp + 4];
        }
#pragma unroll
        for (int mi = 0; mi < 4; mi++)
#pragma unroll
            for (int ni = 0; ni < 4; ni++)
                mma_bf16(acc1[mi][ni], af[mi], bf[ni]);
    }
    __syncthreads();                                   // sync 2

    // bias + relu -> sA
#pragma unroll
    for (int mi = 0; mi < 4; mi++)
#pragma unroll
        for (int half = 0; half < 2; half++) {
            int r = wm * 64 + mi * 16 + (lane >> 2) + half * 8;
#pragma unroll
            for (int ni = 0; ni < 4; ni++) {
                int c = wn * 32 + ni * 8 + (lane & 3) * 2;
                float bx = (c < 64) ? b1[k * BS + c] : b1[NB * BS + k * BS + (c - 64)];
                float by = (c + 1 < 64) ? b1[k * BS + c + 1] : b1[NB * BS + k * BS + (c + 1 - 64)];
                float vx = fmaxf(0.5f * acc1[mi][ni][half * 2 + 0] + bx, 0.f);
                float vy = fmaxf(0.5f * acc1[mi][ni][half * 2 + 1] + by, 0.f);
                sA[r * MS2 + (c >> 1)] = packbf(vx, vy);
            }
        }
    __syncthreads();                                   // sync 3

    // ---- Fused Layer 2a (o2k, K=128) + Layer 2b pass 1 (o1n@w2a, K=64) ----
    float acc2[4][2][4], accn[4][2][4];
#pragma unroll
    for (int mi = 0; mi < 4; mi++)
#pragma unroll
        for (int ni = 0; ni < 2; ni++)
#pragma unroll
            for (int q = 0; q < 4; q++) { acc2[mi][ni][q] = 0.f; accn[mi][ni][q] = 0.f; }

#pragma unroll
    for (int kk = 0; kk < 8; kk++) {
        uint32_t af[4][4], bf[2][2];
        const int kp = kk * 8 + (lane & 3);
#pragma unroll
        for (int mi = 0; mi < 4; mi++) {
            int r0 = wm * 64 + mi * 16 + (lane >> 2);
            af[mi][0] = sA[r0 * MS2 + kp];
            af[mi][1] = sA[(r0 + 8) * MS2 + kp];
            af[mi][2] = sA[r0 * MS2 + kp + 4];
            af[mi][3] = sA[(r0 + 8) * MS2 + kp + 4];
        }
#pragma unroll
        for (int ni = 0; ni < 2; ni++) {
            int n0 = wn * 16 + ni * 8 + (lane >> 2);
            bf[ni][0] = sW2[n0 * MS2 + kp];
            bf[ni][1] = sW2[n0 * MS2 + kp + 4];
        }
#pragma unroll
        for (int mi = 0; mi < 4; mi++)
#pragma unroll
            for (int ni = 0; ni < 2; ni++)
                mma_bf16(acc2[mi][ni], af[mi], bf[ni]);

        if (kk >= 4) {
            // o1n rows (k 64..127 of o1) with w2a (sW2 k 0..63):
            // af2 fragment k index = (kk-4)*8 + ... + 32 uint32 offset
            uint32_t af2[4][4], bf2[2][2];
            const int kp2 = (kk - 4) * 8 + (lane & 3);
#pragma unroll
            for (int mi = 0; mi < 4; mi++) {
                int r0 = wm * 64 + mi * 16 + (lane >> 2);
                af2[mi][0] = sA[r0 * MS2 + 32 + kp2];
                af2[mi][1] = sA[(r0 + 8) * MS2 + 32 + kp2];
                af2[mi][2] = sA[r0 * MS2 + 32 + kp2 + 4];
                af2[mi][3] = sA[(r0 + 8) * MS2 + 32 + kp2 + 4];
            }
#pragma unroll
            for (int ni = 0; ni < 2; ni++) {
                int n0 = wn * 16 + ni * 8 + (lane >> 2);
                bf2[ni][0] = sW2[n0 * MS2 + kp2];
                bf2[ni][1] = sW2[n0 * MS2 + kp2 + 4];
            }
#pragma unroll
            for (int mi = 0; mi < 4; mi++)
#pragma unroll
                for (int ni = 0; ni < 2; ni++)
                    mma_bf16(accn[mi][ni], af2[mi], bf2[ni]);
        }
    }

    float v2k[4][2][4];
#pragma unroll
    for (int mi = 0; mi < 4; mi++)
#pragma unroll
        for (int half = 0; half < 2; half++) {
            int r = wm * 64 + mi * 16 + (lane >> 2) + half * 8;
#pragma unroll
            for (int ni = 0; ni < 2; ni++) {
                int c = wn * 16 + ni * 8 + (lane & 3) * 2;
                float vx = 0.5f * acc2[mi][ni][half * 2 + 0] + b2[k * BS + c];
                float vy = 0.5f * acc2[mi][ni][half * 2 + 1] + b2[k * BS + c + 1];
                v2k[mi][ni][half * 2 + 0] = vx;
                v2k[mi][ni][half * 2 + 1] = vy;
                sO2[r * O2S2 + (c >> 1)] = packbf(vx, vy);
            }
        }
    __syncthreads();                                   // sync 4

    // ---- Layer 2b pass 2: += o2k @ w2b (K=64) ----
#pragma unroll
    for (int kk = 0; kk < 4; kk++) {
        uint32_t af[4][4], bf[2][2];
        const int kp = kk * 8 + (lane & 3);
#pragma unroll
        for (int mi = 0; mi < 4; mi++) {
            int r0 = wm * 64 + mi * 16 + (lane >> 2);
            af[mi][0] = sO2[r0 * O2S2 + kp];
            af[mi][1] = sO2[(r0 + 8) * O2S2 + kp];
            af[mi][2] = sO2[r0 * O2S2 + kp + 4];
            af[mi][3] = sO2[(r0 + 8) * O2S2 + kp + 4];
        }
#pragma unroll
        for (int ni = 0; ni < 2; ni++) {
            int n0 = wn * 16 + ni * 8 + (lane >> 2);
            bf[ni][0] = sW2[n0 * MS2 + 32 + kp];
            bf[ni][1] = sW2[n0 * MS2 + 32 + kp + 4];
        }
#pragma unroll
        for (int mi = 0; mi < 4; mi++)
#pragma unroll
            for (int ni = 0; ni < 2; ni++)
                mma_bf16(accn[mi][ni], af[mi], bf[ni]);
    }

    // y = softshrink(o2k + o2n)
#pragma unroll
    for (int mi = 0; mi < 4; mi++)
#pragma unroll
        for (int half = 0; half < 2; half++) {
            int r = wm * 64 + mi * 16 + (lane >> 2) + half * 8;
            int p = p0 + r;
            if (p < P_TOT) {
#pragma unroll
                for (int ni = 0; ni < 2; ni++) {
                    int c = wn * 16 + ni * 8 + (lane & 3) * 2;
                    float vx = v2k[mi][ni][half * 2 + 0]
                             + 0.5f * accn[mi][ni][half * 2 + 0] + b2[NB * BS + k * BS + c];
                    float vy = v2k[mi][ni][half * 2 + 1]
                             + 0.5f * accn[mi][ni][half * 2 + 1] + b2[NB * BS + k * BS + c + 1];
                    float ax = fabsf(vx) - SPARSITY;
                    float ay = fabsf(vy) - SPARSITY;
                    float rx = ax > 0.f ? copysignf(ax, vx) : 0.f;
                    float ry = ay > 0.f ? copysignf(ay, vy) : 0.f;
                    *(uint32_t*)(y + (size_t)p * C_DIM + k * BS + c) = packbf(rx, ry);
                }
            }
        }
}

// ---------------------------------------------------------------------------
// kernel_launch
// ---------------------------------------------------------------------------
extern "C" void kernel_launch(void* const* d_in, const int* in_sizes, int n_in,
                              void* d_out, int out_size) {
    const float* x  = (const float*)d_in[0];
    const float* w1 = (const float*)d_in[1];
    const float* b1 = (const float*)d_in[2];
    const float* w2 = (const float*)d_in[3];
    const float* b2 = (const float*)d_in[4];
    float* out = (float*)d_out;

    bf16 *bufA, *bufB, *casC, *casW, *xbf;
    cudaGetSymbolAddress((void**)&bufA, g_bufA);
    cudaGetSymbolAddress((void**)&bufB, g_bufB);
    cudaGetSymbolAddress((void**)&casC, g_casC);
    cudaGetSymbolAddress((void**)&casW, g_casW);
    cudaGetSymbolAddress((void**)&xbf,  g_xbf);

    cudaFuncSetAttribute(mlp_tc_kernel, cudaFuncAttributeMaxDynamicSharedMemorySize,
                         MLP_TC_SMEM);
    cudaFuncSetAttribute(bf16gemm_kernel, cudaFuncAttributeMaxDynamicSharedMemorySize,
                         GEMM_SMEM);

    init_cas_kernel<<<(C_DIM * C_DIM + 255) / 256, 256>>>(casC, C_DIM);
    init_casw_pad_kernel<<<(WPAD * WPAD + 255) / 256, 256>>>();
    convert_x_kernel<<<(NELEM / 4 + 255) / 256, 256>>>(x);
    {
        int nprep = NB * 128 * 64 + NB * 64 * 64;
        prep_mlp_weights<<<(nprep + 255) / 256, 256>>>(w1, w2);
    }

    const long long sPadH = (long long)C_DIM * WPAD;
    const long long sCmpH = (long long)W_DIM * C_DIM;

    // GEMM1 (flat M): T1t = (X @ casC)^T -> padded bufA (pads zero-filled in epi)
    bf16gemm_kernel<<<dim3(C_DIM / 128, (P_TOT + 127) / 128, 1), 128, GEMM_SMEM>>>(
        P_TOT, C_DIM, P_TOT,
        xbf, C_DIM, 0,
        casC, C_DIM, 0,
        bufA, 0, 0,
        1.0f, nullptr, 0, 1);

    // GEMM2: XH[h] = casW @ T1[h] -> compact bf16 bufB
    bf16gemm_kernel<<<dim3(C_DIM / 128, 3, H_DIM), 128, GEMM_SMEM>>>(
        W_DIM, WPAD, WPAD,
        casW, WPAD, 0,
        bufA, WPAD, sPadH,
        bufB, C_DIM, sCmpH,
        1.0f, nullptr, 0, 2);

    // bf16 tensor-core block MLP + softshrink: bufB -> bufA (compact)
    mlp_tc_kernel<<<dim3((P_TOT + 127) / 128, NB), 256, MLP_TC_SMEM>>>(
        bufB, b1, b2, bufA);

    // GEMM3 (flat M): T2t = (Y @ casC)^T -> padded bufB (pads zero-filled in epi)
    bf16gemm_kernel<<<dim3(C_DIM / 128, (P_TOT + 127) / 128, 1), 128, GEMM_SMEM>>>(
        P_TOT, C_DIM, P_TOT,
        bufA, C_DIM, 0,
        casC, C_DIM, 0,
        bufB, 0, 0,
        1.0f, nullptr, 0, 1);

    // GEMM4: out[h] = casW @ T2[h] / (W*C) + x[h]  (fp32 out, exact fp32 bias)
    bf16gemm_kernel<<<dim3(C_DIM / 128, 3, H_DIM), 128, GEMM_SMEM>>>(
        W_DIM, WPAD, WPAD,
        casW, WPAD, 0,
        bufB, WPAD, sPadH,
        out, C_DIM, sCmpH,
        1.0f / (float)(W_DIM * C_DIM), x, sCmpH, 0);
}